// round 1
// baseline (speedup 1.0000x reference)
#include <cuda_runtime.h>
#include <math.h>

#define NB 32
#define NINP 256
#define NHW 1024
#define NCS 64
#define NAOUT 256
#define NCF 513
#define NC5 256
#define EPSV 1e-5f

// ---------------- scratch (static device allocations, harness-legal) ----------
__device__ float g_theta[NB * NCS * NHW];   // [b][c][p]
__device__ float g_phi[NB * NCS * NHW];     // [b][c][p] ; P[j][c] = phi_flat[j*64+c]
__device__ float g_WP[NB * NAOUT * NCS];    // [b][o][c] = sum_j w4[o,j] * P[j,c]
__device__ float g_TW[NB * NCS * NAOUT];    // [b][c][o] = sum_p theta[c,p] * w4[o,p]
__device__ float g_y[NB * NCF * NHW];       // [b][f][p], f: 0=x_embed, 1..256 aff_a, 257..512 aff_b
__device__ float g_av[NB * NHW];            // gate a[b][p]
__device__ float g_w5t[NCF * NC5];          // w5 transposed [f][k], pre-scaled by bn5 scale
__device__ float g_sc[3 * NCS];             // folded BN scale for conv1..3
__device__ float g_sh[3 * NCS];             // folded BN shift (incl conv bias)
__device__ float g_sh5[NC5];                // folded BN shift for conv5

__device__ __forceinline__ float f4get(const float4& v, int i) {
    return i == 0 ? v.x : (i == 1 ? v.y : (i == 2 ? v.z : v.w));
}

// ---------------- K0: fold BN params, transpose+scale w5 ----------------------
__global__ void k0_prep(const float* __restrict__ w5,
                        const float* __restrict__ g5, const float* __restrict__ v5,
                        const float* __restrict__ b5, const float* __restrict__ bt5,
                        const float* __restrict__ m5,
                        const float* __restrict__ b1, const float* __restrict__ g1,
                        const float* __restrict__ bt1, const float* __restrict__ m1,
                        const float* __restrict__ v1,
                        const float* __restrict__ b2, const float* __restrict__ g2,
                        const float* __restrict__ bt2, const float* __restrict__ m2,
                        const float* __restrict__ v2,
                        const float* __restrict__ b3, const float* __restrict__ g3,
                        const float* __restrict__ bt3, const float* __restrict__ m3,
                        const float* __restrict__ v3)
{
    const int f = blockIdx.x;
    const int k = threadIdx.x;      // 0..255
    if (f < NCF) {
        float s5 = g5[k] * rsqrtf(v5[k] + EPSV);
        g_w5t[f * NC5 + k] = w5[k * NCF + f] * s5;
    } else {
        float s5 = g5[k] * rsqrtf(v5[k] + EPSV);
        g_sh5[k] = (b5[k] - m5[k]) * s5 + bt5[k];
        if (k < 3 * NCS) {
            int cv = k / NCS, c = k % NCS;
            const float* bb = cv == 0 ? b1 : (cv == 1 ? b2 : b3);
            const float* gg = cv == 0 ? g1 : (cv == 1 ? g2 : g3);
            const float* bt = cv == 0 ? bt1 : (cv == 1 ? bt2 : bt3);
            const float* mm = cv == 0 ? m1 : (cv == 1 ? m2 : m3);
            const float* vv = cv == 0 ? v1 : (cv == 1 ? v2 : v3);
            float s = gg[c] * rsqrtf(vv[c] + EPSV);
            g_sc[k] = s;
            g_sh[k] = (bb[c] - mm[c]) * s + bt[c];
        }
    }
}

// ---------------- K1: theta/phi/x3 convs (+BN+relu), x_embed mean -------------
// grid (8 ptiles, 3 convs, 32 b), 256 threads
// dyn smem: xs[256][128] + ws[64][256] = 196608 B
__global__ void __launch_bounds__(256) k1_conv(const float* __restrict__ x,
                                               const float* __restrict__ w1,
                                               const float* __restrict__ w2,
                                               const float* __restrict__ w3)
{
    extern __shared__ float sm1[];
    float* xs = sm1;                    // [256][128]
    float* ws = sm1 + NINP * 128;       // [64][256]
    const int p0 = blockIdx.x * 128;
    const int cv = blockIdx.y;
    const int b  = blockIdx.z;
    const int tid = threadIdx.x;

    const float* W = cv == 0 ? w1 : (cv == 1 ? w2 : w3);

    const float4* xg4 = reinterpret_cast<const float4*>(x + (size_t)b * NINP * NHW);
    float4* xs4 = reinterpret_cast<float4*>(xs);
    const int p04 = p0 >> 2;
    for (int i = tid; i < NINP * 32; i += 256) {
        int row = i >> 5, c4 = i & 31;
        xs4[i] = xg4[row * (NHW / 4) + p04 + c4];
    }
    const float4* Wg4 = reinterpret_cast<const float4*>(W);
    float4* ws4 = reinterpret_cast<float4*>(ws);
    for (int i = tid; i < (NCS * NINP) / 4; i += 256) ws4[i] = Wg4[i];
    __syncthreads();

    const int tp = tid & 31;   // pixels tp*4 .. +3
    const int tc = tid >> 5;   // channels tc*8 .. +7
    float acc[8][4];
#pragma unroll
    for (int i = 0; i < 8; i++)
#pragma unroll
        for (int j = 0; j < 4; j++) acc[i][j] = 0.f;

#pragma unroll 4
    for (int k4 = 0; k4 < 64; k4++) {
        float4 xv[4];
#pragma unroll
        for (int kk = 0; kk < 4; kk++) xv[kk] = xs4[(k4 * 4 + kk) * 32 + tp];
#pragma unroll
        for (int cc = 0; cc < 8; cc++) {
            float4 wv = ws4[(tc * 8 + cc) * 64 + k4];
#pragma unroll
            for (int kk = 0; kk < 4; kk++) {
                float wk = f4get(wv, kk);
#pragma unroll
                for (int j = 0; j < 4; j++)
                    acc[cc][j] = fmaf(wk, f4get(xv[kk], j), acc[cc][j]);
            }
        }
    }

    if (cv < 2) {
        float* dst = (cv == 0 ? g_theta : g_phi) + (size_t)b * NCS * NHW;
#pragma unroll
        for (int cc = 0; cc < 8; cc++) {
            int c = tc * 8 + cc;
            float s = g_sc[cv * NCS + c], h = g_sh[cv * NCS + c];
            float4 o;
            o.x = fmaxf(fmaf(s, acc[cc][0], h), 0.f);
            o.y = fmaxf(fmaf(s, acc[cc][1], h), 0.f);
            o.z = fmaxf(fmaf(s, acc[cc][2], h), 0.f);
            o.w = fmaxf(fmaf(s, acc[cc][3], h), 0.f);
            reinterpret_cast<float4*>(dst + (size_t)c * NHW + p0)[tp] = o;
        }
    } else {
        float psum[4] = {0.f, 0.f, 0.f, 0.f};
#pragma unroll
        for (int cc = 0; cc < 8; cc++) {
            int c = tc * 8 + cc;
            float s = g_sc[2 * NCS + c], h = g_sh[2 * NCS + c];
#pragma unroll
            for (int j = 0; j < 4; j++)
                psum[j] += fmaxf(fmaf(s, acc[cc][j], h), 0.f);
        }
        __syncthreads();            // done reading ws
        float* red = ws;            // [8][128]
#pragma unroll
        for (int j = 0; j < 4; j++) red[tc * 128 + tp * 4 + j] = psum[j];
        __syncthreads();
        if (tid < 128) {
            float ssum = 0.f;
#pragma unroll
            for (int t = 0; t < 8; t++) ssum += red[t * 128 + tid];
            g_y[(size_t)b * NCF * NHW + p0 + tid] = ssum * (1.f / NCS);
        }
    }
}

// ---------------- K2: WP = w4 @ P ; TW = theta @ w4^T  (per batch) ------------
// grid (4 tiles, 32 b, 2 which), 256 threads. out tile [64m][64n], K=1024
__global__ void __launch_bounds__(256) k2_small(const float* __restrict__ w4)
{
    __shared__ __align__(16) float As[64 * 68];
    __shared__ __align__(16) float Bs[64 * 68];
    const int tile = blockIdx.x;
    const int b = blockIdx.y;
    const int which = blockIdx.z;
    const int tid = threadIdx.x;
    const int tm = tid >> 4, tn = tid & 15;

    const float* phi = g_phi + (size_t)b * NCS * NHW;
    const float* th  = g_theta + (size_t)b * NCS * NHW;

    float acc[4][4];
#pragma unroll
    for (int i = 0; i < 4; i++)
#pragma unroll
        for (int j = 0; j < 4; j++) acc[i][j] = 0.f;

    for (int k0 = 0; k0 < NHW; k0 += 64) {
        __syncthreads();
        if (which == 0) {
            const int m0 = tile * 64;
            for (int i = tid; i < 64 * 16; i += 256) {      // As[k][m=o] (transpose)
                int m = i >> 4, kq = i & 15;
                float4 v = *reinterpret_cast<const float4*>(w4 + (size_t)(m0 + m) * NHW + k0 + kq * 4);
                As[(kq * 4 + 0) * 68 + m] = v.x;
                As[(kq * 4 + 1) * 68 + m] = v.y;
                As[(kq * 4 + 2) * 68 + m] = v.z;
                As[(kq * 4 + 3) * 68 + m] = v.w;
            }
            for (int i = tid; i < 64 * 16; i += 256) {      // Bs[k][n=c] direct
                int k = i >> 4, nq = i & 15;
                float4 v = *reinterpret_cast<const float4*>(phi + (size_t)(k0 + k) * 64 + nq * 4);
                *reinterpret_cast<float4*>(Bs + k * 68 + nq * 4) = v;
            }
        } else {
            for (int i = tid; i < 64 * 16; i += 256) {      // As[k][m=c] (transpose)
                int m = i >> 4, kq = i & 15;
                float4 v = *reinterpret_cast<const float4*>(th + (size_t)m * NHW + k0 + kq * 4);
                As[(kq * 4 + 0) * 68 + m] = v.x;
                As[(kq * 4 + 1) * 68 + m] = v.y;
                As[(kq * 4 + 2) * 68 + m] = v.z;
                As[(kq * 4 + 3) * 68 + m] = v.w;
            }
            const int n0 = tile * 64;
            for (int i = tid; i < 64 * 16; i += 256) {      // Bs[k][n=o] (transpose)
                int n = i >> 4, kq = i & 15;
                float4 v = *reinterpret_cast<const float4*>(w4 + (size_t)(n0 + n) * NHW + k0 + kq * 4);
                Bs[(kq * 4 + 0) * 68 + n] = v.x;
                Bs[(kq * 4 + 1) * 68 + n] = v.y;
                Bs[(kq * 4 + 2) * 68 + n] = v.z;
                Bs[(kq * 4 + 3) * 68 + n] = v.w;
            }
        }
        __syncthreads();
#pragma unroll 8
        for (int k = 0; k < 64; k++) {
            float4 av = *reinterpret_cast<const float4*>(As + k * 68 + tm * 4);
            float4 bv = *reinterpret_cast<const float4*>(Bs + k * 68 + tn * 4);
#pragma unroll
            for (int i = 0; i < 4; i++)
#pragma unroll
                for (int j = 0; j < 4; j++)
                    acc[i][j] = fmaf(f4get(av, i), f4get(bv, j), acc[i][j]);
        }
    }

    if (which == 0) {
        float* WPd = g_WP + (size_t)b * NAOUT * NCS;
        const int m0 = tile * 64;
#pragma unroll
        for (int i = 0; i < 4; i++)
#pragma unroll
            for (int j = 0; j < 4; j++)
                WPd[(size_t)(m0 + tm * 4 + i) * NCS + tn * 4 + j] = acc[i][j];
    } else {
        float* TWd = g_TW + (size_t)b * NCS * NAOUT;
        const int n0 = tile * 64;
#pragma unroll
        for (int i = 0; i < 4; i++)
#pragma unroll
            for (int j = 0; j < 4; j++)
                TWd[(size_t)(tm * 4 + i) * NAOUT + n0 + tn * 4 + j] = acc[i][j];
    }
}

// ---------------- K3: aff_a / aff_b embeds -> y -------------------------------
// grid (8 ptiles, 8 = 4 otiles x 2 which, 32 b), 256 threads; K=64
// dyn smem: As[64][68] + Bs[64][132] = 51200 B
__global__ void __launch_bounds__(256) k3_aff(const float* __restrict__ b4)
{
    extern __shared__ float sm3[];
    float* As = sm3;              // [64][68]  A[k=c][o]
    float* Bs = sm3 + 64 * 68;    // [64][132] B[k=c][p]
    const int p0 = blockIdx.x * 128;
    const int by = blockIdx.y;
    const int b  = blockIdx.z;
    const int which = by >> 2;
    const int o0 = (by & 3) * 64;
    const int tid = threadIdx.x;

    if (which == 0) {
        const float* WPd = g_WP + (size_t)b * NAOUT * NCS;
        for (int i = tid; i < 64 * 16; i += 256) {          // transpose WP[o][c] -> As[c][o]
            int o = i >> 4, cq = i & 15;
            float4 v = *reinterpret_cast<const float4*>(WPd + (size_t)(o0 + o) * NCS + cq * 4);
            As[(cq * 4 + 0) * 68 + o] = v.x;
            As[(cq * 4 + 1) * 68 + o] = v.y;
            As[(cq * 4 + 2) * 68 + o] = v.z;
            As[(cq * 4 + 3) * 68 + o] = v.w;
        }
        const float* th = g_theta + (size_t)b * NCS * NHW;
        for (int i = tid; i < 64 * 32; i += 256) {          // Bs[c][p] direct
            int c = i >> 5, pq = i & 31;
            *reinterpret_cast<float4*>(Bs + c * 132 + pq * 4) =
                *reinterpret_cast<const float4*>(th + (size_t)c * NHW + p0 + pq * 4);
        }
    } else {
        const float* TWd = g_TW + (size_t)b * NCS * NAOUT;
        for (int i = tid; i < 64 * 16; i += 256) {          // As[c][o] direct
            int c = i >> 4, oq = i & 15;
            *reinterpret_cast<float4*>(As + c * 68 + oq * 4) =
                *reinterpret_cast<const float4*>(TWd + (size_t)c * NAOUT + o0 + oq * 4);
        }
        const float* phi = g_phi + (size_t)b * NCS * NHW;
        for (int i = tid; i < 128 * 16; i += 256) {         // transpose P[p][c] -> Bs[c][p]
            int p = i >> 4, cq = i & 15;
            float4 v = *reinterpret_cast<const float4*>(phi + (size_t)(p0 + p) * 64 + cq * 4);
            Bs[(cq * 4 + 0) * 132 + p] = v.x;
            Bs[(cq * 4 + 1) * 132 + p] = v.y;
            Bs[(cq * 4 + 2) * 132 + p] = v.z;
            Bs[(cq * 4 + 3) * 132 + p] = v.w;
        }
    }
    __syncthreads();

    const int tp = tid & 31;   // pixels tp*4..+3
    const int tc = tid >> 5;   // out channels tc*8..+7 (local)
    float acc[8][4];
#pragma unroll
    for (int i = 0; i < 8; i++)
#pragma unroll
        for (int j = 0; j < 4; j++) acc[i][j] = 0.f;

#pragma unroll 8
    for (int k = 0; k < 64; k++) {
        float4 xv = *reinterpret_cast<const float4*>(Bs + k * 132 + tp * 4);
        float4 w0 = *reinterpret_cast<const float4*>(As + k * 68 + tc * 8);
        float4 w1v = *reinterpret_cast<const float4*>(As + k * 68 + tc * 8 + 4);
#pragma unroll
        for (int cc = 0; cc < 8; cc++) {
            float wk = cc < 4 ? f4get(w0, cc) : f4get(w1v, cc - 4);
#pragma unroll
            for (int j = 0; j < 4; j++)
                acc[cc][j] = fmaf(wk, f4get(xv, j), acc[cc][j]);
        }
    }

    float* yd = g_y + (size_t)b * NCF * NHW + (size_t)(1 + which * NAOUT + o0) * NHW;
#pragma unroll
    for (int cc = 0; cc < 8; cc++) {
        float bb = b4[o0 + tc * 8 + cc];
        float4 o;
        o.x = fmaxf(acc[cc][0] + bb, 0.f);
        o.y = fmaxf(acc[cc][1] + bb, 0.f);
        o.z = fmaxf(acc[cc][2] + bb, 0.f);
        o.w = fmaxf(acc[cc][3] + bb, 0.f);
        *reinterpret_cast<float4*>(yd + (size_t)(tc * 8 + cc) * NHW + p0 + tp * 4) = o;
    }
}

// ---------------- K4: z = relu(bn5(w5 @ y)), a = sigmoid(w6.z + b6) -----------
// grid (16 ptiles, 32 b), 256 threads; out tile [256k][64p], K=513 in 9x57
// dyn smem: W5s[57][256] + Ys[57][64] + red[64][33] = 81408 B
__global__ void __launch_bounds__(256) k4_final(const float* __restrict__ w6,
                                                const float* __restrict__ b6)
{
    extern __shared__ float sm4[];
    float* W5s = sm4;               // [57][256]
    float* Ys  = sm4 + 57 * 256;    // [57][64]
    float* red = Ys + 57 * 64;      // [64][33]
    const int p0 = blockIdx.x * 64;
    const int b  = blockIdx.y;
    const int tid = threadIdx.x;
    const int tp = tid & 7;     // pixels tp*8..+7
    const int tk = tid >> 3;    // k channels tk*8..+7

    const float* yb = g_y + (size_t)b * NCF * NHW;

    float acc[8][8];
#pragma unroll
    for (int i = 0; i < 8; i++)
#pragma unroll
        for (int j = 0; j < 8; j++) acc[i][j] = 0.f;

    for (int f0 = 0; f0 < NCF; f0 += 57) {
        __syncthreads();
        for (int i = tid; i < 57 * 64; i += 256) {
            int ff = i >> 6, kq = i & 63;
            *reinterpret_cast<float4*>(W5s + ff * 256 + kq * 4) =
                *reinterpret_cast<const float4*>(g_w5t + (size_t)(f0 + ff) * NC5 + kq * 4);
        }
        for (int i = tid; i < 57 * 16; i += 256) {
            int ff = i >> 4, pq = i & 15;
            *reinterpret_cast<float4*>(Ys + ff * 64 + pq * 4) =
                *reinterpret_cast<const float4*>(yb + (size_t)(f0 + ff) * NHW + p0 + pq * 4);
        }
        __syncthreads();
#pragma unroll 3
        for (int f = 0; f < 57; f++) {
            float4 w0 = *reinterpret_cast<const float4*>(W5s + f * 256 + tk * 8);
            float4 w1v = *reinterpret_cast<const float4*>(W5s + f * 256 + tk * 8 + 4);
            float4 y0 = *reinterpret_cast<const float4*>(Ys + f * 64 + tp * 8);
            float4 y1 = *reinterpret_cast<const float4*>(Ys + f * 64 + tp * 8 + 4);
            float wr[8] = {w0.x, w0.y, w0.z, w0.w, w1v.x, w1v.y, w1v.z, w1v.w};
            float yr[8] = {y0.x, y0.y, y0.z, y0.w, y1.x, y1.y, y1.z, y1.w};
#pragma unroll
            for (int kk = 0; kk < 8; kk++)
#pragma unroll
                for (int pp = 0; pp < 8; pp++)
                    acc[kk][pp] = fmaf(wr[kk], yr[pp], acc[kk][pp]);
        }
    }

    float part[8] = {0.f, 0.f, 0.f, 0.f, 0.f, 0.f, 0.f, 0.f};
#pragma unroll
    for (int kk = 0; kk < 8; kk++) {
        int k = tk * 8 + kk;
        float sh = g_sh5[k], wk = w6[k];
#pragma unroll
        for (int pp = 0; pp < 8; pp++) {
            float z = fmaxf(acc[kk][pp] + sh, 0.f);
            part[pp] = fmaf(z, wk, part[pp]);
        }
    }
    __syncthreads();
#pragma unroll
    for (int pp = 0; pp < 8; pp++) red[(tp * 8 + pp) * 33 + tk] = part[pp];
    __syncthreads();
    if (tid < 64) {
        float ssum = 0.f;
#pragma unroll
        for (int t = 0; t < 32; t++) ssum += red[tid * 33 + t];
        float aval = 1.f / (1.f + expf(-(ssum + b6[0])));
        g_av[b * NHW + p0 + tid] = aval;
    }
}

// ---------------- K5: out = x * a --------------------------------------------
__global__ void __launch_bounds__(256) k5_scale(const float* __restrict__ x,
                                                float* __restrict__ out)
{
    int idx = blockIdx.x * 256 + threadIdx.x;   // float4 index over 32*256*1024/4
    float4 xv = reinterpret_cast<const float4*>(x)[idx];
    int pix4 = idx & 255;       // 256 float4 per channel row
    int b = idx >> 16;          // 65536 float4 per batch
    float4 av = reinterpret_cast<const float4*>(g_av)[b * 256 + pix4];
    float4 o;
    o.x = xv.x * av.x; o.y = xv.y * av.y; o.z = xv.z * av.z; o.w = xv.w * av.w;
    reinterpret_cast<float4*>(out)[idx] = o;
}

// ---------------- launch ------------------------------------------------------
extern "C" void kernel_launch(void* const* d_in, const int* in_sizes, int n_in,
                              void* d_out, int out_size)
{
    const float* x   = (const float*)d_in[0];
    const float* w1  = (const float*)d_in[1];
    const float* b1  = (const float*)d_in[2];
    const float* g1  = (const float*)d_in[3];
    const float* bt1 = (const float*)d_in[4];
    const float* m1  = (const float*)d_in[5];
    const float* v1  = (const float*)d_in[6];
    const float* w2  = (const float*)d_in[7];
    const float* b2  = (const float*)d_in[8];
    const float* g2  = (const float*)d_in[9];
    const float* bt2 = (const float*)d_in[10];
    const float* m2  = (const float*)d_in[11];
    const float* v2  = (const float*)d_in[12];
    const float* w3  = (const float*)d_in[13];
    const float* b3  = (const float*)d_in[14];
    const float* g3  = (const float*)d_in[15];
    const float* bt3 = (const float*)d_in[16];
    const float* m3  = (const float*)d_in[17];
    const float* v3  = (const float*)d_in[18];
    const float* w4  = (const float*)d_in[19];
    const float* b4  = (const float*)d_in[20];
    const float* w5  = (const float*)d_in[21];
    const float* b5  = (const float*)d_in[22];
    const float* g5  = (const float*)d_in[23];
    const float* bt5 = (const float*)d_in[24];
    const float* m5  = (const float*)d_in[25];
    const float* v5  = (const float*)d_in[26];
    const float* w6  = (const float*)d_in[27];
    const float* b6  = (const float*)d_in[28];

    cudaFuncSetAttribute(k1_conv, cudaFuncAttributeMaxDynamicSharedMemorySize, 196608);
    cudaFuncSetAttribute(k3_aff, cudaFuncAttributeMaxDynamicSharedMemorySize, 51200);
    cudaFuncSetAttribute(k4_final, cudaFuncAttributeMaxDynamicSharedMemorySize, 81408);

    k0_prep<<<NCF + 1, 256>>>(w5, g5, v5, b5, bt5, m5,
                              b1, g1, bt1, m1, v1,
                              b2, g2, bt2, m2, v2,
                              b3, g3, bt3, m3, v3);
    k1_conv<<<dim3(8, 3, NB), 256, 196608>>>(x, w1, w2, w3);
    k2_small<<<dim3(4, NB, 2), 256>>>(w4);
    k3_aff<<<dim3(8, 8, NB), 256, 51200>>>(b4);
    k4_final<<<dim3(16, NB), 256, 81408>>>(w6, b6);
    k5_scale<<<(NB * NINP * NHW / 4) / 256, 256>>>(x, (float*)d_out);
}

// round 4
// speedup vs baseline: 1.0835x; 1.0835x over previous
#include <cuda_runtime.h>
#include <math.h>
#include <stdint.h>

#define NB 32
#define NINP 256
#define NHW 1024
#define NCS 64
#define NAOUT 256
#define NCF 513
#define NC5 256
#define EPSV 1e-5f
#define KP 544          // padded feature count (multiple of 32)
#define NCHUNK 17       // KP / 32

// ---------------- scratch ------------------------------------------------------
__device__ float g_theta[NB * NCS * NHW];   // [b][c][p]
__device__ float g_phi[NB * NCS * NHW];     // [b][c][p]
__device__ float g_WP[NB * NAOUT * NCS];    // [b][o][c]
__device__ float g_TW[NB * NCS * NAOUT];    // [b][c][o]
__device__ float g_y[NB * KP * NHW];        // [b][f][p], f: 0=x_embed, 1..256 aff_a, 257..512 aff_b, 513.. pad(0)
__device__ float g_av[NB * NHW];            // gate a
__device__ float g_w5k[NC5 * KP];           // bn5-scaled w5, [c5][f] matching g_y f-order, zero pad
__device__ float g_sc[3 * NCS];
__device__ float g_sh[3 * NCS];
__device__ float g_sh5[NC5];

__device__ __forceinline__ float f4get(const float4& v, int i) {
    return i == 0 ? v.x : (i == 1 ? v.y : (i == 2 ? v.z : v.w));
}

__device__ __forceinline__ uint32_t smem_u32(const void* p) {
    uint32_t a;
    asm("{ .reg .u64 t; cvta.to.shared.u64 t, %1; cvt.u32.u64 %0, t; }" : "=r"(a) : "l"(p));
    return a;
}

// split fp32 -> (hi, lo) tf32 pair
__device__ __forceinline__ void tf32_split(float v, uint32_t& hi, uint32_t& lo) {
    asm("cvt.rna.tf32.f32 %0, %1;" : "=r"(hi) : "f"(v));
    float res = v - __uint_as_float(hi);
    asm("cvt.rna.tf32.f32 %0, %1;" : "=r"(lo) : "f"(res));
}

// ---------------- K0: fold BN params, build w5k, zero y pad rows --------------
__global__ void k0_prep(const float* __restrict__ w5,
                        const float* __restrict__ g5, const float* __restrict__ v5,
                        const float* __restrict__ b5, const float* __restrict__ bt5,
                        const float* __restrict__ m5,
                        const float* __restrict__ b1, const float* __restrict__ g1,
                        const float* __restrict__ bt1, const float* __restrict__ m1,
                        const float* __restrict__ v1,
                        const float* __restrict__ b2, const float* __restrict__ g2,
                        const float* __restrict__ bt2, const float* __restrict__ m2,
                        const float* __restrict__ v2,
                        const float* __restrict__ b3, const float* __restrict__ g3,
                        const float* __restrict__ bt3, const float* __restrict__ m3,
                        const float* __restrict__ v3)
{
    const int blk = blockIdx.x;
    const int tid = threadIdx.x;
    if (blk < NC5) {
        const int k = blk;
        float s5 = g5[k] * rsqrtf(v5[k] + EPSV);
        for (int f = tid; f < KP; f += 256)
            g_w5k[k * KP + f] = (f < NCF) ? w5[k * NCF + f] * s5 : 0.f;
    } else if (blk == NC5) {
        const int k = tid;
        float s5 = g5[k] * rsqrtf(v5[k] + EPSV);
        g_sh5[k] = (b5[k] - m5[k]) * s5 + bt5[k];
        if (k < 3 * NCS) {
            int cv = k / NCS, c = k % NCS;
            const float* bb = cv == 0 ? b1 : (cv == 1 ? b2 : b3);
            const float* gg = cv == 0 ? g1 : (cv == 1 ? g2 : g3);
            const float* bt = cv == 0 ? bt1 : (cv == 1 ? bt2 : bt3);
            const float* mm = cv == 0 ? m1 : (cv == 1 ? m2 : m3);
            const float* vv = cv == 0 ? v1 : (cv == 1 ? v2 : v3);
            float s = gg[c] * rsqrtf(vv[c] + EPSV);
            g_sc[k] = s;
            g_sh[k] = (bb[c] - mm[c]) * s + bt[c];
        }
    } else {
        // zero pad rows f = 513..543 of g_y for batch (blk - 257)
        const int b = blk - NC5 - 1;
        float4* dst = reinterpret_cast<float4*>(g_y + (size_t)b * KP * NHW + (size_t)NCF * NHW);
        const int n4 = (KP - NCF) * NHW / 4;    // 7936
        float4 z = make_float4(0.f, 0.f, 0.f, 0.f);
        for (int i = tid; i < n4; i += 256) dst[i] = z;
    }
}

// ---------------- K1: theta/phi/x3 convs (+BN+relu), x_embed mean -------------
__global__ void __launch_bounds__(256) k1_conv(const float* __restrict__ x,
                                               const float* __restrict__ w1,
                                               const float* __restrict__ w2,
                                               const float* __restrict__ w3)
{
    extern __shared__ float sm1[];
    float* xs = sm1;                    // [256][128]
    float* ws = sm1 + NINP * 128;       // [64][256]
    const int p0 = blockIdx.x * 128;
    const int cv = blockIdx.y;
    const int b  = blockIdx.z;
    const int tid = threadIdx.x;

    const float* W = cv == 0 ? w1 : (cv == 1 ? w2 : w3);

    const float4* xg4 = reinterpret_cast<const float4*>(x + (size_t)b * NINP * NHW);
    float4* xs4 = reinterpret_cast<float4*>(xs);
    const int p04 = p0 >> 2;
    for (int i = tid; i < NINP * 32; i += 256) {
        int row = i >> 5, c4 = i & 31;
        xs4[i] = xg4[row * (NHW / 4) + p04 + c4];
    }
    const float4* Wg4 = reinterpret_cast<const float4*>(W);
    float4* ws4 = reinterpret_cast<float4*>(ws);
    for (int i = tid; i < (NCS * NINP) / 4; i += 256) ws4[i] = Wg4[i];
    __syncthreads();

    const int tp = tid & 31;
    const int tc = tid >> 5;
    float acc[8][4];
#pragma unroll
    for (int i = 0; i < 8; i++)
#pragma unroll
        for (int j = 0; j < 4; j++) acc[i][j] = 0.f;

#pragma unroll 4
    for (int k4 = 0; k4 < 64; k4++) {
        float4 xv[4];
#pragma unroll
        for (int kk = 0; kk < 4; kk++) xv[kk] = xs4[(k4 * 4 + kk) * 32 + tp];
#pragma unroll
        for (int cc = 0; cc < 8; cc++) {
            float4 wv = ws4[(tc * 8 + cc) * 64 + k4];
#pragma unroll
            for (int kk = 0; kk < 4; kk++) {
                float wk = f4get(wv, kk);
#pragma unroll
                for (int j = 0; j < 4; j++)
                    acc[cc][j] = fmaf(wk, f4get(xv[kk], j), acc[cc][j]);
            }
        }
    }

    if (cv < 2) {
        float* dst = (cv == 0 ? g_theta : g_phi) + (size_t)b * NCS * NHW;
#pragma unroll
        for (int cc = 0; cc < 8; cc++) {
            int c = tc * 8 + cc;
            float s = g_sc[cv * NCS + c], h = g_sh[cv * NCS + c];
            float4 o;
            o.x = fmaxf(fmaf(s, acc[cc][0], h), 0.f);
            o.y = fmaxf(fmaf(s, acc[cc][1], h), 0.f);
            o.z = fmaxf(fmaf(s, acc[cc][2], h), 0.f);
            o.w = fmaxf(fmaf(s, acc[cc][3], h), 0.f);
            reinterpret_cast<float4*>(dst + (size_t)c * NHW + p0)[tp] = o;
        }
    } else {
        float psum[4] = {0.f, 0.f, 0.f, 0.f};
#pragma unroll
        for (int cc = 0; cc < 8; cc++) {
            int c = tc * 8 + cc;
            float s = g_sc[2 * NCS + c], h = g_sh[2 * NCS + c];
#pragma unroll
            for (int j = 0; j < 4; j++)
                psum[j] += fmaxf(fmaf(s, acc[cc][j], h), 0.f);
        }
        __syncthreads();
        float* red = ws;
#pragma unroll
        for (int j = 0; j < 4; j++) red[tc * 128 + tp * 4 + j] = psum[j];
        __syncthreads();
        if (tid < 128) {
            float ssum = 0.f;
#pragma unroll
            for (int t = 0; t < 8; t++) ssum += red[t * 128 + tid];
            g_y[(size_t)b * KP * NHW + p0 + tid] = ssum * (1.f / NCS);  // f = 0 row
        }
    }
}

// ---------------- K2: WP = w4 @ P ; TW = theta @ w4^T -------------------------
__global__ void __launch_bounds__(256) k2_small(const float* __restrict__ w4)
{
    __shared__ __align__(16) float As[64 * 68];
    __shared__ __align__(16) float Bs[64 * 68];
    const int tile = blockIdx.x;
    const int b = blockIdx.y;
    const int which = blockIdx.z;
    const int tid = threadIdx.x;
    const int tm = tid >> 4, tn = tid & 15;

    const float* phi = g_phi + (size_t)b * NCS * NHW;
    const float* th  = g_theta + (size_t)b * NCS * NHW;

    float acc[4][4];
#pragma unroll
    for (int i = 0; i < 4; i++)
#pragma unroll
        for (int j = 0; j < 4; j++) acc[i][j] = 0.f;

    for (int k0 = 0; k0 < NHW; k0 += 64) {
        __syncthreads();
        if (which == 0) {
            const int m0 = tile * 64;
            for (int i = tid; i < 64 * 16; i += 256) {
                int m = i >> 4, kq = i & 15;
                float4 v = *reinterpret_cast<const float4*>(w4 + (size_t)(m0 + m) * NHW + k0 + kq * 4);
                As[(kq * 4 + 0) * 68 + m] = v.x;
                As[(kq * 4 + 1) * 68 + m] = v.y;
                As[(kq * 4 + 2) * 68 + m] = v.z;
                As[(kq * 4 + 3) * 68 + m] = v.w;
            }
            for (int i = tid; i < 64 * 16; i += 256) {
                int k = i >> 4, nq = i & 15;
                float4 v = *reinterpret_cast<const float4*>(phi + (size_t)(k0 + k) * 64 + nq * 4);
                *reinterpret_cast<float4*>(Bs + k * 68 + nq * 4) = v;
            }
        } else {
            for (int i = tid; i < 64 * 16; i += 256) {
                int m = i >> 4, kq = i & 15;
                float4 v = *reinterpret_cast<const float4*>(th + (size_t)m * NHW + k0 + kq * 4);
                As[(kq * 4 + 0) * 68 + m] = v.x;
                As[(kq * 4 + 1) * 68 + m] = v.y;
                As[(kq * 4 + 2) * 68 + m] = v.z;
                As[(kq * 4 + 3) * 68 + m] = v.w;
            }
            const int n0 = tile * 64;
            for (int i = tid; i < 64 * 16; i += 256) {
                int n = i >> 4, kq = i & 15;
                float4 v = *reinterpret_cast<const float4*>(w4 + (size_t)(n0 + n) * NHW + k0 + kq * 4);
                Bs[(kq * 4 + 0) * 68 + n] = v.x;
                Bs[(kq * 4 + 1) * 68 + n] = v.y;
                Bs[(kq * 4 + 2) * 68 + n] = v.z;
                Bs[(kq * 4 + 3) * 68 + n] = v.w;
            }
        }
        __syncthreads();
#pragma unroll 8
        for (int k = 0; k < 64; k++) {
            float4 av = *reinterpret_cast<const float4*>(As + k * 68 + tm * 4);
            float4 bv = *reinterpret_cast<const float4*>(Bs + k * 68 + tn * 4);
#pragma unroll
            for (int i = 0; i < 4; i++)
#pragma unroll
                for (int j = 0; j < 4; j++)
                    acc[i][j] = fmaf(f4get(av, i), f4get(bv, j), acc[i][j]);
        }
    }

    if (which == 0) {
        float* WPd = g_WP + (size_t)b * NAOUT * NCS;
        const int m0 = tile * 64;
#pragma unroll
        for (int i = 0; i < 4; i++)
#pragma unroll
            for (int j = 0; j < 4; j++)
                WPd[(size_t)(m0 + tm * 4 + i) * NCS + tn * 4 + j] = acc[i][j];
    } else {
        float* TWd = g_TW + (size_t)b * NCS * NAOUT;
        const int n0 = tile * 64;
#pragma unroll
        for (int i = 0; i < 4; i++)
#pragma unroll
            for (int j = 0; j < 4; j++)
                TWd[(size_t)(tm * 4 + i) * NAOUT + n0 + tn * 4 + j] = acc[i][j];
    }
}

// ---------------- K3: aff_a / aff_b embeds -> y -------------------------------
__global__ void __launch_bounds__(256) k3_aff(const float* __restrict__ b4)
{
    extern __shared__ float sm3[];
    float* As = sm3;              // [64][68]  A[k=c][o]
    float* Bs = sm3 + 64 * 68;    // [64][132] B[k=c][p]
    const int p0 = blockIdx.x * 128;
    const int by = blockIdx.y;
    const int b  = blockIdx.z;
    const int which = by >> 2;
    const int o0 = (by & 3) * 64;
    const int tid = threadIdx.x;

    if (which == 0) {
        const float* WPd = g_WP + (size_t)b * NAOUT * NCS;
        for (int i = tid; i < 64 * 16; i += 256) {
            int o = i >> 4, cq = i & 15;
            float4 v = *reinterpret_cast<const float4*>(WPd + (size_t)(o0 + o) * NCS + cq * 4);
            As[(cq * 4 + 0) * 68 + o] = v.x;
            As[(cq * 4 + 1) * 68 + o] = v.y;
            As[(cq * 4 + 2) * 68 + o] = v.z;
            As[(cq * 4 + 3) * 68 + o] = v.w;
        }
        const float* th = g_theta + (size_t)b * NCS * NHW;
        for (int i = tid; i < 64 * 32; i += 256) {
            int c = i >> 5, pq = i & 31;
            *reinterpret_cast<float4*>(Bs + c * 132 + pq * 4) =
                *reinterpret_cast<const float4*>(th + (size_t)c * NHW + p0 + pq * 4);
        }
    } else {
        const float* TWd = g_TW + (size_t)b * NCS * NAOUT;
        for (int i = tid; i < 64 * 16; i += 256) {
            int c = i >> 4, oq = i & 15;
            *reinterpret_cast<float4*>(As + c * 68 + oq * 4) =
                *reinterpret_cast<const float4*>(TWd + (size_t)c * NAOUT + o0 + oq * 4);
        }
        const float* phi = g_phi + (size_t)b * NCS * NHW;
        for (int i = tid; i < 128 * 16; i += 256) {
            int p = i >> 4, cq = i & 15;
            float4 v = *reinterpret_cast<const float4*>(phi + (size_t)(p0 + p) * 64 + cq * 4);
            Bs[(cq * 4 + 0) * 132 + p] = v.x;
            Bs[(cq * 4 + 1) * 132 + p] = v.y;
            Bs[(cq * 4 + 2) * 132 + p] = v.z;
            Bs[(cq * 4 + 3) * 132 + p] = v.w;
        }
    }
    __syncthreads();

    const int tp = tid & 31;   // pixels tp*4..+3
    const int tc = tid >> 5;   // out channels tc*8..+7 (local)
    float acc[8][4];
#pragma unroll
    for (int i = 0; i < 8; i++)
#pragma unroll
        for (int j = 0; j < 4; j++) acc[i][j] = 0.f;

#pragma unroll 8
    for (int k = 0; k < 64; k++) {
        float4 xv = *reinterpret_cast<const float4*>(Bs + k * 132 + tp * 4);
        float4 w0 = *reinterpret_cast<const float4*>(As + k * 68 + tc * 8);
        float4 w1v = *reinterpret_cast<const float4*>(As + k * 68 + tc * 8 + 4);
#pragma unroll
        for (int cc = 0; cc < 8; cc++) {
            float wk = cc < 4 ? f4get(w0, cc) : f4get(w1v, cc - 4);
#pragma unroll
            for (int j = 0; j < 4; j++)
                acc[cc][j] = fmaf(wk, f4get(xv, j), acc[cc][j]);
        }
    }

    float* yd = g_y + (size_t)b * KP * NHW + (size_t)(1 + which * NAOUT + o0) * NHW;
#pragma unroll
    for (int cc = 0; cc < 8; cc++) {
        float bb = b4[o0 + tc * 8 + cc];
        float4 o;
        o.x = fmaxf(acc[cc][0] + bb, 0.f);
        o.y = fmaxf(acc[cc][1] + bb, 0.f);
        o.z = fmaxf(acc[cc][2] + bb, 0.f);
        o.w = fmaxf(acc[cc][3] + bb, 0.f);
        *reinterpret_cast<float4*>(yd + (size_t)(tc * 8 + cc) * NHW + p0 + tp * 4) = o;
    }
}

// ---------------- K4: 3xTF32 mma.sync GEMM + fused epilogue -------------------
// grid 256 (pixel tiles of 128), 512 threads (16 warps, 4M x 4N).
// CTA tile: M=256 (c5), N=128 (pixels), K=544 in 17 chunks of 32, cp.async dbuf.
// smem: As[2][256][36] + Bs[2][32][132] = 107520 B
__global__ void __launch_bounds__(512) k4_mma(const float* __restrict__ w6,
                                              const float* __restrict__ b6)
{
    extern __shared__ float sm4[];
    float* As = sm4;                    // [2][256*36]
    float* Bs = sm4 + 2 * 256 * 36;     // [2][32*132]
    const uint32_t As_u = smem_u32(As);
    const uint32_t Bs_u = smem_u32(Bs);
    const int tid = threadIdx.x;
    const int lane = tid & 31;
    const int wid = tid >> 5;
    const int mw = wid & 3;             // M offset mw*64
    const int nw = wid >> 2;            // N offset nw*32
    const int b = blockIdx.x >> 3;
    const int p0 = (blockIdx.x & 7) * 128;
    const float* Bg = g_y + (size_t)b * KP * NHW + p0;

    float acc[4][4][4];
#pragma unroll
    for (int mi = 0; mi < 4; mi++)
#pragma unroll
        for (int ni = 0; ni < 4; ni++)
#pragma unroll
            for (int c = 0; c < 4; c++) acc[mi][ni][c] = 0.f;

#define COPY_CHUNK(ch, buf) do {                                                   \
    const float* as_ = g_w5k + (ch) * 32;                                          \
    for (int i = tid; i < 2048; i += 512) {                                        \
        int row = i >> 3, q = i & 7;                                               \
        uint32_t d = As_u + (uint32_t)((buf) * 9216 + row * 36 + q * 4) * 4u;      \
        asm volatile("cp.async.cg.shared.global [%0], [%1], 16;"                   \
                     :: "r"(d), "l"(as_ + (size_t)row * KP + q * 4));              \
    }                                                                              \
    for (int i = tid; i < 1024; i += 512) {                                        \
        int row = i >> 5, q = i & 31;                                              \
        uint32_t d = Bs_u + (uint32_t)((buf) * 4224 + row * 132 + q * 4) * 4u;     \
        asm volatile("cp.async.cg.shared.global [%0], [%1], 16;"                   \
                     :: "r"(d), "l"(Bg + (size_t)((ch) * 32 + row) * NHW + q * 4));\
    }                                                                              \
    asm volatile("cp.async.commit_group;");                                        \
} while (0)

#define MMA_TF32(ACC, A0, A1, A2, A3, B0, B1)                                      \
    asm volatile(                                                                  \
        "mma.sync.aligned.m16n8k8.row.col.f32.tf32.tf32.f32 "                      \
        "{%0,%1,%2,%3}, {%4,%5,%6,%7}, {%8,%9}, {%0,%1,%2,%3};"                    \
        : "+f"((ACC)[0]), "+f"((ACC)[1]), "+f"((ACC)[2]), "+f"((ACC)[3])           \
        : "r"(A0), "r"(A1), "r"(A2), "r"(A3), "r"(B0), "r"(B1))

    COPY_CHUNK(0, 0);
    for (int ch = 0; ch < NCHUNK; ch++) {
        if (ch < NCHUNK - 1) {
            COPY_CHUNK(ch + 1, (ch + 1) & 1);
            asm volatile("cp.async.wait_group 1;");
        } else {
            asm volatile("cp.async.wait_group 0;");
        }
        __syncthreads();
        const float* A = As + (ch & 1) * 9216 + mw * 64 * 36;
        const float* B = Bs + (ch & 1) * 4224 + nw * 32;
#pragma unroll
        for (int ks = 0; ks < 4; ks++) {
            uint32_t ah[4][4], al[4][4], bh[4][2], bl[4][2];
            const int ar = lane >> 2, ac = ks * 8 + (lane & 3);
#pragma unroll
            for (int mi = 0; mi < 4; mi++) {
                tf32_split(A[(mi * 16 + ar) * 36 + ac],         ah[mi][0], al[mi][0]);
                tf32_split(A[(mi * 16 + ar + 8) * 36 + ac],     ah[mi][1], al[mi][1]);
                tf32_split(A[(mi * 16 + ar) * 36 + ac + 4],     ah[mi][2], al[mi][2]);
                tf32_split(A[(mi * 16 + ar + 8) * 36 + ac + 4], ah[mi][3], al[mi][3]);
            }
            const int br = ks * 8 + (lane & 3), bc = lane >> 2;
#pragma unroll
            for (int ni = 0; ni < 4; ni++) {
                tf32_split(B[br * 132 + ni * 8 + bc],       bh[ni][0], bl[ni][0]);
                tf32_split(B[(br + 4) * 132 + ni * 8 + bc], bh[ni][1], bl[ni][1]);
            }
#pragma unroll
            for (int mi = 0; mi < 4; mi++)
#pragma unroll
                for (int ni = 0; ni < 4; ni++) {
                    MMA_TF32(acc[mi][ni], al[mi][0], al[mi][1], al[mi][2], al[mi][3],
                             bh[ni][0], bh[ni][1]);
                    MMA_TF32(acc[mi][ni], ah[mi][0], ah[mi][1], ah[mi][2], ah[mi][3],
                             bl[ni][0], bl[ni][1]);
                    MMA_TF32(acc[mi][ni], ah[mi][0], ah[mi][1], ah[mi][2], ah[mi][3],
                             bh[ni][0], bh[ni][1]);
                }
        }
        __syncthreads();
    }
#undef COPY_CHUNK
#undef MMA_TF32

    // ---- epilogue: relu(d + sh5) * w6, reduce over m=256, sigmoid ------------
    float shv[8], wkv[8];
#pragma unroll
    for (int mi = 0; mi < 4; mi++)
#pragma unroll
        for (int rh = 0; rh < 2; rh++) {
            int m = mw * 64 + mi * 16 + (lane >> 2) + rh * 8;
            shv[mi * 2 + rh] = g_sh5[m];
            wkv[mi * 2 + rh] = w6[m];
        }

    float* red = sm4;                   // [128][33]
    const int slice = mw * 8 + (lane >> 2);
#pragma unroll
    for (int ni = 0; ni < 4; ni++)
#pragma unroll
        for (int j = 0; j < 2; j++) {
            float s = 0.f;
#pragma unroll
            for (int mi = 0; mi < 4; mi++)
#pragma unroll
                for (int rh = 0; rh < 2; rh++) {
                    float z = fmaxf(acc[mi][ni][rh * 2 + j] + shv[mi * 2 + rh], 0.f);
                    s = fmaf(z, wkv[mi * 2 + rh], s);
                }
            int col = nw * 32 + ni * 8 + 2 * (lane & 3) + j;
            red[col * 33 + slice] = s;
        }
    __syncthreads();
    if (tid < 128) {
        float t = b6[0];
#pragma unroll
        for (int r = 0; r < 32; r++) t += red[tid * 33 + r];
        g_av[b * NHW + p0 + tid] = 1.f / (1.f + expf(-t));
    }
}

// ---------------- K5: out = x * a --------------------------------------------
__global__ void __launch_bounds__(256) k5_scale(const float* __restrict__ x,
                                                float* __restrict__ out)
{
    int idx = blockIdx.x * 256 + threadIdx.x;
    float4 xv = reinterpret_cast<const float4*>(x)[idx];
    int pix4 = idx & 255;
    int b = idx >> 16;
    float4 av = reinterpret_cast<const float4*>(g_av)[b * 256 + pix4];
    float4 o;
    o.x = xv.x * av.x; o.y = xv.y * av.y; o.z = xv.z * av.z; o.w = xv.w * av.w;
    reinterpret_cast<float4*>(out)[idx] = o;
}

// ---------------- launch ------------------------------------------------------
extern "C" void kernel_launch(void* const* d_in, const int* in_sizes, int n_in,
                              void* d_out, int out_size)
{
    const float* x   = (const float*)d_in[0];
    const float* w1  = (const float*)d_in[1];
    const float* b1  = (const float*)d_in[2];
    const float* g1  = (const float*)d_in[3];
    const float* bt1 = (const float*)d_in[4];
    const float* m1  = (const float*)d_in[5];
    const float* v1  = (const float*)d_in[6];
    const float* w2  = (const float*)d_in[7];
    const float* b2  = (const float*)d_in[8];
    const float* g2  = (const float*)d_in[9];
    const float* bt2 = (const float*)d_in[10];
    const float* m2  = (const float*)d_in[11];
    const float* v2  = (const float*)d_in[12];
    const float* w3  = (const float*)d_in[13];
    const float* b3  = (const float*)d_in[14];
    const float* g3  = (const float*)d_in[15];
    const float* bt3 = (const float*)d_in[16];
    const float* m3  = (const float*)d_in[17];
    const float* v3  = (const float*)d_in[18];
    const float* w4  = (const float*)d_in[19];
    const float* b4  = (const float*)d_in[20];
    const float* w5  = (const float*)d_in[21];
    const float* b5  = (const float*)d_in[22];
    const float* g5  = (const float*)d_in[23];
    const float* bt5 = (const float*)d_in[24];
    const float* m5  = (const float*)d_in[25];
    const float* v5  = (const float*)d_in[26];
    const float* w6  = (const float*)d_in[27];
    const float* b6  = (const float*)d_in[28];

    cudaFuncSetAttribute(k1_conv, cudaFuncAttributeMaxDynamicSharedMemorySize, 196608);
    cudaFuncSetAttribute(k3_aff, cudaFuncAttributeMaxDynamicSharedMemorySize, 51200);
    cudaFuncSetAttribute(k4_mma, cudaFuncAttributeMaxDynamicSharedMemorySize, 107520);

    k0_prep<<<NC5 + 1 + NB, 256>>>(w5, g5, v5, b5, bt5, m5,
                                   b1, g1, bt1, m1, v1,
                                   b2, g2, bt2, m2, v2,
                                   b3, g3, bt3, m3, v3);
    k1_conv<<<dim3(8, 3, NB), 256, 196608>>>(x, w1, w2, w3);
    k2_small<<<dim3(4, NB, 2), 256>>>(w4);
    k3_aff<<<dim3(8, 8, NB), 256, 51200>>>(b4);
    k4_mma<<<256, 512, 107520>>>(w6, b6);
    k5_scale<<<(NB * NINP * NHW / 4) / 256, 256>>>(x, (float*)d_out);
}

// round 5
// speedup vs baseline: 1.3045x; 1.2040x over previous
#include <cuda_runtime.h>
#include <cuda_bf16.h>
#include <math.h>
#include <stdint.h>

#define NB 32
#define NINP 256
#define NHW 1024
#define NCS 64
#define NAOUT 256
#define NCF 513
#define NC5 256
#define EPSV 1e-5f
#define KP 544          // padded feature count (multiple of 32)
#define NCHUNK 17       // KP / 32

// ---------------- scratch ------------------------------------------------------
__device__ float g_theta[NB * NCS * NHW];   // [b][c][p]
__device__ float g_phi[NB * NCS * NHW];     // [b][c][p]
__device__ float g_WP[NB * NAOUT * NCS];    // [b][o][c]
__device__ float g_TW[NB * NCS * NAOUT];    // [b][c][o]
// y in split-bf16, [b][pixel][f'] with f' contiguous.
// f' order: 0..255 aff_a, 256..511 aff_b, 512 x_embed, 513..543 pad(0)
__device__ __align__(16) __nv_bfloat16 g_yh[NB * NHW * KP];
__device__ __align__(16) __nv_bfloat16 g_yl[NB * NHW * KP];
__device__ float g_av[NB * NHW];            // gate a
__device__ __align__(16) __nv_bfloat16 g_w5h[NC5 * KP];  // bn5-scaled w5 (f' order), hi part
__device__ __align__(16) __nv_bfloat16 g_w5l[NC5 * KP];  // lo part
__device__ float g_sc[3 * NCS];
__device__ float g_sh[3 * NCS];
__device__ float g_sh5[NC5];

__device__ __forceinline__ float f4get(const float4& v, int i) {
    return i == 0 ? v.x : (i == 1 ? v.y : (i == 2 ? v.z : v.w));
}

__device__ __forceinline__ uint32_t smem_u32(const void* p) {
    uint32_t a;
    asm("{ .reg .u64 t; cvta.to.shared.u64 t, %1; cvt.u32.u64 %0, t; }" : "=r"(a) : "l"(p));
    return a;
}

__device__ __forceinline__ void bf16_split(float v, __nv_bfloat16& h, __nv_bfloat16& l) {
    h = __float2bfloat16_rn(v);
    l = __float2bfloat16_rn(v - __bfloat162float(h));
}

// ---------------- K0: fold BN params, split w5, zero y pad --------------------
__global__ void k0_prep(const float* __restrict__ w5,
                        const float* __restrict__ g5, const float* __restrict__ v5,
                        const float* __restrict__ b5, const float* __restrict__ bt5,
                        const float* __restrict__ m5,
                        const float* __restrict__ b1, const float* __restrict__ g1,
                        const float* __restrict__ bt1, const float* __restrict__ m1,
                        const float* __restrict__ v1,
                        const float* __restrict__ b2, const float* __restrict__ g2,
                        const float* __restrict__ bt2, const float* __restrict__ m2,
                        const float* __restrict__ v2,
                        const float* __restrict__ b3, const float* __restrict__ g3,
                        const float* __restrict__ bt3, const float* __restrict__ m3,
                        const float* __restrict__ v3)
{
    const int blk = blockIdx.x;
    const int tid = threadIdx.x;
    if (blk < NC5) {
        const int k = blk;
        float s5 = g5[k] * rsqrtf(v5[k] + EPSV);
        for (int f = tid; f < KP; f += 256) {
            float val;
            if (f < 512) val = w5[k * NCF + 1 + f] * s5;     // aff channels
            else if (f == 512) val = w5[k * NCF] * s5;       // x_embed channel
            else val = 0.f;
            __nv_bfloat16 h, l;
            bf16_split(val, h, l);
            g_w5h[k * KP + f] = h;
            g_w5l[k * KP + f] = l;
        }
    } else if (blk == NC5) {
        const int k = tid;
        float s5 = g5[k] * rsqrtf(v5[k] + EPSV);
        g_sh5[k] = (b5[k] - m5[k]) * s5 + bt5[k];
        if (k < 3 * NCS) {
            int cv = k / NCS, c = k % NCS;
            const float* bb = cv == 0 ? b1 : (cv == 1 ? b2 : b3);
            const float* gg = cv == 0 ? g1 : (cv == 1 ? g2 : g3);
            const float* bt = cv == 0 ? bt1 : (cv == 1 ? bt2 : bt3);
            const float* mm = cv == 0 ? m1 : (cv == 1 ? m2 : m3);
            const float* vv = cv == 0 ? v1 : (cv == 1 ? v2 : v3);
            float s = gg[c] * rsqrtf(vv[c] + EPSV);
            g_sc[k] = s;
            g_sh[k] = (bb[c] - mm[c]) * s + bt[c];
        }
    } else {
        // zero f' = 512..543 tail (64 B) of every pixel row for batch blk-257.
        // k1 later overwrites f'=512 with x_embed; 513..543 stay zero pad.
        const int b = blk - NC5 - 1;
        char* baseh = (char*)(g_yh + (size_t)b * NHW * KP + 512);
        char* basel = (char*)(g_yl + (size_t)b * NHW * KP + 512);
        uint4 z = make_uint4(0u, 0u, 0u, 0u);
        for (int i = tid; i < NHW * 4; i += 256) {
            int p = i >> 2, q = i & 3;
            *reinterpret_cast<uint4*>(baseh + (size_t)p * (KP * 2) + q * 16) = z;
            *reinterpret_cast<uint4*>(basel + (size_t)p * (KP * 2) + q * 16) = z;
        }
    }
}

// ---------------- K1: theta/phi/x3 convs (+BN+relu), x_embed mean -------------
__global__ void __launch_bounds__(256) k1_conv(const float* __restrict__ x,
                                               const float* __restrict__ w1,
                                               const float* __restrict__ w2,
                                               const float* __restrict__ w3)
{
    extern __shared__ float sm1[];
    float* xs = sm1;                    // [256][128]
    float* ws = sm1 + NINP * 128;       // [64][256]
    const int p0 = blockIdx.x * 128;
    const int cv = blockIdx.y;
    const int b  = blockIdx.z;
    const int tid = threadIdx.x;

    const float* W = cv == 0 ? w1 : (cv == 1 ? w2 : w3);

    const float4* xg4 = reinterpret_cast<const float4*>(x + (size_t)b * NINP * NHW);
    float4* xs4 = reinterpret_cast<float4*>(xs);
    const int p04 = p0 >> 2;
    for (int i = tid; i < NINP * 32; i += 256) {
        int row = i >> 5, c4 = i & 31;
        xs4[i] = xg4[row * (NHW / 4) + p04 + c4];
    }
    const float4* Wg4 = reinterpret_cast<const float4*>(W);
    float4* ws4 = reinterpret_cast<float4*>(ws);
    for (int i = tid; i < (NCS * NINP) / 4; i += 256) ws4[i] = Wg4[i];
    __syncthreads();

    const int tp = tid & 31;
    const int tc = tid >> 5;
    float acc[8][4];
#pragma unroll
    for (int i = 0; i < 8; i++)
#pragma unroll
        for (int j = 0; j < 4; j++) acc[i][j] = 0.f;

#pragma unroll 4
    for (int k4 = 0; k4 < 64; k4++) {
        float4 xv[4];
#pragma unroll
        for (int kk = 0; kk < 4; kk++) xv[kk] = xs4[(k4 * 4 + kk) * 32 + tp];
#pragma unroll
        for (int cc = 0; cc < 8; cc++) {
            float4 wv = ws4[(tc * 8 + cc) * 64 + k4];
#pragma unroll
            for (int kk = 0; kk < 4; kk++) {
                float wk = f4get(wv, kk);
#pragma unroll
                for (int j = 0; j < 4; j++)
                    acc[cc][j] = fmaf(wk, f4get(xv[kk], j), acc[cc][j]);
            }
        }
    }

    if (cv < 2) {
        float* dst = (cv == 0 ? g_theta : g_phi) + (size_t)b * NCS * NHW;
#pragma unroll
        for (int cc = 0; cc < 8; cc++) {
            int c = tc * 8 + cc;
            float s = g_sc[cv * NCS + c], h = g_sh[cv * NCS + c];
            float4 o;
            o.x = fmaxf(fmaf(s, acc[cc][0], h), 0.f);
            o.y = fmaxf(fmaf(s, acc[cc][1], h), 0.f);
            o.z = fmaxf(fmaf(s, acc[cc][2], h), 0.f);
            o.w = fmaxf(fmaf(s, acc[cc][3], h), 0.f);
            reinterpret_cast<float4*>(dst + (size_t)c * NHW + p0)[tp] = o;
        }
    } else {
        float psum[4] = {0.f, 0.f, 0.f, 0.f};
#pragma unroll
        for (int cc = 0; cc < 8; cc++) {
            int c = tc * 8 + cc;
            float s = g_sc[2 * NCS + c], h = g_sh[2 * NCS + c];
#pragma unroll
            for (int j = 0; j < 4; j++)
                psum[j] += fmaxf(fmaf(s, acc[cc][j], h), 0.f);
        }
        __syncthreads();
        float* red = ws;
#pragma unroll
        for (int j = 0; j < 4; j++) red[tc * 128 + tp * 4 + j] = psum[j];
        __syncthreads();
        if (tid < 128) {
            float ssum = 0.f;
#pragma unroll
            for (int t = 0; t < 8; t++) ssum += red[t * 128 + tid];
            float val = ssum * (1.f / NCS);
            __nv_bfloat16 h, l;
            bf16_split(val, h, l);
            size_t base = (size_t)(b * NHW + p0 + tid) * KP + 512;
            g_yh[base] = h;
            g_yl[base] = l;
        }
    }
}

// ---------------- K2: WP = w4 @ P ; TW = theta @ w4^T -------------------------
__global__ void __launch_bounds__(256) k2_small(const float* __restrict__ w4)
{
    __shared__ __align__(16) float As[64 * 68];
    __shared__ __align__(16) float Bs[64 * 68];
    const int tile = blockIdx.x;
    const int b = blockIdx.y;
    const int which = blockIdx.z;
    const int tid = threadIdx.x;
    const int tm = tid >> 4, tn = tid & 15;

    const float* phi = g_phi + (size_t)b * NCS * NHW;
    const float* th  = g_theta + (size_t)b * NCS * NHW;

    float acc[4][4];
#pragma unroll
    for (int i = 0; i < 4; i++)
#pragma unroll
        for (int j = 0; j < 4; j++) acc[i][j] = 0.f;

    for (int k0 = 0; k0 < NHW; k0 += 64) {
        __syncthreads();
        if (which == 0) {
            const int m0 = tile * 64;
            for (int i = tid; i < 64 * 16; i += 256) {
                int m = i >> 4, kq = i & 15;
                float4 v = *reinterpret_cast<const float4*>(w4 + (size_t)(m0 + m) * NHW + k0 + kq * 4);
                As[(kq * 4 + 0) * 68 + m] = v.x;
                As[(kq * 4 + 1) * 68 + m] = v.y;
                As[(kq * 4 + 2) * 68 + m] = v.z;
                As[(kq * 4 + 3) * 68 + m] = v.w;
            }
            for (int i = tid; i < 64 * 16; i += 256) {
                int k = i >> 4, nq = i & 15;
                float4 v = *reinterpret_cast<const float4*>(phi + (size_t)(k0 + k) * 64 + nq * 4);
                *reinterpret_cast<float4*>(Bs + k * 68 + nq * 4) = v;
            }
        } else {
            for (int i = tid; i < 64 * 16; i += 256) {
                int m = i >> 4, kq = i & 15;
                float4 v = *reinterpret_cast<const float4*>(th + (size_t)m * NHW + k0 + kq * 4);
                As[(kq * 4 + 0) * 68 + m] = v.x;
                As[(kq * 4 + 1) * 68 + m] = v.y;
                As[(kq * 4 + 2) * 68 + m] = v.z;
                As[(kq * 4 + 3) * 68 + m] = v.w;
            }
            const int n0 = tile * 64;
            for (int i = tid; i < 64 * 16; i += 256) {
                int n = i >> 4, kq = i & 15;
                float4 v = *reinterpret_cast<const float4*>(w4 + (size_t)(n0 + n) * NHW + k0 + kq * 4);
                Bs[(kq * 4 + 0) * 68 + n] = v.x;
                Bs[(kq * 4 + 1) * 68 + n] = v.y;
                Bs[(kq * 4 + 2) * 68 + n] = v.z;
                Bs[(kq * 4 + 3) * 68 + n] = v.w;
            }
        }
        __syncthreads();
#pragma unroll 8
        for (int k = 0; k < 64; k++) {
            float4 av = *reinterpret_cast<const float4*>(As + k * 68 + tm * 4);
            float4 bv = *reinterpret_cast<const float4*>(Bs + k * 68 + tn * 4);
#pragma unroll
            for (int i = 0; i < 4; i++)
#pragma unroll
                for (int j = 0; j < 4; j++)
                    acc[i][j] = fmaf(f4get(av, i), f4get(bv, j), acc[i][j]);
        }
    }

    if (which == 0) {
        float* WPd = g_WP + (size_t)b * NAOUT * NCS;
        const int m0 = tile * 64;
#pragma unroll
        for (int i = 0; i < 4; i++)
#pragma unroll
            for (int j = 0; j < 4; j++)
                WPd[(size_t)(m0 + tm * 4 + i) * NCS + tn * 4 + j] = acc[i][j];
    } else {
        float* TWd = g_TW + (size_t)b * NCS * NAOUT;
        const int n0 = tile * 64;
#pragma unroll
        for (int i = 0; i < 4; i++)
#pragma unroll
            for (int j = 0; j < 4; j++)
                TWd[(size_t)(tm * 4 + i) * NAOUT + n0 + tn * 4 + j] = acc[i][j];
    }
}

// ---------------- K3: aff_a / aff_b embeds -> split-bf16 y --------------------
// grid (8 ptiles, 8 = 4 otiles x 2 which, 32 b), 256 threads; K=64
__global__ void __launch_bounds__(256) k3_aff(const float* __restrict__ b4)
{
    extern __shared__ float sm3[];
    float* As = sm3;              // [64][68]  A[k=c][o]
    float* Bs = sm3 + 64 * 68;    // [64][132] B[k=c][p]
    const int p0 = blockIdx.x * 128;
    const int by = blockIdx.y;
    const int b  = blockIdx.z;
    const int which = by >> 2;
    const int o0 = (by & 3) * 64;
    const int tid = threadIdx.x;

    if (which == 0) {
        const float* WPd = g_WP + (size_t)b * NAOUT * NCS;
        for (int i = tid; i < 64 * 16; i += 256) {          // transpose WP[o][c] -> As[c][o]
            int o = i >> 4, cq = i & 15;
            float4 v = *reinterpret_cast<const float4*>(WPd + (size_t)(o0 + o) * NCS + cq * 4);
            As[(cq * 4 + 0) * 68 + o] = v.x;
            As[(cq * 4 + 1) * 68 + o] = v.y;
            As[(cq * 4 + 2) * 68 + o] = v.z;
            As[(cq * 4 + 3) * 68 + o] = v.w;
        }
        const float* th = g_theta + (size_t)b * NCS * NHW;
        for (int i = tid; i < 64 * 32; i += 256) {          // Bs[c][p] direct
            int c = i >> 5, pq = i & 31;
            *reinterpret_cast<float4*>(Bs + c * 132 + pq * 4) =
                *reinterpret_cast<const float4*>(th + (size_t)c * NHW + p0 + pq * 4);
        }
    } else {
        const float* TWd = g_TW + (size_t)b * NCS * NAOUT;
        for (int i = tid; i < 64 * 16; i += 256) {          // As[c][o] direct
            int c = i >> 4, oq = i & 15;
            *reinterpret_cast<float4*>(As + c * 68 + oq * 4) =
                *reinterpret_cast<const float4*>(TWd + (size_t)c * NAOUT + o0 + oq * 4);
        }
        const float* phi = g_phi + (size_t)b * NCS * NHW;
        for (int i = tid; i < 128 * 16; i += 256) {         // transpose P[p][c] -> Bs[c][p]
            int p = i >> 4, cq = i & 15;
            float4 v = *reinterpret_cast<const float4*>(phi + (size_t)(p0 + p) * 64 + cq * 4);
            Bs[(cq * 4 + 0) * 132 + p] = v.x;
            Bs[(cq * 4 + 1) * 132 + p] = v.y;
            Bs[(cq * 4 + 2) * 132 + p] = v.z;
            Bs[(cq * 4 + 3) * 132 + p] = v.w;
        }
    }
    __syncthreads();

    const int tf = tid & 15;   // f-quad: local f = tf*4..+3
    const int tp = tid >> 4;   // pixel group: p = tp*8..+7
    float acc[8][4];           // [p][f]
#pragma unroll
    for (int i = 0; i < 8; i++)
#pragma unroll
        for (int j = 0; j < 4; j++) acc[i][j] = 0.f;

#pragma unroll 8
    for (int k = 0; k < 64; k++) {
        float4 bv0 = *reinterpret_cast<const float4*>(Bs + k * 132 + tp * 8);
        float4 bv1 = *reinterpret_cast<const float4*>(Bs + k * 132 + tp * 8 + 4);
        float4 av  = *reinterpret_cast<const float4*>(As + k * 68 + tf * 4);
#pragma unroll
        for (int pp = 0; pp < 8; pp++) {
            float bp = pp < 4 ? f4get(bv0, pp) : f4get(bv1, pp - 4);
#pragma unroll
            for (int ff = 0; ff < 4; ff++)
                acc[pp][ff] = fmaf(bp, f4get(av, ff), acc[pp][ff]);
        }
    }

    const int fbase = which * 256 + o0 + tf * 4;            // f' index
    float4 bb = *reinterpret_cast<const float4*>(b4 + o0 + tf * 4);
#pragma unroll
    for (int pp = 0; pp < 8; pp++) {
        float o0v = fmaxf(acc[pp][0] + bb.x, 0.f);
        float o1v = fmaxf(acc[pp][1] + bb.y, 0.f);
        float o2v = fmaxf(acc[pp][2] + bb.z, 0.f);
        float o3v = fmaxf(acc[pp][3] + bb.w, 0.f);
        __nv_bfloat16 h0, l0, h1, l1, h2, l2, h3, l3;
        bf16_split(o0v, h0, l0); bf16_split(o1v, h1, l1);
        bf16_split(o2v, h2, l2); bf16_split(o3v, h3, l3);
        size_t base = (size_t)(b * NHW + p0 + tp * 8 + pp) * KP + fbase;
        __nv_bfloat162 ph0; ph0.x = h0; ph0.y = h1;
        __nv_bfloat162 ph1; ph1.x = h2; ph1.y = h3;
        __nv_bfloat162 pl0; pl0.x = l0; pl0.y = l1;
        __nv_bfloat162 pl1; pl1.x = l2; pl1.y = l3;
        *reinterpret_cast<__nv_bfloat162*>(&g_yh[base])     = ph0;
        *reinterpret_cast<__nv_bfloat162*>(&g_yh[base + 2]) = ph1;
        *reinterpret_cast<__nv_bfloat162*>(&g_yl[base])     = pl0;
        *reinterpret_cast<__nv_bfloat162*>(&g_yl[base + 2]) = pl1;
    }
}

// ---------------- K4: split-bf16 m16n8k16 GEMM + fused epilogue ---------------
// grid 256 (32b x 8 ptiles of 128 px), 512 threads (16 warps, 4M x 4N).
// CTA tile: M=256 (c5), N=128 (px), K=544 in 17 chunks of 32, cp.async dbuf.
// smem (bf16 elems, row stride 40): Ah[2][10240] Al[2][10240] Bh[2][5120] Bl[2][5120]
//   = 61440 elems = 122880 B
__global__ void __launch_bounds__(512) k4_mma(const float* __restrict__ w6,
                                              const float* __restrict__ b6)
{
    extern __shared__ __nv_bfloat16 smb[];
    const int AH = 0, AL = 20480, BH = 40960, BL = 51200;   // elem offsets
    const uint32_t smb_u = smem_u32(smb);
    const int tid = threadIdx.x;
    const int lane = tid & 31;
    const int wid = tid >> 5;
    const int mw = wid & 3;             // M offset mw*64
    const int nw = wid >> 2;            // N offset nw*32
    const int b = blockIdx.x >> 3;
    const int p0 = (blockIdx.x & 7) * 128;
    const size_t pixbase = (size_t)(b * NHW + p0);

    float acc[4][4][4];
#pragma unroll
    for (int mi = 0; mi < 4; mi++)
#pragma unroll
        for (int ni = 0; ni < 4; ni++)
#pragma unroll
            for (int c = 0; c < 4; c++) acc[mi][ni][c] = 0.f;

    // each cp.async: 16 B = 8 bf16. A: 256 rows x 4 q; B: 128 rows x 4 q.
#define COPY_CHUNK(ch, buf) do {                                                     \
    for (int i = tid; i < 1024; i += 512) {                                          \
        int row = i >> 2, q = i & 3;                                                 \
        uint32_t dh = smb_u + (uint32_t)(AH + (buf) * 10240 + row * 40 + q * 8) * 2u;\
        uint32_t dl = smb_u + (uint32_t)(AL + (buf) * 10240 + row * 40 + q * 8) * 2u;\
        size_t so = (size_t)row * KP + (ch) * 32 + q * 8;                            \
        asm volatile("cp.async.ca.shared.global [%0], [%1], 16;" :: "r"(dh), "l"(g_w5h + so)); \
        asm volatile("cp.async.ca.shared.global [%0], [%1], 16;" :: "r"(dl), "l"(g_w5l + so)); \
    }                                                                                \
    for (int i = tid; i < 512; i += 512) {                                           \
        int row = i >> 2, q = i & 3;                                                 \
        uint32_t dh = smb_u + (uint32_t)(BH + (buf) * 5120 + row * 40 + q * 8) * 2u; \
        uint32_t dl = smb_u + (uint32_t)(BL + (buf) * 5120 + row * 40 + q * 8) * 2u; \
        size_t so = (pixbase + row) * KP + (ch) * 32 + q * 8;                        \
        asm volatile("cp.async.ca.shared.global [%0], [%1], 16;" :: "r"(dh), "l"(g_yh + so)); \
        asm volatile("cp.async.ca.shared.global [%0], [%1], 16;" :: "r"(dl), "l"(g_yl + so)); \
    }                                                                                \
    asm volatile("cp.async.commit_group;");                                          \
} while (0)

#define MMA_BF16(ACC, A0, A1, A2, A3, B0, B1)                                        \
    asm volatile(                                                                    \
        "mma.sync.aligned.m16n8k16.row.col.f32.bf16.bf16.f32 "                       \
        "{%0,%1,%2,%3}, {%4,%5,%6,%7}, {%8,%9}, {%0,%1,%2,%3};"                      \
        : "+f"((ACC)[0]), "+f"((ACC)[1]), "+f"((ACC)[2]), "+f"((ACC)[3])             \
        : "r"(A0), "r"(A1), "r"(A2), "r"(A3), "r"(B0), "r"(B1))

    COPY_CHUNK(0, 0);
    for (int ch = 0; ch < NCHUNK; ch++) {
        if (ch < NCHUNK - 1) {
            COPY_CHUNK(ch + 1, (ch + 1) & 1);
            asm volatile("cp.async.wait_group 1;");
        } else {
            asm volatile("cp.async.wait_group 0;");
        }
        __syncthreads();
        const int buf = ch & 1;
        const __nv_bfloat16* Ah = smb + AH + buf * 10240 + (mw * 64) * 40;
        const __nv_bfloat16* Al = smb + AL + buf * 10240 + (mw * 64) * 40;
        const __nv_bfloat16* Bh = smb + BH + buf * 5120 + (nw * 32) * 40;
        const __nv_bfloat16* Bl = smb + BL + buf * 5120 + (nw * 32) * 40;
#pragma unroll
        for (int ks = 0; ks < 2; ks++) {
            const int ar = lane >> 2;                   // row in 16-row group
            const int ak = ks * 16 + (lane & 3) * 2;    // k pair base
            uint32_t ah[4][4], al[4][4], bh[4][2], bl[4][2];
#pragma unroll
            for (int mi = 0; mi < 4; mi++) {
                int r = mi * 16 + ar;
                ah[mi][0] = *reinterpret_cast<const uint32_t*>(Ah + r * 40 + ak);
                ah[mi][1] = *reinterpret_cast<const uint32_t*>(Ah + (r + 8) * 40 + ak);
                ah[mi][2] = *reinterpret_cast<const uint32_t*>(Ah + r * 40 + ak + 8);
                ah[mi][3] = *reinterpret_cast<const uint32_t*>(Ah + (r + 8) * 40 + ak + 8);
                al[mi][0] = *reinterpret_cast<const uint32_t*>(Al + r * 40 + ak);
                al[mi][1] = *reinterpret_cast<const uint32_t*>(Al + (r + 8) * 40 + ak);
                al[mi][2] = *reinterpret_cast<const uint32_t*>(Al + r * 40 + ak + 8);
                al[mi][3] = *reinterpret_cast<const uint32_t*>(Al + (r + 8) * 40 + ak + 8);
            }
#pragma unroll
            for (int ni = 0; ni < 4; ni++) {
                int n = ni * 8 + (lane >> 2);
                bh[ni][0] = *reinterpret_cast<const uint32_t*>(Bh + n * 40 + ak);
                bh[ni][1] = *reinterpret_cast<const uint32_t*>(Bh + n * 40 + ak + 8);
                bl[ni][0] = *reinterpret_cast<const uint32_t*>(Bl + n * 40 + ak);
                bl[ni][1] = *reinterpret_cast<const uint32_t*>(Bl + n * 40 + ak + 8);
            }
#pragma unroll
            for (int mi = 0; mi < 4; mi++)
#pragma unroll
                for (int ni = 0; ni < 4; ni++) {
                    MMA_BF16(acc[mi][ni], al[mi][0], al[mi][1], al[mi][2], al[mi][3],
                             bh[ni][0], bh[ni][1]);
                    MMA_BF16(acc[mi][ni], ah[mi][0], ah[mi][1], ah[mi][2], ah[mi][3],
                             bl[ni][0], bl[ni][1]);
                    MMA_BF16(acc[mi][ni], ah[mi][0], ah[mi][1], ah[mi][2], ah[mi][3],
                             bh[ni][0], bh[ni][1]);
                }
        }
        __syncthreads();
    }
#undef COPY_CHUNK
#undef MMA_BF16

    // ---- epilogue: relu(d + sh5) * w6, reduce over m=256, sigmoid ------------
    float shv[8], wkv[8];
#pragma unroll
    for (int mi = 0; mi < 4; mi++)
#pragma unroll
        for (int rh = 0; rh < 2; rh++) {
            int m = mw * 64 + mi * 16 + (lane >> 2) + rh * 8;
            shv[mi * 2 + rh] = g_sh5[m];
            wkv[mi * 2 + rh] = w6[m];
        }

    float* red = reinterpret_cast<float*>(smb);     // [128][33]
    const int slice = mw * 8 + (lane >> 2);
#pragma unroll
    for (int ni = 0; ni < 4; ni++)
#pragma unroll
        for (int j = 0; j < 2; j++) {
            float s = 0.f;
#pragma unroll
            for (int mi = 0; mi < 4; mi++)
#pragma unroll
                for (int rh = 0; rh < 2; rh++) {
                    float z = fmaxf(acc[mi][ni][rh * 2 + j] + shv[mi * 2 + rh], 0.f);
                    s = fmaf(z, wkv[mi * 2 + rh], s);
                }
            int col = nw * 32 + ni * 8 + 2 * (lane & 3) + j;
            red[col * 33 + slice] = s;
        }
    __syncthreads();
    if (tid < 128) {
        float t = b6[0];
#pragma unroll
        for (int r = 0; r < 32; r++) t += red[tid * 33 + r];
        g_av[b * NHW + p0 + tid] = 1.f / (1.f + expf(-t));
    }
}

// ---------------- K5: out = x * a --------------------------------------------
__global__ void __launch_bounds__(256) k5_scale(const float* __restrict__ x,
                                                float* __restrict__ out)
{
    int idx = blockIdx.x * 256 + threadIdx.x;
    float4 xv = reinterpret_cast<const float4*>(x)[idx];
    int pix4 = idx & 255;
    int b = idx >> 16;
    float4 av = reinterpret_cast<const float4*>(g_av)[b * 256 + pix4];
    float4 o;
    o.x = xv.x * av.x; o.y = xv.y * av.y; o.z = xv.z * av.z; o.w = xv.w * av.w;
    reinterpret_cast<float4*>(out)[idx] = o;
}

// ---------------- launch ------------------------------------------------------
extern "C" void kernel_launch(void* const* d_in, const int* in_sizes, int n_in,
                              void* d_out, int out_size)
{
    const float* x   = (const float*)d_in[0];
    const float* w1  = (const float*)d_in[1];
    const float* b1  = (const float*)d_in[2];
    const float* g1  = (const float*)d_in[3];
    const float* bt1 = (const float*)d_in[4];
    const float* m1  = (const float*)d_in[5];
    const float* v1  = (const float*)d_in[6];
    const float* w2  = (const float*)d_in[7];
    const float* b2  = (const float*)d_in[8];
    const float* g2  = (const float*)d_in[9];
    const float* bt2 = (const float*)d_in[10];
    const float* m2  = (const float*)d_in[11];
    const float* v2  = (const float*)d_in[12];
    const float* w3  = (const float*)d_in[13];
    const float* b3  = (const float*)d_in[14];
    const float* g3  = (const float*)d_in[15];
    const float* bt3 = (const float*)d_in[16];
    const float* m3  = (const float*)d_in[17];
    const float* v3  = (const float*)d_in[18];
    const float* w4  = (const float*)d_in[19];
    const float* b4  = (const float*)d_in[20];
    const float* w5  = (const float*)d_in[21];
    const float* b5  = (const float*)d_in[22];
    const float* g5  = (const float*)d_in[23];
    const float* bt5 = (const float*)d_in[24];
    const float* m5  = (const float*)d_in[25];
    const float* v5  = (const float*)d_in[26];
    const float* w6  = (const float*)d_in[27];
    const float* b6  = (const float*)d_in[28];

    cudaFuncSetAttribute(k1_conv, cudaFuncAttributeMaxDynamicSharedMemorySize, 196608);
    cudaFuncSetAttribute(k3_aff, cudaFuncAttributeMaxDynamicSharedMemorySize, 51200);
    cudaFuncSetAttribute(k4_mma, cudaFuncAttributeMaxDynamicSharedMemorySize, 122880);

    k0_prep<<<NC5 + 1 + NB, 256>>>(w5, g5, v5, b5, bt5, m5,
                                   b1, g1, bt1, m1, v1,
                                   b2, g2, bt2, m2, v2,
                                   b3, g3, bt3, m3, v3);
    k1_conv<<<dim3(8, 3, NB), 256, 196608>>>(x, w1, w2, w3);
    k2_small<<<dim3(4, NB, 2), 256>>>(w4);
    k3_aff<<<dim3(8, 8, NB), 256, 51200>>>(b4);
    k4_mma<<<256, 512, 122880>>>(w6, b6);
    k5_scale<<<(NB * NINP * NHW / 4) / 256, 256>>>(x, (float*)d_out);
}

// round 7
// speedup vs baseline: 1.5582x; 1.1945x over previous
#include <cuda_runtime.h>
#include <cuda_bf16.h>
#include <math.h>
#include <stdint.h>

#define NB 32
#define NINP 256
#define NHW 1024
#define NCS 64
#define NAOUT 256
#define NCF 513
#define NC5 256
#define EPSV 1e-5f
#define KP 544
#define NCHUNK 17

// ---------------- scratch ------------------------------------------------------
__device__ float g_theta[NB * NCS * NHW];   // [b][c][p] fp32
__device__ float g_phi[NB * NCS * NHW];     // [b][c][p] fp32
__device__ __align__(16) __nv_bfloat16 g_xth[NB * NHW * NINP];  // x^T split hi [b][p][c]
__device__ __align__(16) __nv_bfloat16 g_xtl[NB * NHW * NINP];  // lo
__device__ __align__(16) __nv_bfloat16 g_wch[192 * NINP];       // stacked folded conv w (hi)
__device__ __align__(16) __nv_bfloat16 g_wcl[192 * NINP];
__device__ __align__(16) __nv_bfloat16 g_WPh[NB * 512 * NCS];   // [b][row][c]; rows 0..255 WP, 256..511 TW^T
__device__ __align__(16) __nv_bfloat16 g_WPl[NB * 512 * NCS];
__device__ __align__(16) __nv_bfloat16 g_yh[NB * NHW * KP];     // [b][p][f'] hi
__device__ __align__(16) __nv_bfloat16 g_yl[NB * NHW * KP];
__device__ float g_av[NB * NHW];
__device__ __align__(16) __nv_bfloat16 g_w5h[NC5 * KP];
__device__ __align__(16) __nv_bfloat16 g_w5l[NC5 * KP];
__device__ float g_sc[3 * NCS];
__device__ float g_sh[3 * NCS];
__device__ float g_sh5[NC5];

__device__ __forceinline__ float f4get(const float4& v, int i) {
    return i == 0 ? v.x : (i == 1 ? v.y : (i == 2 ? v.z : v.w));
}

__device__ __forceinline__ uint32_t smem_u32(const void* p) {
    uint32_t a;
    asm("{ .reg .u64 t; cvta.to.shared.u64 t, %1; cvt.u32.u64 %0, t; }" : "=r"(a) : "l"(p));
    return a;
}

__device__ __forceinline__ void bf16_split(float v, __nv_bfloat16& h, __nv_bfloat16& l) {
    h = __float2bfloat16_rn(v);
    l = __float2bfloat16_rn(v - __bfloat162float(h));
}

__device__ __forceinline__ uint32_t pk2(__nv_bfloat16 a, __nv_bfloat16 b) {
    __nv_bfloat162 t; t.x = a; t.y = b;
    return *reinterpret_cast<uint32_t*>(&t);
}

#define MMA_BF16(ACC, A0, A1, A2, A3, B0, B1)                                        \
    asm volatile(                                                                    \
        "mma.sync.aligned.m16n8k16.row.col.f32.bf16.bf16.f32 "                       \
        "{%0,%1,%2,%3}, {%4,%5,%6,%7}, {%8,%9}, {%0,%1,%2,%3};"                      \
        : "+f"((ACC)[0]), "+f"((ACC)[1]), "+f"((ACC)[2]), "+f"((ACC)[3])             \
        : "r"(A0), "r"(A1), "r"(A2), "r"(A3), "r"(B0), "r"(B1))

// ---------------- K0: params, w5 split, conv-w split, y pad zero --------------
__global__ void k0_prep(const float* __restrict__ w5,
                        const float* __restrict__ g5, const float* __restrict__ v5,
                        const float* __restrict__ b5, const float* __restrict__ bt5,
                        const float* __restrict__ m5,
                        const float* __restrict__ w1, const float* __restrict__ b1,
                        const float* __restrict__ g1, const float* __restrict__ bt1,
                        const float* __restrict__ m1, const float* __restrict__ v1,
                        const float* __restrict__ w2, const float* __restrict__ b2,
                        const float* __restrict__ g2, const float* __restrict__ bt2,
                        const float* __restrict__ m2, const float* __restrict__ v2,
                        const float* __restrict__ w3, const float* __restrict__ b3,
                        const float* __restrict__ g3, const float* __restrict__ bt3,
                        const float* __restrict__ m3, const float* __restrict__ v3)
{
    const int blk = blockIdx.x;
    const int tid = threadIdx.x;
    if (blk < NC5) {
        const int k = blk;
        float s5 = g5[k] * rsqrtf(v5[k] + EPSV);
        for (int f = tid; f < KP; f += 256) {
            float val;
            if (f < 512) val = w5[k * NCF + 1 + f] * s5;
            else if (f == 512) val = w5[k * NCF] * s5;
            else val = 0.f;
            __nv_bfloat16 h, l;
            bf16_split(val, h, l);
            g_w5h[k * KP + f] = h;
            g_w5l[k * KP + f] = l;
        }
    } else if (blk == NC5) {
        const int k = tid;
        float s5 = g5[k] * rsqrtf(v5[k] + EPSV);
        g_sh5[k] = (b5[k] - m5[k]) * s5 + bt5[k];
        if (k < 3 * NCS) {
            int cv = k / NCS, c = k % NCS;
            const float* bb = cv == 0 ? b1 : (cv == 1 ? b2 : b3);
            const float* gg = cv == 0 ? g1 : (cv == 1 ? g2 : g3);
            const float* bt = cv == 0 ? bt1 : (cv == 1 ? bt2 : bt3);
            const float* mm = cv == 0 ? m1 : (cv == 1 ? m2 : m3);
            const float* vv = cv == 0 ? v1 : (cv == 1 ? v2 : v3);
            float s = gg[c] * rsqrtf(vv[c] + EPSV);
            g_sc[k] = s;
            g_sh[k] = (bb[c] - mm[c]) * s + bt[c];
        }
    } else if (blk < NC5 + 1 + NB) {
        const int b = blk - NC5 - 1;
        char* baseh = (char*)(g_yh + (size_t)b * NHW * KP + 512);
        char* basel = (char*)(g_yl + (size_t)b * NHW * KP + 512);
        uint4 z = make_uint4(0u, 0u, 0u, 0u);
        for (int i = tid; i < NHW * 4; i += 256) {
            int p = i >> 2, q = i & 3;
            *reinterpret_cast<uint4*>(baseh + (size_t)p * (KP * 2) + q * 16) = z;
            *reinterpret_cast<uint4*>(basel + (size_t)p * (KP * 2) + q * 16) = z;
        }
    } else {
        // folded conv weight split: row = blk - 289, rows 0..191
        const int row = blk - (NC5 + 1 + NB);
        const int cv = row >> 6, c = row & 63;
        const float* W  = cv == 0 ? w1 : (cv == 1 ? w2 : w3);
        const float* gg = cv == 0 ? g1 : (cv == 1 ? g2 : g3);
        const float* vv = cv == 0 ? v1 : (cv == 1 ? v2 : v3);
        float s = gg[c] * rsqrtf(vv[c] + EPSV);
        float val = W[c * NINP + tid] * s;
        __nv_bfloat16 h, l;
        bf16_split(val, h, l);
        g_wch[row * NINP + tid] = h;
        g_wcl[row * NINP + tid] = l;
    }
}

// ---------------- Kx: x [b][c][p] fp32 -> x^T [b][p][c] split bf16 ------------
// grid (16 ptiles of 64, 4 ctiles of 64, 32 b), 256 thr
__global__ void __launch_bounds__(256) k_x(const float* __restrict__ x)
{
    __shared__ float sm[64 * 68];
    const int p0 = blockIdx.x * 64;
    const int c0 = blockIdx.y * 64;
    const int b  = blockIdx.z;
    const int tid = threadIdx.x;

    const float* src = x + (size_t)b * NINP * NHW;
    for (int i = tid; i < 1024; i += 256) {
        int c = i >> 4, pq = i & 15;
        float4 v = *reinterpret_cast<const float4*>(src + (size_t)(c0 + c) * NHW + p0 + pq * 4);
        *reinterpret_cast<float4*>(sm + c * 68 + pq * 4) = v;
    }
    __syncthreads();

    const int p = tid >> 2;
    const int cs = (tid & 3) * 16;
    uint32_t hb[8], lb[8];
#pragma unroll
    for (int j2 = 0; j2 < 8; j2++) {
        __nv_bfloat16 h0, l0, h1, l1;
        bf16_split(sm[(cs + j2 * 2) * 68 + p], h0, l0);
        bf16_split(sm[(cs + j2 * 2 + 1) * 68 + p], h1, l1);
        hb[j2] = pk2(h0, h1);
        lb[j2] = pk2(l0, l1);
    }
    size_t base = ((size_t)(b * NHW + p0 + p)) * NINP + c0 + cs;
    *reinterpret_cast<uint4*>(&g_xth[base])     = make_uint4(hb[0], hb[1], hb[2], hb[3]);
    *reinterpret_cast<uint4*>(&g_xth[base + 8]) = make_uint4(hb[4], hb[5], hb[6], hb[7]);
    *reinterpret_cast<uint4*>(&g_xtl[base])     = make_uint4(lb[0], lb[1], lb[2], lb[3]);
    *reinterpret_cast<uint4*>(&g_xtl[base + 8]) = make_uint4(lb[4], lb[5], lb[6], lb[7]);
}

// ---------------- K1: conv GEMM C[192,128px] = Wc[192,256] @ xt^T -------------
// grid (8 ptiles, 32 b), 384 thr = 12 warps (3 M x 4 N)
// smem bf16: Ah[2][7680] Al[2][7680] Bh[2][5120] Bl[2][5120] = 51200 el = 102400 B
__global__ void __launch_bounds__(384) k1_mma(const float* __restrict__ dummy)
{
    extern __shared__ __nv_bfloat16 smb[];
    const int AH = 0, AL = 15360, BH = 30720, BL = 40960;
    const uint32_t smb_u = smem_u32(smb);
    const int tid = threadIdx.x;
    const int lane = tid & 31;
    const int wid = tid >> 5;
    const int mw3 = wid % 3;            // conv id / M-tile
    const int nw4 = wid / 3;            // N: nw4*32 pixels
    const int b = blockIdx.y;
    const int p0 = blockIdx.x * 128;

    float acc[4][4][4];
#pragma unroll
    for (int mi = 0; mi < 4; mi++)
#pragma unroll
        for (int ni = 0; ni < 4; ni++)
#pragma unroll
            for (int c = 0; c < 4; c++) acc[mi][ni][c] = 0.f;

#define K1_COPY(ch, buf) do {                                                         \
    for (int i = tid; i < 768; i += 384) {                                            \
        int row = i >> 2, q = i & 3;                                                  \
        uint32_t dh = smb_u + (uint32_t)(AH + (buf) * 7680 + row * 40 + q * 8) * 2u;  \
        uint32_t dl = smb_u + (uint32_t)(AL + (buf) * 7680 + row * 40 + q * 8) * 2u;  \
        size_t so = (size_t)row * NINP + (ch) * 32 + q * 8;                           \
        asm volatile("cp.async.ca.shared.global [%0], [%1], 16;" :: "r"(dh), "l"(g_wch + so)); \
        asm volatile("cp.async.ca.shared.global [%0], [%1], 16;" :: "r"(dl), "l"(g_wcl + so)); \
    }                                                                                 \
    for (int i = tid; i < 512; i += 384) {                                            \
        int row = i >> 2, q = i & 3;                                                  \
        uint32_t dh = smb_u + (uint32_t)(BH + (buf) * 5120 + row * 40 + q * 8) * 2u;  \
        uint32_t dl = smb_u + (uint32_t)(BL + (buf) * 5120 + row * 40 + q * 8) * 2u;  \
        size_t so = ((size_t)(b * NHW + p0 + row)) * NINP + (ch) * 32 + q * 8;        \
        asm volatile("cp.async.ca.shared.global [%0], [%1], 16;" :: "r"(dh), "l"(g_xth + so)); \
        asm volatile("cp.async.ca.shared.global [%0], [%1], 16;" :: "r"(dl), "l"(g_xtl + so)); \
    }                                                                                 \
    asm volatile("cp.async.commit_group;");                                           \
} while (0)

    K1_COPY(0, 0);
    for (int ch = 0; ch < 8; ch++) {
        if (ch < 7) {
            K1_COPY(ch + 1, (ch + 1) & 1);
            asm volatile("cp.async.wait_group 1;");
        } else {
            asm volatile("cp.async.wait_group 0;");
        }
        __syncthreads();
        const int buf = ch & 1;
        const __nv_bfloat16* Ah = smb + AH + buf * 7680 + (mw3 * 64) * 40;
        const __nv_bfloat16* Al = smb + AL + buf * 7680 + (mw3 * 64) * 40;
        const __nv_bfloat16* Bh = smb + BH + buf * 5120 + (nw4 * 32) * 40;
        const __nv_bfloat16* Bl = smb + BL + buf * 5120 + (nw4 * 32) * 40;
#pragma unroll
        for (int ks = 0; ks < 2; ks++) {
            const int ar = lane >> 2;
            const int ak = ks * 16 + (lane & 3) * 2;
            uint32_t ah[4][4], al[4][4], bh[4][2], bl[4][2];
#pragma unroll
            for (int mi = 0; mi < 4; mi++) {
                int r = mi * 16 + ar;
                ah[mi][0] = *reinterpret_cast<const uint32_t*>(Ah + r * 40 + ak);
                ah[mi][1] = *reinterpret_cast<const uint32_t*>(Ah + (r + 8) * 40 + ak);
                ah[mi][2] = *reinterpret_cast<const uint32_t*>(Ah + r * 40 + ak + 8);
                ah[mi][3] = *reinterpret_cast<const uint32_t*>(Ah + (r + 8) * 40 + ak + 8);
                al[mi][0] = *reinterpret_cast<const uint32_t*>(Al + r * 40 + ak);
                al[mi][1] = *reinterpret_cast<const uint32_t*>(Al + (r + 8) * 40 + ak);
                al[mi][2] = *reinterpret_cast<const uint32_t*>(Al + r * 40 + ak + 8);
                al[mi][3] = *reinterpret_cast<const uint32_t*>(Al + (r + 8) * 40 + ak + 8);
            }
#pragma unroll
            for (int ni = 0; ni < 4; ni++) {
                int n = ni * 8 + (lane >> 2);
                bh[ni][0] = *reinterpret_cast<const uint32_t*>(Bh + n * 40 + ak);
                bh[ni][1] = *reinterpret_cast<const uint32_t*>(Bh + n * 40 + ak + 8);
                bl[ni][0] = *reinterpret_cast<const uint32_t*>(Bl + n * 40 + ak);
                bl[ni][1] = *reinterpret_cast<const uint32_t*>(Bl + n * 40 + ak + 8);
            }
#pragma unroll
            for (int mi = 0; mi < 4; mi++)
#pragma unroll
                for (int ni = 0; ni < 4; ni++) {
                    MMA_BF16(acc[mi][ni], al[mi][0], al[mi][1], al[mi][2], al[mi][3],
                             bh[ni][0], bh[ni][1]);
                    MMA_BF16(acc[mi][ni], ah[mi][0], ah[mi][1], ah[mi][2], ah[mi][3],
                             bl[ni][0], bl[ni][1]);
                    MMA_BF16(acc[mi][ni], ah[mi][0], ah[mi][1], ah[mi][2], ah[mi][3],
                             bh[ni][0], bh[ni][1]);
                }
        }
        __syncthreads();
    }
#undef K1_COPY

    // ---- epilogue ----
    const int ar = lane >> 2;
    const int qq = lane & 3;
    if (mw3 < 2) {
        float* dst = (mw3 == 0 ? g_theta : g_phi) + (size_t)b * NCS * NHW;
#pragma unroll
        for (int mi = 0; mi < 4; mi++)
#pragma unroll
            for (int rh = 0; rh < 2; rh++) {
                int c = mi * 16 + ar + rh * 8;
                float sh = g_sh[mw3 * 64 + c];
#pragma unroll
                for (int ni = 0; ni < 4; ni++) {
                    int px = p0 + nw4 * 32 + ni * 8 + 2 * qq;
                    float2 o;
                    o.x = fmaxf(acc[mi][ni][rh * 2 + 0] + sh, 0.f);
                    o.y = fmaxf(acc[mi][ni][rh * 2 + 1] + sh, 0.f);
                    *reinterpret_cast<float2*>(dst + (size_t)c * NHW + px) = o;
                }
            }
    } else {
        float s_px[8];
#pragma unroll
        for (int ni = 0; ni < 4; ni++)
#pragma unroll
            for (int j = 0; j < 2; j++) {
                float s = 0.f;
#pragma unroll
                for (int mi = 0; mi < 4; mi++)
#pragma unroll
                    for (int rh = 0; rh < 2; rh++) {
                        int c = mi * 16 + ar + rh * 8;
                        s += fmaxf(acc[mi][ni][rh * 2 + j] + g_sh[128 + c], 0.f);
                    }
                s_px[ni * 2 + j] = s;
            }
#pragma unroll
        for (int v = 0; v < 8; v++) {
            s_px[v] += __shfl_xor_sync(0xffffffffu, s_px[v], 4);
            s_px[v] += __shfl_xor_sync(0xffffffffu, s_px[v], 8);
            s_px[v] += __shfl_xor_sync(0xffffffffu, s_px[v], 16);
        }
        if (lane < 4) {
#pragma unroll
            for (int ni = 0; ni < 4; ni++)
#pragma unroll
                for (int j = 0; j < 2; j++) {
                    int px = p0 + nw4 * 32 + ni * 8 + 2 * lane + j;
                    float val = s_px[ni * 2 + j] * (1.f / NCS);
                    __nv_bfloat16 h, l;
                    bf16_split(val, h, l);
                    size_t base = (size_t)(b * NHW + px) * KP + 512;
                    g_yh[base] = h;
                    g_yl[base] = l;
                }
        }
    }
}

// ---------------- K2: WP = w4 @ P ; TW^T; outputs split bf16 [row][c] ---------
__global__ void __launch_bounds__(256) k2_small(const float* __restrict__ w4)
{
    __shared__ __align__(16) float As[64 * 68];
    __shared__ __align__(16) float Bs[64 * 68];
    const int tile = blockIdx.x;
    const int b = blockIdx.y;
    const int which = blockIdx.z;
    const int tid = threadIdx.x;
    const int tm = tid >> 4, tn = tid & 15;

    const float* phi = g_phi + (size_t)b * NCS * NHW;
    const float* th  = g_theta + (size_t)b * NCS * NHW;

    float acc[4][4];
#pragma unroll
    for (int i = 0; i < 4; i++)
#pragma unroll
        for (int j = 0; j < 4; j++) acc[i][j] = 0.f;

    for (int k0 = 0; k0 < NHW; k0 += 64) {
        __syncthreads();
        if (which == 0) {
            const int m0 = tile * 64;
            for (int i = tid; i < 64 * 16; i += 256) {
                int m = i >> 4, kq = i & 15;
                float4 v = *reinterpret_cast<const float4*>(w4 + (size_t)(m0 + m) * NHW + k0 + kq * 4);
                As[(kq * 4 + 0) * 68 + m] = v.x;
                As[(kq * 4 + 1) * 68 + m] = v.y;
                As[(kq * 4 + 2) * 68 + m] = v.z;
                As[(kq * 4 + 3) * 68 + m] = v.w;
            }
            for (int i = tid; i < 64 * 16; i += 256) {
                int k = i >> 4, nq = i & 15;
                float4 v = *reinterpret_cast<const float4*>(phi + (size_t)(k0 + k) * 64 + nq * 4);
                *reinterpret_cast<float4*>(Bs + k * 68 + nq * 4) = v;
            }
        } else {
            for (int i = tid; i < 64 * 16; i += 256) {
                int m = i >> 4, kq = i & 15;
                float4 v = *reinterpret_cast<const float4*>(th + (size_t)m * NHW + k0 + kq * 4);
                As[(kq * 4 + 0) * 68 + m] = v.x;
                As[(kq * 4 + 1) * 68 + m] = v.y;
                As[(kq * 4 + 2) * 68 + m] = v.z;
                As[(kq * 4 + 3) * 68 + m] = v.w;
            }
            const int n0 = tile * 64;
            for (int i = tid; i < 64 * 16; i += 256) {
                int n = i >> 4, kq = i & 15;
                float4 v = *reinterpret_cast<const float4*>(w4 + (size_t)(n0 + n) * NHW + k0 + kq * 4);
                Bs[(kq * 4 + 0) * 68 + n] = v.x;
                Bs[(kq * 4 + 1) * 68 + n] = v.y;
                Bs[(kq * 4 + 2) * 68 + n] = v.z;
                Bs[(kq * 4 + 3) * 68 + n] = v.w;
            }
        }
        __syncthreads();
#pragma unroll 8
        for (int k = 0; k < 64; k++) {
            float4 av = *reinterpret_cast<const float4*>(As + k * 68 + tm * 4);
            float4 bv = *reinterpret_cast<const float4*>(Bs + k * 68 + tn * 4);
#pragma unroll
            for (int i = 0; i < 4; i++)
#pragma unroll
                for (int j = 0; j < 4; j++)
                    acc[i][j] = fmaf(f4get(av, i), f4get(bv, j), acc[i][j]);
        }
    }

    __nv_bfloat16* WH = g_WPh + (size_t)b * 512 * NCS;
    __nv_bfloat16* WL = g_WPl + (size_t)b * 512 * NCS;
    if (which == 0) {
        const int m0 = tile * 64;
#pragma unroll
        for (int i = 0; i < 4; i++) {
            int o = m0 + tm * 4 + i;
            __nv_bfloat16 h[4], l[4];
#pragma unroll
            for (int j = 0; j < 4; j++) bf16_split(acc[i][j], h[j], l[j]);
            *reinterpret_cast<uint2*>(WH + o * NCS + tn * 4) =
                make_uint2(pk2(h[0], h[1]), pk2(h[2], h[3]));
            *reinterpret_cast<uint2*>(WL + o * NCS + tn * 4) =
                make_uint2(pk2(l[0], l[1]), pk2(l[2], l[3]));
        }
    } else {
        const int n0 = tile * 64;
#pragma unroll
        for (int j = 0; j < 4; j++) {
            int o = 256 + n0 + tn * 4 + j;
            __nv_bfloat16 h[4], l[4];
#pragma unroll
            for (int i = 0; i < 4; i++) bf16_split(acc[i][j], h[i], l[i]);
            *reinterpret_cast<uint2*>(WH + o * NCS + tm * 4) =
                make_uint2(pk2(h[0], h[1]), pk2(h[2], h[3]));
            *reinterpret_cast<uint2*>(WL + o * NCS + tm * 4) =
                make_uint2(pk2(l[0], l[1]), pk2(l[2], l[3]));
        }
    }
}

// ---------------- K3: C[128px, 256f] = A[px, 64c] @ B[f, 64c]^T ---------------
// grid (8 ptiles, 2 which, 32 b), 512 thr = 16 warps (4M x 4N)
// smem bf16: Ah[9216] Al[9216] Bh[18432] Bl[18432] = 55296 el = 110592 B (stride 72)
__global__ void __launch_bounds__(512) k3_mma(const float* __restrict__ b4)
{
    extern __shared__ __nv_bfloat16 smb[];
    const int AH = 0, AL = 9216, BH = 18432, BL = 36864;
    const uint32_t smb_u = smem_u32(smb);
    const int tid = threadIdx.x;
    const int lane = tid & 31;
    const int wid = tid >> 5;
    const int mw = wid & 3;             // M: mw*32 px
    const int nw = wid >> 2;            // N: nw*64 f
    const int p0 = blockIdx.x * 128;
    const int which = blockIdx.y;
    const int b = blockIdx.z;

    // B: WP/TWt rows [which*256 .. +256), 64 c each — cp.async
    {
        const __nv_bfloat16* srch = g_WPh + ((size_t)b * 512 + which * 256) * NCS;
        const __nv_bfloat16* srcl = g_WPl + ((size_t)b * 512 + which * 256) * NCS;
        for (int i = tid; i < 2048; i += 512) {
            int row = i >> 3, q = i & 7;
            uint32_t dh = smb_u + (uint32_t)(BH + row * 72 + q * 8) * 2u;
            uint32_t dl = smb_u + (uint32_t)(BL + row * 72 + q * 8) * 2u;
            size_t so = (size_t)row * NCS + q * 8;
            asm volatile("cp.async.ca.shared.global [%0], [%1], 16;" :: "r"(dh), "l"(srch + so));
            asm volatile("cp.async.ca.shared.global [%0], [%1], 16;" :: "r"(dl), "l"(srcl + so));
        }
        asm volatile("cp.async.commit_group;");
    }
    // A: convert from fp32 theta (transposed read) or phi (flat read)
    if (which == 0) {
        const float* th = g_theta + (size_t)b * NCS * NHW;
        for (int i = tid; i < 2048; i += 512) {
            int c = i >> 5, pq = i & 31;
            float4 v = *reinterpret_cast<const float4*>(th + (size_t)c * NHW + p0 + pq * 4);
#pragma unroll
            for (int j = 0; j < 4; j++) {
                __nv_bfloat16 h, l;
                bf16_split(f4get(v, j), h, l);
                smb[AH + (pq * 4 + j) * 72 + c] = h;
                smb[AL + (pq * 4 + j) * 72 + c] = l;
            }
        }
    } else {
        const float* ph = g_phi + (size_t)b * NCS * NHW;   // flat [j][c], c contig
        for (int i = tid; i < 2048; i += 512) {
            int p = i >> 4, cq = i & 15;
            float4 v = *reinterpret_cast<const float4*>(ph + (size_t)(p0 + p) * NCS + cq * 4);
            __nv_bfloat16 h0, l0, h1, l1, h2, l2, h3, l3;
            bf16_split(v.x, h0, l0); bf16_split(v.y, h1, l1);
            bf16_split(v.z, h2, l2); bf16_split(v.w, h3, l3);
            *reinterpret_cast<uint2*>(&smb[AH + p * 72 + cq * 4]) =
                make_uint2(pk2(h0, h1), pk2(h2, h3));
            *reinterpret_cast<uint2*>(&smb[AL + p * 72 + cq * 4]) =
                make_uint2(pk2(l0, l1), pk2(l2, l3));
        }
    }
    asm volatile("cp.async.wait_group 0;");
    __syncthreads();

    float acc[2][8][4];
#pragma unroll
    for (int mi = 0; mi < 2; mi++)
#pragma unroll
        for (int ni = 0; ni < 8; ni++)
#pragma unroll
            for (int c = 0; c < 4; c++) acc[mi][ni][c] = 0.f;

    const __nv_bfloat16* Ah = smb + AH + (mw * 32) * 72;
    const __nv_bfloat16* Al = smb + AL + (mw * 32) * 72;
    const __nv_bfloat16* Bh = smb + BH + (nw * 64) * 72;
    const __nv_bfloat16* Bl = smb + BL + (nw * 64) * 72;
#pragma unroll
    for (int ks = 0; ks < 4; ks++) {
        const int ar = lane >> 2;
        const int ak = ks * 16 + (lane & 3) * 2;
        uint32_t ah[2][4], al[2][4];
#pragma unroll
        for (int mi = 0; mi < 2; mi++) {
            int r = mi * 16 + ar;
            ah[mi][0] = *reinterpret_cast<const uint32_t*>(Ah + r * 72 + ak);
            ah[mi][1] = *reinterpret_cast<const uint32_t*>(Ah + (r + 8) * 72 + ak);
            ah[mi][2] = *reinterpret_cast<const uint32_t*>(Ah + r * 72 + ak + 8);
            ah[mi][3] = *reinterpret_cast<const uint32_t*>(Ah + (r + 8) * 72 + ak + 8);
            al[mi][0] = *reinterpret_cast<const uint32_t*>(Al + r * 72 + ak);
            al[mi][1] = *reinterpret_cast<const uint32_t*>(Al + (r + 8) * 72 + ak);
            al[mi][2] = *reinterpret_cast<const uint32_t*>(Al + r * 72 + ak + 8);
            al[mi][3] = *reinterpret_cast<const uint32_t*>(Al + (r + 8) * 72 + ak + 8);
        }
#pragma unroll
        for (int ni = 0; ni < 8; ni++) {
            int n = ni * 8 + (lane >> 2);
            uint32_t bh0 = *reinterpret_cast<const uint32_t*>(Bh + n * 72 + ak);
            uint32_t bh1 = *reinterpret_cast<const uint32_t*>(Bh + n * 72 + ak + 8);
            uint32_t bl0 = *reinterpret_cast<const uint32_t*>(Bl + n * 72 + ak);
            uint32_t bl1 = *reinterpret_cast<const uint32_t*>(Bl + n * 72 + ak + 8);
#pragma unroll
            for (int mi = 0; mi < 2; mi++) {
                MMA_BF16(acc[mi][ni], al[mi][0], al[mi][1], al[mi][2], al[mi][3], bh0, bh1);
                MMA_BF16(acc[mi][ni], ah[mi][0], ah[mi][1], ah[mi][2], ah[mi][3], bl0, bl1);
                MMA_BF16(acc[mi][ni], ah[mi][0], ah[mi][1], ah[mi][2], ah[mi][3], bh0, bh1);
            }
        }
    }

    // epilogue: relu(acc + b4[o]) -> split bf16 -> y[p][f']
    const int ar = lane >> 2;
    const int qq = lane & 3;
#pragma unroll
    for (int ni = 0; ni < 8; ni++) {
        int o = nw * 64 + ni * 8 + 2 * qq;
        float2 bb = *reinterpret_cast<const float2*>(b4 + o);
        int f0 = which * 256 + o;
#pragma unroll
        for (int mi = 0; mi < 2; mi++)
#pragma unroll
            for (int rh = 0; rh < 2; rh++) {
                int px = p0 + mw * 32 + mi * 16 + ar + rh * 8;
                float v0 = fmaxf(acc[mi][ni][rh * 2 + 0] + bb.x, 0.f);
                float v1 = fmaxf(acc[mi][ni][rh * 2 + 1] + bb.y, 0.f);
                __nv_bfloat16 h0, l0, h1, l1;
                bf16_split(v0, h0, l0);
                bf16_split(v1, h1, l1);
                size_t base = (size_t)(b * NHW + px) * KP + f0;
                *reinterpret_cast<uint32_t*>(&g_yh[base]) = pk2(h0, h1);
                *reinterpret_cast<uint32_t*>(&g_yl[base]) = pk2(l0, l1);
            }
    }
}

// ---------------- K4: split-bf16 m16n8k16 GEMM + fused epilogue ---------------
__global__ void __launch_bounds__(512) k4_mma(const float* __restrict__ w6,
                                              const float* __restrict__ b6)
{
    extern __shared__ __nv_bfloat16 smb[];
    const int AH = 0, AL = 20480, BH = 40960, BL = 51200;
    const uint32_t smb_u = smem_u32(smb);
    const int tid = threadIdx.x;
    const int lane = tid & 31;
    const int wid = tid >> 5;
    const int mw = wid & 3;
    const int nw = wid >> 2;
    const int b = blockIdx.x >> 3;
    const int p0 = (blockIdx.x & 7) * 128;
    const size_t pixbase = (size_t)(b * NHW + p0);

    float acc[4][4][4];
#pragma unroll
    for (int mi = 0; mi < 4; mi++)
#pragma unroll
        for (int ni = 0; ni < 4; ni++)
#pragma unroll
            for (int c = 0; c < 4; c++) acc[mi][ni][c] = 0.f;

#define COPY_CHUNK(ch, buf) do {                                                     \
    for (int i = tid; i < 1024; i += 512) {                                          \
        int row = i >> 2, q = i & 3;                                                 \
        uint32_t dh = smb_u + (uint32_t)(AH + (buf) * 10240 + row * 40 + q * 8) * 2u;\
        uint32_t dl = smb_u + (uint32_t)(AL + (buf) * 10240 + row * 40 + q * 8) * 2u;\
        size_t so = (size_t)row * KP + (ch) * 32 + q * 8;                            \
        asm volatile("cp.async.ca.shared.global [%0], [%1], 16;" :: "r"(dh), "l"(g_w5h + so)); \
        asm volatile("cp.async.ca.shared.global [%0], [%1], 16;" :: "r"(dl), "l"(g_w5l + so)); \
    }                                                                                \
    for (int i = tid; i < 512; i += 512) {                                           \
        int row = i >> 2, q = i & 3;                                                 \
        uint32_t dh = smb_u + (uint32_t)(BH + (buf) * 5120 + row * 40 + q * 8) * 2u; \
        uint32_t dl = smb_u + (uint32_t)(BL + (buf) * 5120 + row * 40 + q * 8) * 2u; \
        size_t so = (pixbase + row) * KP + (ch) * 32 + q * 8;                        \
        asm volatile("cp.async.ca.shared.global [%0], [%1], 16;" :: "r"(dh), "l"(g_yh + so)); \
        asm volatile("cp.async.ca.shared.global [%0], [%1], 16;" :: "r"(dl), "l"(g_yl + so)); \
    }                                                                                \
    asm volatile("cp.async.commit_group;");                                          \
} while (0)

    COPY_CHUNK(0, 0);
    for (int ch = 0; ch < NCHUNK; ch++) {
        if (ch < NCHUNK - 1) {
            COPY_CHUNK(ch + 1, (ch + 1) & 1);
            asm volatile("cp.async.wait_group 1;");
        } else {
            asm volatile("cp.async.wait_group 0;");
        }
        __syncthreads();
        const int buf = ch & 1;
        const __nv_bfloat16* Ah = smb + AH + buf * 10240 + (mw * 64) * 40;
        const __nv_bfloat16* Al = smb + AL + buf * 10240 + (mw * 64) * 40;
        const __nv_bfloat16* Bh = smb + BH + buf * 5120 + (nw * 32) * 40;
        const __nv_bfloat16* Bl = smb + BL + buf * 5120 + (nw * 32) * 40;
#pragma unroll
        for (int ks = 0; ks < 2; ks++) {
            const int ar = lane >> 2;
            const int ak = ks * 16 + (lane & 3) * 2;
            uint32_t ah[4][4], al[4][4], bh[4][2], bl[4][2];
#pragma unroll
            for (int mi = 0; mi < 4; mi++) {
                int r = mi * 16 + ar;
                ah[mi][0] = *reinterpret_cast<const uint32_t*>(Ah + r * 40 + ak);
                ah[mi][1] = *reinterpret_cast<const uint32_t*>(Ah + (r + 8) * 40 + ak);
                ah[mi][2] = *reinterpret_cast<const uint32_t*>(Ah + r * 40 + ak + 8);
                ah[mi][3] = *reinterpret_cast<const uint32_t*>(Ah + (r + 8) * 40 + ak + 8);
                al[mi][0] = *reinterpret_cast<const uint32_t*>(Al + r * 40 + ak);
                al[mi][1] = *reinterpret_cast<const uint32_t*>(Al + (r + 8) * 40 + ak);
                al[mi][2] = *reinterpret_cast<const uint32_t*>(Al + r * 40 + ak + 8);
                al[mi][3] = *reinterpret_cast<const uint32_t*>(Al + (r + 8) * 40 + ak + 8);
            }
#pragma unroll
            for (int ni = 0; ni < 4; ni++) {
                int n = ni * 8 + (lane >> 2);
                bh[ni][0] = *reinterpret_cast<const uint32_t*>(Bh + n * 40 + ak);
                bh[ni][1] = *reinterpret_cast<const uint32_t*>(Bh + n * 40 + ak + 8);
                bl[ni][0] = *reinterpret_cast<const uint32_t*>(Bl + n * 40 + ak);
                bl[ni][1] = *reinterpret_cast<const uint32_t*>(Bl + n * 40 + ak + 8);
            }
#pragma unroll
            for (int mi = 0; mi < 4; mi++)
#pragma unroll
                for (int ni = 0; ni < 4; ni++) {
                    MMA_BF16(acc[mi][ni], al[mi][0], al[mi][1], al[mi][2], al[mi][3],
                             bh[ni][0], bh[ni][1]);
                    MMA_BF16(acc[mi][ni], ah[mi][0], ah[mi][1], ah[mi][2], ah[mi][3],
                             bl[ni][0], bl[ni][1]);
                    MMA_BF16(acc[mi][ni], ah[mi][0], ah[mi][1], ah[mi][2], ah[mi][3],
                             bh[ni][0], bh[ni][1]);
                }
        }
        __syncthreads();
    }
#undef COPY_CHUNK

    float shv[8], wkv[8];
#pragma unroll
    for (int mi = 0; mi < 4; mi++)
#pragma unroll
        for (int rh = 0; rh < 2; rh++) {
            int m = mw * 64 + mi * 16 + (lane >> 2) + rh * 8;
            shv[mi * 2 + rh] = g_sh5[m];
            wkv[mi * 2 + rh] = w6[m];
        }

    float* red = reinterpret_cast<float*>(smb);     // [128][33]
    const int slice = mw * 8 + (lane >> 2);
#pragma unroll
    for (int ni = 0; ni < 4; ni++)
#pragma unroll
        for (int j = 0; j < 2; j++) {
            float s = 0.f;
#pragma unroll
            for (int mi = 0; mi < 4; mi++)
#pragma unroll
                for (int rh = 0; rh < 2; rh++) {
                    float z = fmaxf(acc[mi][ni][rh * 2 + j] + shv[mi * 2 + rh], 0.f);
                    s = fmaf(z, wkv[mi * 2 + rh], s);
                }
            int col = nw * 32 + ni * 8 + 2 * (lane & 3) + j;
            red[col * 33 + slice] = s;
        }
    __syncthreads();
    if (tid < 128) {
        float t = b6[0];
#pragma unroll
        for (int r = 0; r < 32; r++) t += red[tid * 33 + r];
        g_av[b * NHW + p0 + tid] = 1.f / (1.f + expf(-t));
    }
}

// ---------------- K5: out = x * a --------------------------------------------
__global__ void __launch_bounds__(256) k5_scale(const float* __restrict__ x,
                                                float* __restrict__ out)
{
    int idx = blockIdx.x * 256 + threadIdx.x;
    float4 xv = reinterpret_cast<const float4*>(x)[idx];
    int pix4 = idx & 255;
    int b = idx >> 16;
    float4 av = reinterpret_cast<const float4*>(g_av)[b * 256 + pix4];
    float4 o;
    o.x = xv.x * av.x; o.y = xv.y * av.y; o.z = xv.z * av.z; o.w = xv.w * av.w;
    reinterpret_cast<float4*>(out)[idx] = o;
}

// ---------------- launch ------------------------------------------------------
extern "C" void kernel_launch(void* const* d_in, const int* in_sizes, int n_in,
                              void* d_out, int out_size)
{
    const float* x   = (const float*)d_in[0];
    const float* w1  = (const float*)d_in[1];
    const float* b1  = (const float*)d_in[2];
    const float* g1  = (const float*)d_in[3];
    const float* bt1 = (const float*)d_in[4];
    const float* m1  = (const float*)d_in[5];
    const float* v1  = (const float*)d_in[6];
    const float* w2  = (const float*)d_in[7];
    const float* b2  = (const float*)d_in[8];
    const float* g2  = (const float*)d_in[9];
    const float* bt2 = (const float*)d_in[10];
    const float* m2  = (const float*)d_in[11];
    const float* v2  = (const float*)d_in[12];
    const float* w3  = (const float*)d_in[13];
    const float* b3  = (const float*)d_in[14];
    const float* g3  = (const float*)d_in[15];
    const float* bt3 = (const float*)d_in[16];
    const float* m3  = (const float*)d_in[17];
    const float* v3  = (const float*)d_in[18];
    const float* w4  = (const float*)d_in[19];
    const float* b4  = (const float*)d_in[20];
    const float* w5  = (const float*)d_in[21];
    const float* b5  = (const float*)d_in[22];
    const float* g5  = (const float*)d_in[23];
    const float* bt5 = (const float*)d_in[24];
    const float* m5  = (const float*)d_in[25];
    const float* v5  = (const float*)d_in[26];
    const float* w6  = (const float*)d_in[27];
    const float* b6  = (const float*)d_in[28];

    cudaFuncSetAttribute(k1_mma, cudaFuncAttributeMaxDynamicSharedMemorySize, 102400);
    cudaFuncSetAttribute(k3_mma, cudaFuncAttributeMaxDynamicSharedMemorySize, 110592);
    cudaFuncSetAttribute(k4_mma, cudaFuncAttributeMaxDynamicSharedMemorySize, 122880);

    k0_prep<<<NC5 + 1 + NB + 192, 256>>>(w5, g5, v5, b5, bt5, m5,
                                         w1, b1, g1, bt1, m1, v1,
                                         w2, b2, g2, bt2, m2, v2,
                                         w3, b3, g3, bt3, m3, v3);
    k_x<<<dim3(16, 4, NB), 256>>>(x);
    k1_mma<<<dim3(8, NB), 384, 102400>>>(nullptr);
    k2_small<<<dim3(4, NB, 2), 256>>>(w4);
    k3_mma<<<dim3(8, 2, NB), 512, 110592>>>(b4);
    k4_mma<<<256, 512, 122880>>>(w6, b6);
    k5_scale<<<(NB * NINP * NHW / 4) / 256, 256>>>(x, (float*)d_out);
}

// round 8
// speedup vs baseline: 1.9477x; 1.2500x over previous
#include <cuda_runtime.h>
#include <cuda_bf16.h>
#include <math.h>
#include <stdint.h>

#define NB 32
#define NINP 256
#define NHW 1024
#define NCS 64
#define NAOUT 256
#define NCF 513
#define NC5 256
#define EPSV 1e-5f
#define KP 544
#define NCHUNK 17

// ---------------- scratch ------------------------------------------------------
__device__ float g_theta[NB * NCS * NHW];   // [b][c][p] fp32
__device__ float g_phi[NB * NCS * NHW];     // [b][c][p] fp32
__device__ __align__(16) __nv_bfloat16 g_xth[NB * NHW * NINP];  // x^T split hi [b][p][c]
__device__ __align__(16) __nv_bfloat16 g_xtl[NB * NHW * NINP];
__device__ __align__(16) __nv_bfloat16 g_wch[192 * NINP];       // stacked folded conv w
__device__ __align__(16) __nv_bfloat16 g_wcl[192 * NINP];
__device__ __align__(16) __nv_bfloat16 g_w4h[NAOUT * NHW];      // w4 split [o][j]
__device__ __align__(16) __nv_bfloat16 g_w4l[NAOUT * NHW];
__device__ __align__(16) __nv_bfloat16 g_pTh[NB * NCS * NHW];   // P^T split [b][c][j]
__device__ __align__(16) __nv_bfloat16 g_pTl[NB * NCS * NHW];
__device__ __align__(16) __nv_bfloat16 g_thh[NB * NCS * NHW];   // theta split [b][c][p]
__device__ __align__(16) __nv_bfloat16 g_thl[NB * NCS * NHW];
__device__ __align__(16) __nv_bfloat16 g_WPh[NB * 512 * NCS];   // [b][row][c]; 0..255 WP, 256..511 TW^T
__device__ __align__(16) __nv_bfloat16 g_WPl[NB * 512 * NCS];
__device__ __align__(16) __nv_bfloat16 g_yh[NB * NHW * KP];     // [b][p][f'] hi
__device__ __align__(16) __nv_bfloat16 g_yl[NB * NHW * KP];
__device__ float g_av[NB * NHW];
__device__ __align__(16) __nv_bfloat16 g_w5h[NC5 * KP];
__device__ __align__(16) __nv_bfloat16 g_w5l[NC5 * KP];
__device__ float g_sc[3 * NCS];
__device__ float g_sh[3 * NCS];
__device__ float g_sh5[NC5];

__device__ __forceinline__ float f4get(const float4& v, int i) {
    return i == 0 ? v.x : (i == 1 ? v.y : (i == 2 ? v.z : v.w));
}

__device__ __forceinline__ uint32_t smem_u32(const void* p) {
    uint32_t a;
    asm("{ .reg .u64 t; cvta.to.shared.u64 t, %1; cvt.u32.u64 %0, t; }" : "=r"(a) : "l"(p));
    return a;
}

__device__ __forceinline__ void bf16_split(float v, __nv_bfloat16& h, __nv_bfloat16& l) {
    h = __float2bfloat16_rn(v);
    l = __float2bfloat16_rn(v - __bfloat162float(h));
}

__device__ __forceinline__ uint32_t pk2(__nv_bfloat16 a, __nv_bfloat16 b) {
    __nv_bfloat162 t; t.x = a; t.y = b;
    return *reinterpret_cast<uint32_t*>(&t);
}

#define MMA_BF16(ACC, A0, A1, A2, A3, B0, B1)                                        \
    asm volatile(                                                                    \
        "mma.sync.aligned.m16n8k16.row.col.f32.bf16.bf16.f32 "                       \
        "{%0,%1,%2,%3}, {%4,%5,%6,%7}, {%8,%9}, {%0,%1,%2,%3};"                      \
        : "+f"((ACC)[0]), "+f"((ACC)[1]), "+f"((ACC)[2]), "+f"((ACC)[3])             \
        : "r"(A0), "r"(A1), "r"(A2), "r"(A3), "r"(B0), "r"(B1))

// ---------------- K0: params, w5/convw/w4 split, y pad zero -------------------
__global__ void k0_prep(const float* __restrict__ w5,
                        const float* __restrict__ g5, const float* __restrict__ v5,
                        const float* __restrict__ b5, const float* __restrict__ bt5,
                        const float* __restrict__ m5, const float* __restrict__ w4,
                        const float* __restrict__ w1, const float* __restrict__ b1,
                        const float* __restrict__ g1, const float* __restrict__ bt1,
                        const float* __restrict__ m1, const float* __restrict__ v1,
                        const float* __restrict__ w2, const float* __restrict__ b2,
                        const float* __restrict__ g2, const float* __restrict__ bt2,
                        const float* __restrict__ m2, const float* __restrict__ v2,
                        const float* __restrict__ w3, const float* __restrict__ b3,
                        const float* __restrict__ g3, const float* __restrict__ bt3,
                        const float* __restrict__ m3, const float* __restrict__ v3)
{
    const int blk = blockIdx.x;
    const int tid = threadIdx.x;
    if (blk < NC5) {
        const int k = blk;
        float s5 = g5[k] * rsqrtf(v5[k] + EPSV);
        for (int f = tid; f < KP; f += 256) {
            float val;
            if (f < 512) val = w5[k * NCF + 1 + f] * s5;
            else if (f == 512) val = w5[k * NCF] * s5;
            else val = 0.f;
            __nv_bfloat16 h, l;
            bf16_split(val, h, l);
            g_w5h[k * KP + f] = h;
            g_w5l[k * KP + f] = l;
        }
    } else if (blk == NC5) {
        const int k = tid;
        float s5 = g5[k] * rsqrtf(v5[k] + EPSV);
        g_sh5[k] = (b5[k] - m5[k]) * s5 + bt5[k];
        if (k < 3 * NCS) {
            int cv = k / NCS, c = k % NCS;
            const float* bb = cv == 0 ? b1 : (cv == 1 ? b2 : b3);
            const float* gg = cv == 0 ? g1 : (cv == 1 ? g2 : g3);
            const float* bt = cv == 0 ? bt1 : (cv == 1 ? bt2 : bt3);
            const float* mm = cv == 0 ? m1 : (cv == 1 ? m2 : m3);
            const float* vv = cv == 0 ? v1 : (cv == 1 ? v2 : v3);
            float s = gg[c] * rsqrtf(vv[c] + EPSV);
            g_sc[k] = s;
            g_sh[k] = (bb[c] - mm[c]) * s + bt[c];
        }
    } else if (blk < NC5 + 1 + NB) {
        const int b = blk - NC5 - 1;
        char* baseh = (char*)(g_yh + (size_t)b * NHW * KP + 512);
        char* basel = (char*)(g_yl + (size_t)b * NHW * KP + 512);
        uint4 z = make_uint4(0u, 0u, 0u, 0u);
        for (int i = tid; i < NHW * 4; i += 256) {
            int p = i >> 2, q = i & 3;
            *reinterpret_cast<uint4*>(baseh + (size_t)p * (KP * 2) + q * 16) = z;
            *reinterpret_cast<uint4*>(basel + (size_t)p * (KP * 2) + q * 16) = z;
        }
    } else if (blk < NC5 + 1 + NB + 192) {
        const int row = blk - (NC5 + 1 + NB);
        const int cv = row >> 6, c = row & 63;
        const float* W  = cv == 0 ? w1 : (cv == 1 ? w2 : w3);
        const float* gg = cv == 0 ? g1 : (cv == 1 ? g2 : g3);
        const float* vv = cv == 0 ? v1 : (cv == 1 ? v2 : v3);
        float s = gg[c] * rsqrtf(vv[c] + EPSV);
        float val = W[c * NINP + tid] * s;
        __nv_bfloat16 h, l;
        bf16_split(val, h, l);
        g_wch[row * NINP + tid] = h;
        g_wcl[row * NINP + tid] = l;
    } else {
        // w4 split: row = blk - 481 (0..255), 1024 elems via 256 thr x float4
        const int row = blk - (NC5 + 1 + NB + 192);
        float4 v = *reinterpret_cast<const float4*>(w4 + (size_t)row * NHW + tid * 4);
        __nv_bfloat16 h0, l0, h1, l1, h2, l2, h3, l3;
        bf16_split(v.x, h0, l0); bf16_split(v.y, h1, l1);
        bf16_split(v.z, h2, l2); bf16_split(v.w, h3, l3);
        size_t base = (size_t)row * NHW + tid * 4;
        *reinterpret_cast<uint2*>(&g_w4h[base]) = make_uint2(pk2(h0, h1), pk2(h2, h3));
        *reinterpret_cast<uint2*>(&g_w4l[base]) = make_uint2(pk2(l0, l1), pk2(l2, l3));
    }
}

// ---------------- Kx: x [b][c][p] fp32 -> x^T [b][p][c] split bf16 ------------
__global__ void __launch_bounds__(256) k_x(const float* __restrict__ x)
{
    __shared__ float sm[64 * 68];
    const int p0 = blockIdx.x * 64;
    const int c0 = blockIdx.y * 64;
    const int b  = blockIdx.z;
    const int tid = threadIdx.x;

    const float* src = x + (size_t)b * NINP * NHW;
    for (int i = tid; i < 1024; i += 256) {
        int c = i >> 4, pq = i & 15;
        float4 v = *reinterpret_cast<const float4*>(src + (size_t)(c0 + c) * NHW + p0 + pq * 4);
        *reinterpret_cast<float4*>(sm + c * 68 + pq * 4) = v;
    }
    __syncthreads();

    const int p = tid >> 2;
    const int cs = (tid & 3) * 16;
    uint32_t hb[8], lb[8];
#pragma unroll
    for (int j2 = 0; j2 < 8; j2++) {
        __nv_bfloat16 h0, l0, h1, l1;
        bf16_split(sm[(cs + j2 * 2) * 68 + p], h0, l0);
        bf16_split(sm[(cs + j2 * 2 + 1) * 68 + p], h1, l1);
        hb[j2] = pk2(h0, h1);
        lb[j2] = pk2(l0, l1);
    }
    size_t base = ((size_t)(b * NHW + p0 + p)) * NINP + c0 + cs;
    *reinterpret_cast<uint4*>(&g_xth[base])     = make_uint4(hb[0], hb[1], hb[2], hb[3]);
    *reinterpret_cast<uint4*>(&g_xth[base + 8]) = make_uint4(hb[4], hb[5], hb[6], hb[7]);
    *reinterpret_cast<uint4*>(&g_xtl[base])     = make_uint4(lb[0], lb[1], lb[2], lb[3]);
    *reinterpret_cast<uint4*>(&g_xtl[base + 8]) = make_uint4(lb[4], lb[5], lb[6], lb[7]);
}

// ---------------- K1: conv GEMM C[192,128px] = Wc[192,256] @ xt^T -------------
__global__ void __launch_bounds__(384) k1_mma(const float* __restrict__ dummy)
{
    extern __shared__ __nv_bfloat16 smb[];
    const int AH = 0, AL = 15360, BH = 30720, BL = 40960;
    const uint32_t smb_u = smem_u32(smb);
    const int tid = threadIdx.x;
    const int lane = tid & 31;
    const int wid = tid >> 5;
    const int mw3 = wid % 3;
    const int nw4 = wid / 3;
    const int b = blockIdx.y;
    const int p0 = blockIdx.x * 128;

    float acc[4][4][4];
#pragma unroll
    for (int mi = 0; mi < 4; mi++)
#pragma unroll
        for (int ni = 0; ni < 4; ni++)
#pragma unroll
            for (int c = 0; c < 4; c++) acc[mi][ni][c] = 0.f;

#define K1_COPY(ch, buf) do {                                                         \
    for (int i = tid; i < 768; i += 384) {                                            \
        int row = i >> 2, q = i & 3;                                                  \
        uint32_t dh = smb_u + (uint32_t)(AH + (buf) * 7680 + row * 40 + q * 8) * 2u;  \
        uint32_t dl = smb_u + (uint32_t)(AL + (buf) * 7680 + row * 40 + q * 8) * 2u;  \
        size_t so = (size_t)row * NINP + (ch) * 32 + q * 8;                           \
        asm volatile("cp.async.ca.shared.global [%0], [%1], 16;" :: "r"(dh), "l"(g_wch + so)); \
        asm volatile("cp.async.ca.shared.global [%0], [%1], 16;" :: "r"(dl), "l"(g_wcl + so)); \
    }                                                                                 \
    for (int i = tid; i < 512; i += 384) {                                            \
        int row = i >> 2, q = i & 3;                                                  \
        uint32_t dh = smb_u + (uint32_t)(BH + (buf) * 5120 + row * 40 + q * 8) * 2u;  \
        uint32_t dl = smb_u + (uint32_t)(BL + (buf) * 5120 + row * 40 + q * 8) * 2u;  \
        size_t so = ((size_t)(b * NHW + p0 + row)) * NINP + (ch) * 32 + q * 8;        \
        asm volatile("cp.async.ca.shared.global [%0], [%1], 16;" :: "r"(dh), "l"(g_xth + so)); \
        asm volatile("cp.async.ca.shared.global [%0], [%1], 16;" :: "r"(dl), "l"(g_xtl + so)); \
    }                                                                                 \
    asm volatile("cp.async.commit_group;");                                           \
} while (0)

    K1_COPY(0, 0);
    for (int ch = 0; ch < 8; ch++) {
        if (ch < 7) {
            K1_COPY(ch + 1, (ch + 1) & 1);
            asm volatile("cp.async.wait_group 1;");
        } else {
            asm volatile("cp.async.wait_group 0;");
        }
        __syncthreads();
        const int buf = ch & 1;
        const __nv_bfloat16* Ah = smb + AH + buf * 7680 + (mw3 * 64) * 40;
        const __nv_bfloat16* Al = smb + AL + buf * 7680 + (mw3 * 64) * 40;
        const __nv_bfloat16* Bh = smb + BH + buf * 5120 + (nw4 * 32) * 40;
        const __nv_bfloat16* Bl = smb + BL + buf * 5120 + (nw4 * 32) * 40;
#pragma unroll
        for (int ks = 0; ks < 2; ks++) {
            const int ar = lane >> 2;
            const int ak = ks * 16 + (lane & 3) * 2;
            uint32_t ah[4][4], al[4][4], bh[4][2], bl[4][2];
#pragma unroll
            for (int mi = 0; mi < 4; mi++) {
                int r = mi * 16 + ar;
                ah[mi][0] = *reinterpret_cast<const uint32_t*>(Ah + r * 40 + ak);
                ah[mi][1] = *reinterpret_cast<const uint32_t*>(Ah + (r + 8) * 40 + ak);
                ah[mi][2] = *reinterpret_cast<const uint32_t*>(Ah + r * 40 + ak + 8);
                ah[mi][3] = *reinterpret_cast<const uint32_t*>(Ah + (r + 8) * 40 + ak + 8);
                al[mi][0] = *reinterpret_cast<const uint32_t*>(Al + r * 40 + ak);
                al[mi][1] = *reinterpret_cast<const uint32_t*>(Al + (r + 8) * 40 + ak);
                al[mi][2] = *reinterpret_cast<const uint32_t*>(Al + r * 40 + ak + 8);
                al[mi][3] = *reinterpret_cast<const uint32_t*>(Al + (r + 8) * 40 + ak + 8);
            }
#pragma unroll
            for (int ni = 0; ni < 4; ni++) {
                int n = ni * 8 + (lane >> 2);
                bh[ni][0] = *reinterpret_cast<const uint32_t*>(Bh + n * 40 + ak);
                bh[ni][1] = *reinterpret_cast<const uint32_t*>(Bh + n * 40 + ak + 8);
                bl[ni][0] = *reinterpret_cast<const uint32_t*>(Bl + n * 40 + ak);
                bl[ni][1] = *reinterpret_cast<const uint32_t*>(Bl + n * 40 + ak + 8);
            }
#pragma unroll
            for (int mi = 0; mi < 4; mi++)
#pragma unroll
                for (int ni = 0; ni < 4; ni++) {
                    MMA_BF16(acc[mi][ni], al[mi][0], al[mi][1], al[mi][2], al[mi][3],
                             bh[ni][0], bh[ni][1]);
                    MMA_BF16(acc[mi][ni], ah[mi][0], ah[mi][1], ah[mi][2], ah[mi][3],
                             bl[ni][0], bl[ni][1]);
                    MMA_BF16(acc[mi][ni], ah[mi][0], ah[mi][1], ah[mi][2], ah[mi][3],
                             bh[ni][0], bh[ni][1]);
                }
        }
        __syncthreads();
    }
#undef K1_COPY

    const int ar = lane >> 2;
    const int qq = lane & 3;
    if (mw3 < 2) {
        float* dst = (mw3 == 0 ? g_theta : g_phi) + (size_t)b * NCS * NHW;
#pragma unroll
        for (int mi = 0; mi < 4; mi++)
#pragma unroll
            for (int rh = 0; rh < 2; rh++) {
                int c = mi * 16 + ar + rh * 8;
                float sh = g_sh[mw3 * 64 + c];
#pragma unroll
                for (int ni = 0; ni < 4; ni++) {
                    int px = p0 + nw4 * 32 + ni * 8 + 2 * qq;
                    float2 o;
                    o.x = fmaxf(acc[mi][ni][rh * 2 + 0] + sh, 0.f);
                    o.y = fmaxf(acc[mi][ni][rh * 2 + 1] + sh, 0.f);
                    *reinterpret_cast<float2*>(dst + (size_t)c * NHW + px) = o;
                }
            }
    } else {
        float s_px[8];
#pragma unroll
        for (int ni = 0; ni < 4; ni++)
#pragma unroll
            for (int j = 0; j < 2; j++) {
                float s = 0.f;
#pragma unroll
                for (int mi = 0; mi < 4; mi++)
#pragma unroll
                    for (int rh = 0; rh < 2; rh++) {
                        int c = mi * 16 + ar + rh * 8;
                        s += fmaxf(acc[mi][ni][rh * 2 + j] + g_sh[128 + c], 0.f);
                    }
                s_px[ni * 2 + j] = s;
            }
#pragma unroll
        for (int v = 0; v < 8; v++) {
            s_px[v] += __shfl_xor_sync(0xffffffffu, s_px[v], 4);
            s_px[v] += __shfl_xor_sync(0xffffffffu, s_px[v], 8);
            s_px[v] += __shfl_xor_sync(0xffffffffu, s_px[v], 16);
        }
        if (lane < 4) {
#pragma unroll
            for (int ni = 0; ni < 4; ni++)
#pragma unroll
                for (int j = 0; j < 2; j++) {
                    int px = p0 + nw4 * 32 + ni * 8 + 2 * lane + j;
                    float val = s_px[ni * 2 + j] * (1.f / NCS);
                    __nv_bfloat16 h, l;
                    bf16_split(val, h, l);
                    size_t base = (size_t)(b * NHW + px) * KP + 512;
                    g_yh[base] = h;
                    g_yl[base] = l;
                }
        }
    }
}

// ---------------- K2t: transpose+split phi -> P^T ; split theta ---------------
// grid (16 jt, 2 task, 32 b), 256 thr
__global__ void __launch_bounds__(256) k2t()
{
    __shared__ float sm[64 * 68];
    const int jt = blockIdx.x;
    const int task = blockIdx.y;
    const int b = blockIdx.z;
    const int tid = threadIdx.x;

    if (task == 0) {
        // g_pT[c][jt*64 + j] = phibuf[(jt*64+j)*64 + c]
        const float* src = g_phi + (size_t)b * NCS * NHW + jt * 4096;
        for (int i = tid; i < 1024; i += 256) {
            int r = i >> 4, cq = i & 15;
            float4 v = *reinterpret_cast<const float4*>(src + r * 64 + cq * 4);
            *reinterpret_cast<float4*>(sm + r * 68 + cq * 4) = v;
        }
        __syncthreads();
        const int jg = tid >> 6;        // 0..3 -> 16 j's each
        const int c = tid & 63;
        uint32_t hb[8], lb[8];
#pragma unroll
        for (int k2i = 0; k2i < 8; k2i++) {
            __nv_bfloat16 h0, l0, h1, l1;
            bf16_split(sm[(jg * 16 + k2i * 2) * 68 + c], h0, l0);
            bf16_split(sm[(jg * 16 + k2i * 2 + 1) * 68 + c], h1, l1);
            hb[k2i] = pk2(h0, h1);
            lb[k2i] = pk2(l0, l1);
        }
        size_t base = (size_t)b * NCS * NHW + (size_t)c * NHW + jt * 64 + jg * 16;
        *reinterpret_cast<uint4*>(&g_pTh[base])     = make_uint4(hb[0], hb[1], hb[2], hb[3]);
        *reinterpret_cast<uint4*>(&g_pTh[base + 8]) = make_uint4(hb[4], hb[5], hb[6], hb[7]);
        *reinterpret_cast<uint4*>(&g_pTl[base])     = make_uint4(lb[0], lb[1], lb[2], lb[3]);
        *reinterpret_cast<uint4*>(&g_pTl[base + 8]) = make_uint4(lb[4], lb[5], lb[6], lb[7]);
    } else {
        // straight split theta (layout preserved)
        const float* src = g_theta + (size_t)b * NCS * NHW + jt * 4096;
        size_t dbase = (size_t)b * NCS * NHW + jt * 4096;
        for (int i = tid; i < 1024; i += 256) {
            float4 v = *reinterpret_cast<const float4*>(src + i * 4);
            __nv_bfloat16 h0, l0, h1, l1, h2, l2, h3, l3;
            bf16_split(v.x, h0, l0); bf16_split(v.y, h1, l1);
            bf16_split(v.z, h2, l2); bf16_split(v.w, h3, l3);
            *reinterpret_cast<uint2*>(&g_thh[dbase + i * 4]) = make_uint2(pk2(h0, h1), pk2(h2, h3));
            *reinterpret_cast<uint2*>(&g_thl[dbase + i * 4]) = make_uint2(pk2(l0, l1), pk2(l2, l3));
        }
    }
}

// ---------------- K2: mma GEMM -> WP / TW^T -----------------------------------
// which0: WP[o][c] = sum_j w4[o][j] * pT[c][j]
// which1: TWt[o][c] = sum_p w4[o][p] * theta[c][p]
// grid (4 otiles, 2 which, 32 b), 128 thr = 4 warps (2M x 2N); M=64(o), N=64(c), K=1024
// smem bf16: Ah[2][4608] Al Bh Bl = 36864 el = 73728 B (row stride 72)
__global__ void __launch_bounds__(128) k2_mma()
{
    extern __shared__ __nv_bfloat16 smb[];
    const int AH = 0, AL = 9216, BH = 18432, BL = 27648;
    const uint32_t smb_u = smem_u32(smb);
    const int tid = threadIdx.x;
    const int lane = tid & 31;
    const int wid = tid >> 5;
    const int mw = wid & 1;             // M: mw*32
    const int nw = wid >> 1;            // N: nw*32
    const int o0 = blockIdx.x * 64;
    const int which = blockIdx.y;
    const int b = blockIdx.z;

    const __nv_bfloat16* Asrch = g_w4h + (size_t)o0 * NHW;
    const __nv_bfloat16* Asrcl = g_w4l + (size_t)o0 * NHW;
    const __nv_bfloat16* Bsrch = (which ? g_thh : g_pTh) + (size_t)b * NCS * NHW;
    const __nv_bfloat16* Bsrcl = (which ? g_thl : g_pTl) + (size_t)b * NCS * NHW;

    float acc[2][4][4];
#pragma unroll
    for (int mi = 0; mi < 2; mi++)
#pragma unroll
        for (int ni = 0; ni < 4; ni++)
#pragma unroll
            for (int c = 0; c < 4; c++) acc[mi][ni][c] = 0.f;

#define K2_COPY(ch, buf) do {                                                         \
    for (int i = tid; i < 512; i += 128) {                                            \
        int row = i >> 3, q = i & 7;                                                  \
        uint32_t dh = smb_u + (uint32_t)(AH + (buf) * 4608 + row * 72 + q * 8) * 2u;  \
        uint32_t dl = smb_u + (uint32_t)(AL + (buf) * 4608 + row * 72 + q * 8) * 2u;  \
        size_t so = (size_t)row * NHW + (ch) * 64 + q * 8;                            \
        asm volatile("cp.async.ca.shared.global [%0], [%1], 16;" :: "r"(dh), "l"(Asrch + so)); \
        asm volatile("cp.async.ca.shared.global [%0], [%1], 16;" :: "r"(dl), "l"(Asrcl + so)); \
    }                                                                                 \
    for (int i = tid; i < 512; i += 128) {                                            \
        int row = i >> 3, q = i & 7;                                                  \
        uint32_t dh = smb_u + (uint32_t)(BH + (buf) * 4608 + row * 72 + q * 8) * 2u;  \
        uint32_t dl = smb_u + (uint32_t)(BL + (buf) * 4608 + row * 72 + q * 8) * 2u;  \
        size_t so = (size_t)row * NHW + (ch) * 64 + q * 8;                            \
        asm volatile("cp.async.ca.shared.global [%0], [%1], 16;" :: "r"(dh), "l"(Bsrch + so)); \
        asm volatile("cp.async.ca.shared.global [%0], [%1], 16;" :: "r"(dl), "l"(Bsrcl + so)); \
    }                                                                                 \
    asm volatile("cp.async.commit_group;");                                           \
} while (0)

    K2_COPY(0, 0);
    for (int ch = 0; ch < 16; ch++) {
        if (ch < 15) {
            K2_COPY(ch + 1, (ch + 1) & 1);
            asm volatile("cp.async.wait_group 1;");
        } else {
            asm volatile("cp.async.wait_group 0;");
        }
        __syncthreads();
        const int buf = ch & 1;
        const __nv_bfloat16* Ah = smb + AH + buf * 4608 + (mw * 32) * 72;
        const __nv_bfloat16* Al = smb + AL + buf * 4608 + (mw * 32) * 72;
        const __nv_bfloat16* Bh = smb + BH + buf * 4608 + (nw * 32) * 72;
        const __nv_bfloat16* Bl = smb + BL + buf * 4608 + (nw * 32) * 72;
#pragma unroll
        for (int ks = 0; ks < 4; ks++) {
            const int ar = lane >> 2;
            const int ak = ks * 16 + (lane & 3) * 2;
            uint32_t ah[2][4], al[2][4], bh[4][2], bl[4][2];
#pragma unroll
            for (int mi = 0; mi < 2; mi++) {
                int r = mi * 16 + ar;
                ah[mi][0] = *reinterpret_cast<const uint32_t*>(Ah + r * 72 + ak);
                ah[mi][1] = *reinterpret_cast<const uint32_t*>(Ah + (r + 8) * 72 + ak);
                ah[mi][2] = *reinterpret_cast<const uint32_t*>(Ah + r * 72 + ak + 8);
                ah[mi][3] = *reinterpret_cast<const uint32_t*>(Ah + (r + 8) * 72 + ak + 8);
                al[mi][0] = *reinterpret_cast<const uint32_t*>(Al + r * 72 + ak);
                al[mi][1] = *reinterpret_cast<const uint32_t*>(Al + (r + 8) * 72 + ak);
                al[mi][2] = *reinterpret_cast<const uint32_t*>(Al + r * 72 + ak + 8);
                al[mi][3] = *reinterpret_cast<const uint32_t*>(Al + (r + 8) * 72 + ak + 8);
            }
#pragma unroll
            for (int ni = 0; ni < 4; ni++) {
                int n = ni * 8 + (lane >> 2);
                bh[ni][0] = *reinterpret_cast<const uint32_t*>(Bh + n * 72 + ak);
                bh[ni][1] = *reinterpret_cast<const uint32_t*>(Bh + n * 72 + ak + 8);
                bl[ni][0] = *reinterpret_cast<const uint32_t*>(Bl + n * 72 + ak);
                bl[ni][1] = *reinterpret_cast<const uint32_t*>(Bl + n * 72 + ak + 8);
            }
#pragma unroll
            for (int mi = 0; mi < 2; mi++)
#pragma unroll
                for (int ni = 0; ni < 4; ni++) {
                    MMA_BF16(acc[mi][ni], al[mi][0], al[mi][1], al[mi][2], al[mi][3],
                             bh[ni][0], bh[ni][1]);
                    MMA_BF16(acc[mi][ni], ah[mi][0], ah[mi][1], ah[mi][2], ah[mi][3],
                             bl[ni][0], bl[ni][1]);
                    MMA_BF16(acc[mi][ni], ah[mi][0], ah[mi][1], ah[mi][2], ah[mi][3],
                             bh[ni][0], bh[ni][1]);
                }
        }
        __syncthreads();
    }
#undef K2_COPY

    // epilogue: raw GEMM result -> split bf16 at g_WP[which*256 + o][c]
    const int ar = lane >> 2;
    const int qq = lane & 3;
    __nv_bfloat16* WH = g_WPh + (size_t)b * 512 * NCS;
    __nv_bfloat16* WL = g_WPl + (size_t)b * 512 * NCS;
#pragma unroll
    for (int mi = 0; mi < 2; mi++)
#pragma unroll
        for (int rh = 0; rh < 2; rh++) {
            int row = which * 256 + o0 + mw * 32 + mi * 16 + ar + rh * 8;
#pragma unroll
            for (int ni = 0; ni < 4; ni++) {
                int col = nw * 32 + ni * 8 + 2 * qq;
                __nv_bfloat16 h0, l0, h1, l1;
                bf16_split(acc[mi][ni][rh * 2 + 0], h0, l0);
                bf16_split(acc[mi][ni][rh * 2 + 1], h1, l1);
                *reinterpret_cast<uint32_t*>(WH + (size_t)row * NCS + col) = pk2(h0, h1);
                *reinterpret_cast<uint32_t*>(WL + (size_t)row * NCS + col) = pk2(l0, l1);
            }
        }
}

// ---------------- K3: C[128px, 256f] = A[px, 64c] @ B[f, 64c]^T ---------------
__global__ void __launch_bounds__(512) k3_mma(const float* __restrict__ b4)
{
    extern __shared__ __nv_bfloat16 smb[];
    const int AH = 0, AL = 9216, BH = 18432, BL = 36864;
    const uint32_t smb_u = smem_u32(smb);
    const int tid = threadIdx.x;
    const int lane = tid & 31;
    const int wid = tid >> 5;
    const int mw = wid & 3;
    const int nw = wid >> 2;
    const int p0 = blockIdx.x * 128;
    const int which = blockIdx.y;
    const int b = blockIdx.z;

    {
        const __nv_bfloat16* srch = g_WPh + ((size_t)b * 512 + which * 256) * NCS;
        const __nv_bfloat16* srcl = g_WPl + ((size_t)b * 512 + which * 256) * NCS;
        for (int i = tid; i < 2048; i += 512) {
            int row = i >> 3, q = i & 7;
            uint32_t dh = smb_u + (uint32_t)(BH + row * 72 + q * 8) * 2u;
            uint32_t dl = smb_u + (uint32_t)(BL + row * 72 + q * 8) * 2u;
            size_t so = (size_t)row * NCS + q * 8;
            asm volatile("cp.async.ca.shared.global [%0], [%1], 16;" :: "r"(dh), "l"(srch + so));
            asm volatile("cp.async.ca.shared.global [%0], [%1], 16;" :: "r"(dl), "l"(srcl + so));
        }
        asm volatile("cp.async.commit_group;");
    }
    if (which == 0) {
        const float* th = g_theta + (size_t)b * NCS * NHW;
        for (int i = tid; i < 2048; i += 512) {
            int c = i >> 5, pq = i & 31;
            float4 v = *reinterpret_cast<const float4*>(th + (size_t)c * NHW + p0 + pq * 4);
#pragma unroll
            for (int j = 0; j < 4; j++) {
                __nv_bfloat16 h, l;
                bf16_split(f4get(v, j), h, l);
                smb[AH + (pq * 4 + j) * 72 + c] = h;
                smb[AL + (pq * 4 + j) * 72 + c] = l;
            }
        }
    } else {
        const float* ph = g_phi + (size_t)b * NCS * NHW;
        for (int i = tid; i < 2048; i += 512) {
            int p = i >> 4, cq = i & 15;
            float4 v = *reinterpret_cast<const float4*>(ph + (size_t)(p0 + p) * NCS + cq * 4);
            __nv_bfloat16 h0, l0, h1, l1, h2, l2, h3, l3;
            bf16_split(v.x, h0, l0); bf16_split(v.y, h1, l1);
            bf16_split(v.z, h2, l2); bf16_split(v.w, h3, l3);
            *reinterpret_cast<uint2*>(&smb[AH + p * 72 + cq * 4]) =
                make_uint2(pk2(h0, h1), pk2(h2, h3));
            *reinterpret_cast<uint2*>(&smb[AL + p * 72 + cq * 4]) =
                make_uint2(pk2(l0, l1), pk2(l2, l3));
        }
    }
    asm volatile("cp.async.wait_group 0;");
    __syncthreads();

    float acc[2][8][4];
#pragma unroll
    for (int mi = 0; mi < 2; mi++)
#pragma unroll
        for (int ni = 0; ni < 8; ni++)
#pragma unroll
            for (int c = 0; c < 4; c++) acc[mi][ni][c] = 0.f;

    const __nv_bfloat16* Ah = smb + AH + (mw * 32) * 72;
    const __nv_bfloat16* Al = smb + AL + (mw * 32) * 72;
    const __nv_bfloat16* Bh = smb + BH + (nw * 64) * 72;
    const __nv_bfloat16* Bl = smb + BL + (nw * 64) * 72;
#pragma unroll
    for (int ks = 0; ks < 4; ks++) {
        const int ar = lane >> 2;
        const int ak = ks * 16 + (lane & 3) * 2;
        uint32_t ah[2][4], al[2][4];
#pragma unroll
        for (int mi = 0; mi < 2; mi++) {
            int r = mi * 16 + ar;
            ah[mi][0] = *reinterpret_cast<const uint32_t*>(Ah + r * 72 + ak);
            ah[mi][1] = *reinterpret_cast<const uint32_t*>(Ah + (r + 8) * 72 + ak);
            ah[mi][2] = *reinterpret_cast<const uint32_t*>(Ah + r * 72 + ak + 8);
            ah[mi][3] = *reinterpret_cast<const uint32_t*>(Ah + (r + 8) * 72 + ak + 8);
            al[mi][0] = *reinterpret_cast<const uint32_t*>(Al + r * 72 + ak);
            al[mi][1] = *reinterpret_cast<const uint32_t*>(Al + (r + 8) * 72 + ak);
            al[mi][2] = *reinterpret_cast<const uint32_t*>(Al + r * 72 + ak + 8);
            al[mi][3] = *reinterpret_cast<const uint32_t*>(Al + (r + 8) * 72 + ak + 8);
        }
#pragma unroll
        for (int ni = 0; ni < 8; ni++) {
            int n = ni * 8 + (lane >> 2);
            uint32_t bh0 = *reinterpret_cast<const uint32_t*>(Bh + n * 72 + ak);
            uint32_t bh1 = *reinterpret_cast<const uint32_t*>(Bh + n * 72 + ak + 8);
            uint32_t bl0 = *reinterpret_cast<const uint32_t*>(Bl + n * 72 + ak);
            uint32_t bl1 = *reinterpret_cast<const uint32_t*>(Bl + n * 72 + ak + 8);
#pragma unroll
            for (int mi = 0; mi < 2; mi++) {
                MMA_BF16(acc[mi][ni], al[mi][0], al[mi][1], al[mi][2], al[mi][3], bh0, bh1);
                MMA_BF16(acc[mi][ni], ah[mi][0], ah[mi][1], ah[mi][2], ah[mi][3], bl0, bl1);
                MMA_BF16(acc[mi][ni], ah[mi][0], ah[mi][1], ah[mi][2], ah[mi][3], bh0, bh1);
            }
        }
    }

    const int ar = lane >> 2;
    const int qq = lane & 3;
#pragma unroll
    for (int ni = 0; ni < 8; ni++) {
        int o = nw * 64 + ni * 8 + 2 * qq;
        float2 bb = *reinterpret_cast<const float2*>(b4 + o);
        int f0 = which * 256 + o;
#pragma unroll
        for (int mi = 0; mi < 2; mi++)
#pragma unroll
            for (int rh = 0; rh < 2; rh++) {
                int px = p0 + mw * 32 + mi * 16 + ar + rh * 8;
                float v0 = fmaxf(acc[mi][ni][rh * 2 + 0] + bb.x, 0.f);
                float v1 = fmaxf(acc[mi][ni][rh * 2 + 1] + bb.y, 0.f);
                __nv_bfloat16 h0, l0, h1, l1;
                bf16_split(v0, h0, l0);
                bf16_split(v1, h1, l1);
                size_t base = (size_t)(b * NHW + px) * KP + f0;
                *reinterpret_cast<uint32_t*>(&g_yh[base]) = pk2(h0, h1);
                *reinterpret_cast<uint32_t*>(&g_yl[base]) = pk2(l0, l1);
            }
    }
}

// ---------------- K4: split-bf16 m16n8k16 GEMM + fused epilogue ---------------
__global__ void __launch_bounds__(512) k4_mma(const float* __restrict__ w6,
                                              const float* __restrict__ b6)
{
    extern __shared__ __nv_bfloat16 smb[];
    const int AH = 0, AL = 20480, BH = 40960, BL = 51200;
    const uint32_t smb_u = smem_u32(smb);
    const int tid = threadIdx.x;
    const int lane = tid & 31;
    const int wid = tid >> 5;
    const int mw = wid & 3;
    const int nw = wid >> 2;
    const int b = blockIdx.x >> 3;
    const int p0 = (blockIdx.x & 7) * 128;
    const size_t pixbase = (size_t)(b * NHW + p0);

    float acc[4][4][4];
#pragma unroll
    for (int mi = 0; mi < 4; mi++)
#pragma unroll
        for (int ni = 0; ni < 4; ni++)
#pragma unroll
            for (int c = 0; c < 4; c++) acc[mi][ni][c] = 0.f;

#define COPY_CHUNK(ch, buf) do {                                                     \
    for (int i = tid; i < 1024; i += 512) {                                          \
        int row = i >> 2, q = i & 3;                                                 \
        uint32_t dh = smb_u + (uint32_t)(AH + (buf) * 10240 + row * 40 + q * 8) * 2u;\
        uint32_t dl = smb_u + (uint32_t)(AL + (buf) * 10240 + row * 40 + q * 8) * 2u;\
        size_t so = (size_t)row * KP + (ch) * 32 + q * 8;                            \
        asm volatile("cp.async.ca.shared.global [%0], [%1], 16;" :: "r"(dh), "l"(g_w5h + so)); \
        asm volatile("cp.async.ca.shared.global [%0], [%1], 16;" :: "r"(dl), "l"(g_w5l + so)); \
    }                                                                                \
    for (int i = tid; i < 512; i += 512) {                                           \
        int row = i >> 2, q = i & 3;                                                 \
        uint32_t dh = smb_u + (uint32_t)(BH + (buf) * 5120 + row * 40 + q * 8) * 2u; \
        uint32_t dl = smb_u + (uint32_t)(BL + (buf) * 5120 + row * 40 + q * 8) * 2u; \
        size_t so = (pixbase + row) * KP + (ch) * 32 + q * 8;                        \
        asm volatile("cp.async.ca.shared.global [%0], [%1], 16;" :: "r"(dh), "l"(g_yh + so)); \
        asm volatile("cp.async.ca.shared.global [%0], [%1], 16;" :: "r"(dl), "l"(g_yl + so)); \
    }                                                                                \
    asm volatile("cp.async.commit_group;");                                          \
} while (0)

    COPY_CHUNK(0, 0);
    for (int ch = 0; ch < NCHUNK; ch++) {
        if (ch < NCHUNK - 1) {
            COPY_CHUNK(ch + 1, (ch + 1) & 1);
            asm volatile("cp.async.wait_group 1;");
        } else {
            asm volatile("cp.async.wait_group 0;");
        }
        __syncthreads();
        const int buf = ch & 1;
        const __nv_bfloat16* Ah = smb + AH + buf * 10240 + (mw * 64) * 40;
        const __nv_bfloat16* Al = smb + AL + buf * 10240 + (mw * 64) * 40;
        const __nv_bfloat16* Bh = smb + BH + buf * 5120 + (nw * 32) * 40;
        const __nv_bfloat16* Bl = smb + BL + buf * 5120 + (nw * 32) * 40;
#pragma unroll
        for (int ks = 0; ks < 2; ks++) {
            const int ar = lane >> 2;
            const int ak = ks * 16 + (lane & 3) * 2;
            uint32_t ah[4][4], al[4][4], bh[4][2], bl[4][2];
#pragma unroll
            for (int mi = 0; mi < 4; mi++) {
                int r = mi * 16 + ar;
                ah[mi][0] = *reinterpret_cast<const uint32_t*>(Ah + r * 40 + ak);
                ah[mi][1] = *reinterpret_cast<const uint32_t*>(Ah + (r + 8) * 40 + ak);
                ah[mi][2] = *reinterpret_cast<const uint32_t*>(Ah + r * 40 + ak + 8);
                ah[mi][3] = *reinterpret_cast<const uint32_t*>(Ah + (r + 8) * 40 + ak + 8);
                al[mi][0] = *reinterpret_cast<const uint32_t*>(Al + r * 40 + ak);
                al[mi][1] = *reinterpret_cast<const uint32_t*>(Al + (r + 8) * 40 + ak);
                al[mi][2] = *reinterpret_cast<const uint32_t*>(Al + r * 40 + ak + 8);
                al[mi][3] = *reinterpret_cast<const uint32_t*>(Al + (r + 8) * 40 + ak + 8);
            }
#pragma unroll
            for (int ni = 0; ni < 4; ni++) {
                int n = ni * 8 + (lane >> 2);
                bh[ni][0] = *reinterpret_cast<const uint32_t*>(Bh + n * 40 + ak);
                bh[ni][1] = *reinterpret_cast<const uint32_t*>(Bh + n * 40 + ak + 8);
                bl[ni][0] = *reinterpret_cast<const uint32_t*>(Bl + n * 40 + ak);
                bl[ni][1] = *reinterpret_cast<const uint32_t*>(Bl + n * 40 + ak + 8);
            }
#pragma unroll
            for (int mi = 0; mi < 4; mi++)
#pragma unroll
                for (int ni = 0; ni < 4; ni++) {
                    MMA_BF16(acc[mi][ni], al[mi][0], al[mi][1], al[mi][2], al[mi][3],
                             bh[ni][0], bh[ni][1]);
                    MMA_BF16(acc[mi][ni], ah[mi][0], ah[mi][1], ah[mi][2], ah[mi][3],
                             bl[ni][0], bl[ni][1]);
                    MMA_BF16(acc[mi][ni], ah[mi][0], ah[mi][1], ah[mi][2], ah[mi][3],
                             bh[ni][0], bh[ni][1]);
                }
        }
        __syncthreads();
    }
#undef COPY_CHUNK

    float shv[8], wkv[8];
#pragma unroll
    for (int mi = 0; mi < 4; mi++)
#pragma unroll
        for (int rh = 0; rh < 2; rh++) {
            int m = mw * 64 + mi * 16 + (lane >> 2) + rh * 8;
            shv[mi * 2 + rh] = g_sh5[m];
            wkv[mi * 2 + rh] = w6[m];
        }

    float* red = reinterpret_cast<float*>(smb);     // [128][33]
    const int slice = mw * 8 + (lane >> 2);
#pragma unroll
    for (int ni = 0; ni < 4; ni++)
#pragma unroll
        for (int j = 0; j < 2; j++) {
            float s = 0.f;
#pragma unroll
            for (int mi = 0; mi < 4; mi++)
#pragma unroll
                for (int rh = 0; rh < 2; rh++) {
                    float z = fmaxf(acc[mi][ni][rh * 2 + j] + shv[mi * 2 + rh], 0.f);
                    s = fmaf(z, wkv[mi * 2 + rh], s);
                }
            int col = nw * 32 + ni * 8 + 2 * (lane & 3) + j;
            red[col * 33 + slice] = s;
        }
    __syncthreads();
    if (tid < 128) {
        float t = b6[0];
#pragma unroll
        for (int r = 0; r < 32; r++) t += red[tid * 33 + r];
        g_av[b * NHW + p0 + tid] = 1.f / (1.f + expf(-t));
    }
}

// ---------------- K5: out = x * a --------------------------------------------
__global__ void __launch_bounds__(256) k5_scale(const float* __restrict__ x,
                                                float* __restrict__ out)
{
    int idx = blockIdx.x * 256 + threadIdx.x;
    float4 xv = reinterpret_cast<const float4*>(x)[idx];
    int pix4 = idx & 255;
    int b = idx >> 16;
    float4 av = reinterpret_cast<const float4*>(g_av)[b * 256 + pix4];
    float4 o;
    o.x = xv.x * av.x; o.y = xv.y * av.y; o.z = xv.z * av.z; o.w = xv.w * av.w;
    reinterpret_cast<float4*>(out)[idx] = o;
}

// ---------------- launch ------------------------------------------------------
extern "C" void kernel_launch(void* const* d_in, const int* in_sizes, int n_in,
                              void* d_out, int out_size)
{
    const float* x   = (const float*)d_in[0];
    const float* w1  = (const float*)d_in[1];
    const float* b1  = (const float*)d_in[2];
    const float* g1  = (const float*)d_in[3];
    const float* bt1 = (const float*)d_in[4];
    const float* m1  = (const float*)d_in[5];
    const float* v1  = (const float*)d_in[6];
    const float* w2  = (const float*)d_in[7];
    const float* b2  = (const float*)d_in[8];
    const float* g2  = (const float*)d_in[9];
    const float* bt2 = (const float*)d_in[10];
    const float* m2  = (const float*)d_in[11];
    const float* v2  = (const float*)d_in[12];
    const float* w3  = (const float*)d_in[13];
    const float* b3  = (const float*)d_in[14];
    const float* g3  = (const float*)d_in[15];
    const float* bt3 = (const float*)d_in[16];
    const float* m3  = (const float*)d_in[17];
    const float* v3  = (const float*)d_in[18];
    const float* w4  = (const float*)d_in[19];
    const float* b4  = (const float*)d_in[20];
    const float* w5  = (const float*)d_in[21];
    const float* b5  = (const float*)d_in[22];
    const float* g5  = (const float*)d_in[23];
    const float* bt5 = (const float*)d_in[24];
    const float* m5  = (const float*)d_in[25];
    const float* v5  = (const float*)d_in[26];
    const float* w6  = (const float*)d_in[27];
    const float* b6  = (const float*)d_in[28];

    cudaFuncSetAttribute(k1_mma, cudaFuncAttributeMaxDynamicSharedMemorySize, 102400);
    cudaFuncSetAttribute(k2_mma, cudaFuncAttributeMaxDynamicSharedMemorySize, 73728);
    cudaFuncSetAttribute(k3_mma, cudaFuncAttributeMaxDynamicSharedMemorySize, 110592);
    cudaFuncSetAttribute(k4_mma, cudaFuncAttributeMaxDynamicSharedMemorySize, 122880);

    k0_prep<<<NC5 + 1 + NB + 192 + 256, 256>>>(w5, g5, v5, b5, bt5, m5, w4,
                                               w1, b1, g1, bt1, m1, v1,
                                               w2, b2, g2, bt2, m2, v2,
                                               w3, b3, g3, bt3, m3, v3);
    k_x<<<dim3(16, 4, NB), 256>>>(x);
    k1_mma<<<dim3(8, NB), 384, 102400>>>(nullptr);
    k2t<<<dim3(16, 2, NB), 256>>>();
    k2_mma<<<dim3(4, 2, NB), 128, 73728>>>();
    k3_mma<<<dim3(8, 2, NB), 512, 110592>>>(b4);
    k4_mma<<<256, 512, 122880>>>(w6, b6);
    k5_scale<<<(NB * NINP * NHW / 4) / 256, 256>>>(x, (float*)d_out);
}

// round 9
// speedup vs baseline: 2.0231x; 1.0388x over previous
#include <cuda_runtime.h>
#include <cuda_bf16.h>
#include <math.h>
#include <stdint.h>

#define NB 32
#define NINP 256
#define NHW 1024
#define NCS 64
#define NAOUT 256
#define NCF 513
#define NC5 256
#define EPSV 1e-5f
#define KP 544
#define NCHUNK 17

// ---------------- scratch ------------------------------------------------------
__device__ float g_theta[NB * NCS * NHW];   // [b][c][p] fp32
__device__ float g_phi[NB * NCS * NHW];     // [b][c][p] fp32
__device__ __align__(16) __nv_bfloat16 g_xth[NB * NHW * NINP];  // x^T split hi [b][p][c]
__device__ __align__(16) __nv_bfloat16 g_xtl[NB * NHW * NINP];
__device__ __align__(16) __nv_bfloat16 g_wch[192 * NINP];       // stacked folded conv w
__device__ __align__(16) __nv_bfloat16 g_wcl[192 * NINP];
__device__ __align__(16) __nv_bfloat16 g_w4h[NAOUT * NHW];      // w4 split [o][j]
__device__ __align__(16) __nv_bfloat16 g_w4l[NAOUT * NHW];
__device__ __align__(16) __nv_bfloat16 g_pTh[NB * NCS * NHW];   // P^T split [b][c][j]
__device__ __align__(16) __nv_bfloat16 g_pTl[NB * NCS * NHW];
__device__ __align__(16) __nv_bfloat16 g_thh[NB * NCS * NHW];   // theta split [b][c][p]
__device__ __align__(16) __nv_bfloat16 g_thl[NB * NCS * NHW];
__device__ __align__(16) __nv_bfloat16 g_WPh[NB * 512 * NCS];   // [b][row][c]; 0..255 WP, 256..511 TW^T
__device__ __align__(16) __nv_bfloat16 g_WPl[NB * 512 * NCS];
__device__ __align__(16) __nv_bfloat16 g_yh[NB * NHW * KP];     // [b][p][f'] hi
__device__ __align__(16) __nv_bfloat16 g_yl[NB * NHW * KP];
__device__ float g_part[2][NB * NHW];       // partial logits per M-half
__device__ __align__(16) __nv_bfloat16 g_w5h[NC5 * KP];
__device__ __align__(16) __nv_bfloat16 g_w5l[NC5 * KP];
__device__ float g_sc[3 * NCS];
__device__ float g_sh[3 * NCS];
__device__ float g_sh5[NC5];

__device__ __forceinline__ float f4get(const float4& v, int i) {
    return i == 0 ? v.x : (i == 1 ? v.y : (i == 2 ? v.z : v.w));
}

__device__ __forceinline__ uint32_t smem_u32(const void* p) {
    uint32_t a;
    asm("{ .reg .u64 t; cvta.to.shared.u64 t, %1; cvt.u32.u64 %0, t; }" : "=r"(a) : "l"(p));
    return a;
}

__device__ __forceinline__ void bf16_split(float v, __nv_bfloat16& h, __nv_bfloat16& l) {
    h = __float2bfloat16_rn(v);
    l = __float2bfloat16_rn(v - __bfloat162float(h));
}

__device__ __forceinline__ uint32_t pk2(__nv_bfloat16 a, __nv_bfloat16 b) {
    __nv_bfloat162 t; t.x = a; t.y = b;
    return *reinterpret_cast<uint32_t*>(&t);
}

#define MMA_BF16(ACC, A0, A1, A2, A3, B0, B1)                                        \
    asm volatile(                                                                    \
        "mma.sync.aligned.m16n8k16.row.col.f32.bf16.bf16.f32 "                       \
        "{%0,%1,%2,%3}, {%4,%5,%6,%7}, {%8,%9}, {%0,%1,%2,%3};"                      \
        : "+f"((ACC)[0]), "+f"((ACC)[1]), "+f"((ACC)[2]), "+f"((ACC)[3])             \
        : "r"(A0), "r"(A1), "r"(A2), "r"(A3), "r"(B0), "r"(B1))

// ---------------- K0: params, w5/convw/w4 split, y pad zero -------------------
__global__ void k0_prep(const float* __restrict__ w5,
                        const float* __restrict__ g5, const float* __restrict__ v5,
                        const float* __restrict__ b5, const float* __restrict__ bt5,
                        const float* __restrict__ m5, const float* __restrict__ w4,
                        const float* __restrict__ w1, const float* __restrict__ b1,
                        const float* __restrict__ g1, const float* __restrict__ bt1,
                        const float* __restrict__ m1, const float* __restrict__ v1,
                        const float* __restrict__ w2, const float* __restrict__ b2,
                        const float* __restrict__ g2, const float* __restrict__ bt2,
                        const float* __restrict__ m2, const float* __restrict__ v2,
                        const float* __restrict__ w3, const float* __restrict__ b3,
                        const float* __restrict__ g3, const float* __restrict__ bt3,
                        const float* __restrict__ m3, const float* __restrict__ v3)
{
    const int blk = blockIdx.x;
    const int tid = threadIdx.x;
    if (blk < NC5) {
        const int k = blk;
        float s5 = g5[k] * rsqrtf(v5[k] + EPSV);
        for (int f = tid; f < KP; f += 256) {
            float val;
            if (f < 512) val = w5[k * NCF + 1 + f] * s5;
            else if (f == 512) val = w5[k * NCF] * s5;
            else val = 0.f;
            __nv_bfloat16 h, l;
            bf16_split(val, h, l);
            g_w5h[k * KP + f] = h;
            g_w5l[k * KP + f] = l;
        }
    } else if (blk == NC5) {
        const int k = tid;
        float s5 = g5[k] * rsqrtf(v5[k] + EPSV);
        g_sh5[k] = (b5[k] - m5[k]) * s5 + bt5[k];
        if (k < 3 * NCS) {
            int cv = k / NCS, c = k % NCS;
            const float* bb = cv == 0 ? b1 : (cv == 1 ? b2 : b3);
            const float* gg = cv == 0 ? g1 : (cv == 1 ? g2 : g3);
            const float* bt = cv == 0 ? bt1 : (cv == 1 ? bt2 : bt3);
            const float* mm = cv == 0 ? m1 : (cv == 1 ? m2 : m3);
            const float* vv = cv == 0 ? v1 : (cv == 1 ? v2 : v3);
            float s = gg[c] * rsqrtf(vv[c] + EPSV);
            g_sc[k] = s;
            g_sh[k] = (bb[c] - mm[c]) * s + bt[c];
        }
    } else if (blk < NC5 + 1 + NB) {
        const int b = blk - NC5 - 1;
        char* baseh = (char*)(g_yh + (size_t)b * NHW * KP + 512);
        char* basel = (char*)(g_yl + (size_t)b * NHW * KP + 512);
        uint4 z = make_uint4(0u, 0u, 0u, 0u);
        for (int i = tid; i < NHW * 4; i += 256) {
            int p = i >> 2, q = i & 3;
            *reinterpret_cast<uint4*>(baseh + (size_t)p * (KP * 2) + q * 16) = z;
            *reinterpret_cast<uint4*>(basel + (size_t)p * (KP * 2) + q * 16) = z;
        }
    } else if (blk < NC5 + 1 + NB + 192) {
        const int row = blk - (NC5 + 1 + NB);
        const int cv = row >> 6, c = row & 63;
        const float* W  = cv == 0 ? w1 : (cv == 1 ? w2 : w3);
        const float* gg = cv == 0 ? g1 : (cv == 1 ? g2 : g3);
        const float* vv = cv == 0 ? v1 : (cv == 1 ? v2 : v3);
        float s = gg[c] * rsqrtf(vv[c] + EPSV);
        float val = W[c * NINP + tid] * s;
        __nv_bfloat16 h, l;
        bf16_split(val, h, l);
        g_wch[row * NINP + tid] = h;
        g_wcl[row * NINP + tid] = l;
    } else {
        const int row = blk - (NC5 + 1 + NB + 192);
        float4 v = *reinterpret_cast<const float4*>(w4 + (size_t)row * NHW + tid * 4);
        __nv_bfloat16 h0, l0, h1, l1, h2, l2, h3, l3;
        bf16_split(v.x, h0, l0); bf16_split(v.y, h1, l1);
        bf16_split(v.z, h2, l2); bf16_split(v.w, h3, l3);
        size_t base = (size_t)row * NHW + tid * 4;
        *reinterpret_cast<uint2*>(&g_w4h[base]) = make_uint2(pk2(h0, h1), pk2(h2, h3));
        *reinterpret_cast<uint2*>(&g_w4l[base]) = make_uint2(pk2(l0, l1), pk2(l2, l3));
    }
}

// ---------------- Kx: x [b][c][p] fp32 -> x^T [b][p][c] split bf16 ------------
__global__ void __launch_bounds__(256) k_x(const float* __restrict__ x)
{
    __shared__ float sm[64 * 68];
    const int p0 = blockIdx.x * 64;
    const int c0 = blockIdx.y * 64;
    const int b  = blockIdx.z;
    const int tid = threadIdx.x;

    const float* src = x + (size_t)b * NINP * NHW;
    for (int i = tid; i < 1024; i += 256) {
        int c = i >> 4, pq = i & 15;
        float4 v = *reinterpret_cast<const float4*>(src + (size_t)(c0 + c) * NHW + p0 + pq * 4);
        *reinterpret_cast<float4*>(sm + c * 68 + pq * 4) = v;
    }
    __syncthreads();

    const int p = tid >> 2;
    const int cs = (tid & 3) * 16;
    uint32_t hb[8], lb[8];
#pragma unroll
    for (int j2 = 0; j2 < 8; j2++) {
        __nv_bfloat16 h0, l0, h1, l1;
        bf16_split(sm[(cs + j2 * 2) * 68 + p], h0, l0);
        bf16_split(sm[(cs + j2 * 2 + 1) * 68 + p], h1, l1);
        hb[j2] = pk2(h0, h1);
        lb[j2] = pk2(l0, l1);
    }
    size_t base = ((size_t)(b * NHW + p0 + p)) * NINP + c0 + cs;
    *reinterpret_cast<uint4*>(&g_xth[base])     = make_uint4(hb[0], hb[1], hb[2], hb[3]);
    *reinterpret_cast<uint4*>(&g_xth[base + 8]) = make_uint4(hb[4], hb[5], hb[6], hb[7]);
    *reinterpret_cast<uint4*>(&g_xtl[base])     = make_uint4(lb[0], lb[1], lb[2], lb[3]);
    *reinterpret_cast<uint4*>(&g_xtl[base + 8]) = make_uint4(lb[4], lb[5], lb[6], lb[7]);
}

// ---------------- K1: conv GEMM C[192,128px] = Wc[192,256] @ xt^T -------------
__global__ void __launch_bounds__(384) k1_mma(const float* __restrict__ dummy)
{
    extern __shared__ __nv_bfloat16 smb[];
    const int AH = 0, AL = 15360, BH = 30720, BL = 40960;
    const uint32_t smb_u = smem_u32(smb);
    const int tid = threadIdx.x;
    const int lane = tid & 31;
    const int wid = tid >> 5;
    const int mw3 = wid % 3;
    const int nw4 = wid / 3;
    const int b = blockIdx.y;
    const int p0 = blockIdx.x * 128;

    float acc[4][4][4];
#pragma unroll
    for (int mi = 0; mi < 4; mi++)
#pragma unroll
        for (int ni = 0; ni < 4; ni++)
#pragma unroll
            for (int c = 0; c < 4; c++) acc[mi][ni][c] = 0.f;

#define K1_COPY(ch, buf) do {                                                         \
    for (int i = tid; i < 768; i += 384) {                                            \
        int row = i >> 2, q = i & 3;                                                  \
        uint32_t dh = smb_u + (uint32_t)(AH + (buf) * 7680 + row * 40 + q * 8) * 2u;  \
        uint32_t dl = smb_u + (uint32_t)(AL + (buf) * 7680 + row * 40 + q * 8) * 2u;  \
        size_t so = (size_t)row * NINP + (ch) * 32 + q * 8;                           \
        asm volatile("cp.async.ca.shared.global [%0], [%1], 16;" :: "r"(dh), "l"(g_wch + so)); \
        asm volatile("cp.async.ca.shared.global [%0], [%1], 16;" :: "r"(dl), "l"(g_wcl + so)); \
    }                                                                                 \
    for (int i = tid; i < 512; i += 384) {                                            \
        int row = i >> 2, q = i & 3;                                                  \
        uint32_t dh = smb_u + (uint32_t)(BH + (buf) * 5120 + row * 40 + q * 8) * 2u;  \
        uint32_t dl = smb_u + (uint32_t)(BL + (buf) * 5120 + row * 40 + q * 8) * 2u;  \
        size_t so = ((size_t)(b * NHW + p0 + row)) * NINP + (ch) * 32 + q * 8;        \
        asm volatile("cp.async.ca.shared.global [%0], [%1], 16;" :: "r"(dh), "l"(g_xth + so)); \
        asm volatile("cp.async.ca.shared.global [%0], [%1], 16;" :: "r"(dl), "l"(g_xtl + so)); \
    }                                                                                 \
    asm volatile("cp.async.commit_group;");                                           \
} while (0)

    K1_COPY(0, 0);
    for (int ch = 0; ch < 8; ch++) {
        if (ch < 7) {
            K1_COPY(ch + 1, (ch + 1) & 1);
            asm volatile("cp.async.wait_group 1;");
        } else {
            asm volatile("cp.async.wait_group 0;");
        }
        __syncthreads();
        const int buf = ch & 1;
        const __nv_bfloat16* Ah = smb + AH + buf * 7680 + (mw3 * 64) * 40;
        const __nv_bfloat16* Al = smb + AL + buf * 7680 + (mw3 * 64) * 40;
        const __nv_bfloat16* Bh = smb + BH + buf * 5120 + (nw4 * 32) * 40;
        const __nv_bfloat16* Bl = smb + BL + buf * 5120 + (nw4 * 32) * 40;
#pragma unroll
        for (int ks = 0; ks < 2; ks++) {
            const int ar = lane >> 2;
            const int ak = ks * 16 + (lane & 3) * 2;
            uint32_t ah[4][4], al[4][4], bh[4][2], bl[4][2];
#pragma unroll
            for (int mi = 0; mi < 4; mi++) {
                int r = mi * 16 + ar;
                ah[mi][0] = *reinterpret_cast<const uint32_t*>(Ah + r * 40 + ak);
                ah[mi][1] = *reinterpret_cast<const uint32_t*>(Ah + (r + 8) * 40 + ak);
                ah[mi][2] = *reinterpret_cast<const uint32_t*>(Ah + r * 40 + ak + 8);
                ah[mi][3] = *reinterpret_cast<const uint32_t*>(Ah + (r + 8) * 40 + ak + 8);
                al[mi][0] = *reinterpret_cast<const uint32_t*>(Al + r * 40 + ak);
                al[mi][1] = *reinterpret_cast<const uint32_t*>(Al + (r + 8) * 40 + ak);
                al[mi][2] = *reinterpret_cast<const uint32_t*>(Al + r * 40 + ak + 8);
                al[mi][3] = *reinterpret_cast<const uint32_t*>(Al + (r + 8) * 40 + ak + 8);
            }
#pragma unroll
            for (int ni = 0; ni < 4; ni++) {
                int n = ni * 8 + (lane >> 2);
                bh[ni][0] = *reinterpret_cast<const uint32_t*>(Bh + n * 40 + ak);
                bh[ni][1] = *reinterpret_cast<const uint32_t*>(Bh + n * 40 + ak + 8);
                bl[ni][0] = *reinterpret_cast<const uint32_t*>(Bl + n * 40 + ak);
                bl[ni][1] = *reinterpret_cast<const uint32_t*>(Bl + n * 40 + ak + 8);
            }
#pragma unroll
            for (int mi = 0; mi < 4; mi++)
#pragma unroll
                for (int ni = 0; ni < 4; ni++) {
                    MMA_BF16(acc[mi][ni], al[mi][0], al[mi][1], al[mi][2], al[mi][3],
                             bh[ni][0], bh[ni][1]);
                    MMA_BF16(acc[mi][ni], ah[mi][0], ah[mi][1], ah[mi][2], ah[mi][3],
                             bl[ni][0], bl[ni][1]);
                    MMA_BF16(acc[mi][ni], ah[mi][0], ah[mi][1], ah[mi][2], ah[mi][3],
                             bh[ni][0], bh[ni][1]);
                }
        }
        __syncthreads();
    }
#undef K1_COPY

    const int ar = lane >> 2;
    const int qq = lane & 3;
    if (mw3 < 2) {
        float* dst = (mw3 == 0 ? g_theta : g_phi) + (size_t)b * NCS * NHW;
#pragma unroll
        for (int mi = 0; mi < 4; mi++)
#pragma unroll
            for (int rh = 0; rh < 2; rh++) {
                int c = mi * 16 + ar + rh * 8;
                float sh = g_sh[mw3 * 64 + c];
#pragma unroll
                for (int ni = 0; ni < 4; ni++) {
                    int px = p0 + nw4 * 32 + ni * 8 + 2 * qq;
                    float2 o;
                    o.x = fmaxf(acc[mi][ni][rh * 2 + 0] + sh, 0.f);
                    o.y = fmaxf(acc[mi][ni][rh * 2 + 1] + sh, 0.f);
                    *reinterpret_cast<float2*>(dst + (size_t)c * NHW + px) = o;
                }
            }
    } else {
        float s_px[8];
#pragma unroll
        for (int ni = 0; ni < 4; ni++)
#pragma unroll
            for (int j = 0; j < 2; j++) {
                float s = 0.f;
#pragma unroll
                for (int mi = 0; mi < 4; mi++)
#pragma unroll
                    for (int rh = 0; rh < 2; rh++) {
                        int c = mi * 16 + ar + rh * 8;
                        s += fmaxf(acc[mi][ni][rh * 2 + j] + g_sh[128 + c], 0.f);
                    }
                s_px[ni * 2 + j] = s;
            }
#pragma unroll
        for (int v = 0; v < 8; v++) {
            s_px[v] += __shfl_xor_sync(0xffffffffu, s_px[v], 4);
            s_px[v] += __shfl_xor_sync(0xffffffffu, s_px[v], 8);
            s_px[v] += __shfl_xor_sync(0xffffffffu, s_px[v], 16);
        }
        if (lane < 4) {
#pragma unroll
            for (int ni = 0; ni < 4; ni++)
#pragma unroll
                for (int j = 0; j < 2; j++) {
                    int px = p0 + nw4 * 32 + ni * 8 + 2 * lane + j;
                    float val = s_px[ni * 2 + j] * (1.f / NCS);
                    __nv_bfloat16 h, l;
                    bf16_split(val, h, l);
                    size_t base = (size_t)(b * NHW + px) * KP + 512;
                    g_yh[base] = h;
                    g_yl[base] = l;
                }
        }
    }
}

// ---------------- K2t: transpose+split phi -> P^T ; split theta ---------------
__global__ void __launch_bounds__(256) k2t()
{
    __shared__ float sm[64 * 68];
    const int jt = blockIdx.x;
    const int task = blockIdx.y;
    const int b = blockIdx.z;
    const int tid = threadIdx.x;

    if (task == 0) {
        const float* src = g_phi + (size_t)b * NCS * NHW + jt * 4096;
        for (int i = tid; i < 1024; i += 256) {
            int r = i >> 4, cq = i & 15;
            float4 v = *reinterpret_cast<const float4*>(src + r * 64 + cq * 4);
            *reinterpret_cast<float4*>(sm + r * 68 + cq * 4) = v;
        }
        __syncthreads();
        const int jg = tid >> 6;
        const int c = tid & 63;
        uint32_t hb[8], lb[8];
#pragma unroll
        for (int k2i = 0; k2i < 8; k2i++) {
            __nv_bfloat16 h0, l0, h1, l1;
            bf16_split(sm[(jg * 16 + k2i * 2) * 68 + c], h0, l0);
            bf16_split(sm[(jg * 16 + k2i * 2 + 1) * 68 + c], h1, l1);
            hb[k2i] = pk2(h0, h1);
            lb[k2i] = pk2(l0, l1);
        }
        size_t base = (size_t)b * NCS * NHW + (size_t)c * NHW + jt * 64 + jg * 16;
        *reinterpret_cast<uint4*>(&g_pTh[base])     = make_uint4(hb[0], hb[1], hb[2], hb[3]);
        *reinterpret_cast<uint4*>(&g_pTh[base + 8]) = make_uint4(hb[4], hb[5], hb[6], hb[7]);
        *reinterpret_cast<uint4*>(&g_pTl[base])     = make_uint4(lb[0], lb[1], lb[2], lb[3]);
        *reinterpret_cast<uint4*>(&g_pTl[base + 8]) = make_uint4(lb[4], lb[5], lb[6], lb[7]);
    } else {
        const float* src = g_theta + (size_t)b * NCS * NHW + jt * 4096;
        size_t dbase = (size_t)b * NCS * NHW + jt * 4096;
        for (int i = tid; i < 1024; i += 256) {
            float4 v = *reinterpret_cast<const float4*>(src + i * 4);
            __nv_bfloat16 h0, l0, h1, l1, h2, l2, h3, l3;
            bf16_split(v.x, h0, l0); bf16_split(v.y, h1, l1);
            bf16_split(v.z, h2, l2); bf16_split(v.w, h3, l3);
            *reinterpret_cast<uint2*>(&g_thh[dbase + i * 4]) = make_uint2(pk2(h0, h1), pk2(h2, h3));
            *reinterpret_cast<uint2*>(&g_thl[dbase + i * 4]) = make_uint2(pk2(l0, l1), pk2(l2, l3));
        }
    }
}

// ---------------- K2: mma GEMM -> WP / TW^T -----------------------------------
__global__ void __launch_bounds__(128) k2_mma()
{
    extern __shared__ __nv_bfloat16 smb[];
    const int AH = 0, AL = 9216, BH = 18432, BL = 27648;
    const uint32_t smb_u = smem_u32(smb);
    const int tid = threadIdx.x;
    const int lane = tid & 31;
    const int wid = tid >> 5;
    const int mw = wid & 1;
    const int nw = wid >> 1;
    const int o0 = blockIdx.x * 64;
    const int which = blockIdx.y;
    const int b = blockIdx.z;

    const __nv_bfloat16* Asrch = g_w4h + (size_t)o0 * NHW;
    const __nv_bfloat16* Asrcl = g_w4l + (size_t)o0 * NHW;
    const __nv_bfloat16* Bsrch = (which ? g_thh : g_pTh) + (size_t)b * NCS * NHW;
    const __nv_bfloat16* Bsrcl = (which ? g_thl : g_pTl) + (size_t)b * NCS * NHW;

    float acc[2][4][4];
#pragma unroll
    for (int mi = 0; mi < 2; mi++)
#pragma unroll
        for (int ni = 0; ni < 4; ni++)
#pragma unroll
            for (int c = 0; c < 4; c++) acc[mi][ni][c] = 0.f;

#define K2_COPY(ch, buf) do {                                                         \
    for (int i = tid; i < 512; i += 128) {                                            \
        int row = i >> 3, q = i & 7;                                                  \
        uint32_t dh = smb_u + (uint32_t)(AH + (buf) * 4608 + row * 72 + q * 8) * 2u;  \
        uint32_t dl = smb_u + (uint32_t)(AL + (buf) * 4608 + row * 72 + q * 8) * 2u;  \
        size_t so = (size_t)row * NHW + (ch) * 64 + q * 8;                            \
        asm volatile("cp.async.ca.shared.global [%0], [%1], 16;" :: "r"(dh), "l"(Asrch + so)); \
        asm volatile("cp.async.ca.shared.global [%0], [%1], 16;" :: "r"(dl), "l"(Asrcl + so)); \
    }                                                                                 \
    for (int i = tid; i < 512; i += 128) {                                            \
        int row = i >> 3, q = i & 7;                                                  \
        uint32_t dh = smb_u + (uint32_t)(BH + (buf) * 4608 + row * 72 + q * 8) * 2u;  \
        uint32_t dl = smb_u + (uint32_t)(BL + (buf) * 4608 + row * 72 + q * 8) * 2u;  \
        size_t so = (size_t)row * NHW + (ch) * 64 + q * 8;                            \
        asm volatile("cp.async.ca.shared.global [%0], [%1], 16;" :: "r"(dh), "l"(Bsrch + so)); \
        asm volatile("cp.async.ca.shared.global [%0], [%1], 16;" :: "r"(dl), "l"(Bsrcl + so)); \
    }                                                                                 \
    asm volatile("cp.async.commit_group;");                                           \
} while (0)

    K2_COPY(0, 0);
    for (int ch = 0; ch < 16; ch++) {
        if (ch < 15) {
            K2_COPY(ch + 1, (ch + 1) & 1);
            asm volatile("cp.async.wait_group 1;");
        } else {
            asm volatile("cp.async.wait_group 0;");
        }
        __syncthreads();
        const int buf = ch & 1;
        const __nv_bfloat16* Ah = smb + AH + buf * 4608 + (mw * 32) * 72;
        const __nv_bfloat16* Al = smb + AL + buf * 4608 + (mw * 32) * 72;
        const __nv_bfloat16* Bh = smb + BH + buf * 4608 + (nw * 32) * 72;
        const __nv_bfloat16* Bl = smb + BL + buf * 4608 + (nw * 32) * 72;
#pragma unroll
        for (int ks = 0; ks < 4; ks++) {
            const int ar = lane >> 2;
            const int ak = ks * 16 + (lane & 3) * 2;
            uint32_t ah[2][4], al[2][4], bh[4][2], bl[4][2];
#pragma unroll
            for (int mi = 0; mi < 2; mi++) {
                int r = mi * 16 + ar;
                ah[mi][0] = *reinterpret_cast<const uint32_t*>(Ah + r * 72 + ak);
                ah[mi][1] = *reinterpret_cast<const uint32_t*>(Ah + (r + 8) * 72 + ak);
                ah[mi][2] = *reinterpret_cast<const uint32_t*>(Ah + r * 72 + ak + 8);
                ah[mi][3] = *reinterpret_cast<const uint32_t*>(Ah + (r + 8) * 72 + ak + 8);
                al[mi][0] = *reinterpret_cast<const uint32_t*>(Al + r * 72 + ak);
                al[mi][1] = *reinterpret_cast<const uint32_t*>(Al + (r + 8) * 72 + ak);
                al[mi][2] = *reinterpret_cast<const uint32_t*>(Al + r * 72 + ak + 8);
                al[mi][3] = *reinterpret_cast<const uint32_t*>(Al + (r + 8) * 72 + ak + 8);
            }
#pragma unroll
            for (int ni = 0; ni < 4; ni++) {
                int n = ni * 8 + (lane >> 2);
                bh[ni][0] = *reinterpret_cast<const uint32_t*>(Bh + n * 72 + ak);
                bh[ni][1] = *reinterpret_cast<const uint32_t*>(Bh + n * 72 + ak + 8);
                bl[ni][0] = *reinterpret_cast<const uint32_t*>(Bl + n * 72 + ak);
                bl[ni][1] = *reinterpret_cast<const uint32_t*>(Bl + n * 72 + ak + 8);
            }
#pragma unroll
            for (int mi = 0; mi < 2; mi++)
#pragma unroll
                for (int ni = 0; ni < 4; ni++) {
                    MMA_BF16(acc[mi][ni], al[mi][0], al[mi][1], al[mi][2], al[mi][3],
                             bh[ni][0], bh[ni][1]);
                    MMA_BF16(acc[mi][ni], ah[mi][0], ah[mi][1], ah[mi][2], ah[mi][3],
                             bl[ni][0], bl[ni][1]);
                    MMA_BF16(acc[mi][ni], ah[mi][0], ah[mi][1], ah[mi][2], ah[mi][3],
                             bh[ni][0], bh[ni][1]);
                }
        }
        __syncthreads();
    }
#undef K2_COPY

    const int ar = lane >> 2;
    const int qq = lane & 3;
    __nv_bfloat16* WH = g_WPh + (size_t)b * 512 * NCS;
    __nv_bfloat16* WL = g_WPl + (size_t)b * 512 * NCS;
#pragma unroll
    for (int mi = 0; mi < 2; mi++)
#pragma unroll
        for (int rh = 0; rh < 2; rh++) {
            int row = which * 256 + o0 + mw * 32 + mi * 16 + ar + rh * 8;
#pragma unroll
            for (int ni = 0; ni < 4; ni++) {
                int col = nw * 32 + ni * 8 + 2 * qq;
                __nv_bfloat16 h0, l0, h1, l1;
                bf16_split(acc[mi][ni][rh * 2 + 0], h0, l0);
                bf16_split(acc[mi][ni][rh * 2 + 1], h1, l1);
                *reinterpret_cast<uint32_t*>(WH + (size_t)row * NCS + col) = pk2(h0, h1);
                *reinterpret_cast<uint32_t*>(WL + (size_t)row * NCS + col) = pk2(l0, l1);
            }
        }
}

// ---------------- K3: C[128px, 256f] = A[px, 64c] @ B[f, 64c]^T ---------------
__global__ void __launch_bounds__(512) k3_mma(const float* __restrict__ b4)
{
    extern __shared__ __nv_bfloat16 smb[];
    const int AH = 0, AL = 9216, BH = 18432, BL = 36864;
    const uint32_t smb_u = smem_u32(smb);
    const int tid = threadIdx.x;
    const int lane = tid & 31;
    const int wid = tid >> 5;
    const int mw = wid & 3;
    const int nw = wid >> 2;
    const int p0 = blockIdx.x * 128;
    const int which = blockIdx.y;
    const int b = blockIdx.z;

    {
        const __nv_bfloat16* srch = g_WPh + ((size_t)b * 512 + which * 256) * NCS;
        const __nv_bfloat16* srcl = g_WPl + ((size_t)b * 512 + which * 256) * NCS;
        for (int i = tid; i < 2048; i += 512) {
            int row = i >> 3, q = i & 7;
            uint32_t dh = smb_u + (uint32_t)(BH + row * 72 + q * 8) * 2u;
            uint32_t dl = smb_u + (uint32_t)(BL + row * 72 + q * 8) * 2u;
            size_t so = (size_t)row * NCS + q * 8;
            asm volatile("cp.async.ca.shared.global [%0], [%1], 16;" :: "r"(dh), "l"(srch + so));
            asm volatile("cp.async.ca.shared.global [%0], [%1], 16;" :: "r"(dl), "l"(srcl + so));
        }
        asm volatile("cp.async.commit_group;");
    }
    if (which == 0) {
        const float* th = g_theta + (size_t)b * NCS * NHW;
        for (int i = tid; i < 2048; i += 512) {
            int c = i >> 5, pq = i & 31;
            float4 v = *reinterpret_cast<const float4*>(th + (size_t)c * NHW + p0 + pq * 4);
#pragma unroll
            for (int j = 0; j < 4; j++) {
                __nv_bfloat16 h, l;
                bf16_split(f4get(v, j), h, l);
                smb[AH + (pq * 4 + j) * 72 + c] = h;
                smb[AL + (pq * 4 + j) * 72 + c] = l;
            }
        }
    } else {
        const float* ph = g_phi + (size_t)b * NCS * NHW;
        for (int i = tid; i < 2048; i += 512) {
            int p = i >> 4, cq = i & 15;
            float4 v = *reinterpret_cast<const float4*>(ph + (size_t)(p0 + p) * NCS + cq * 4);
            __nv_bfloat16 h0, l0, h1, l1, h2, l2, h3, l3;
            bf16_split(v.x, h0, l0); bf16_split(v.y, h1, l1);
            bf16_split(v.z, h2, l2); bf16_split(v.w, h3, l3);
            *reinterpret_cast<uint2*>(&smb[AH + p * 72 + cq * 4]) =
                make_uint2(pk2(h0, h1), pk2(h2, h3));
            *reinterpret_cast<uint2*>(&smb[AL + p * 72 + cq * 4]) =
                make_uint2(pk2(l0, l1), pk2(l2, l3));
        }
    }
    asm volatile("cp.async.wait_group 0;");
    __syncthreads();

    float acc[2][8][4];
#pragma unroll
    for (int mi = 0; mi < 2; mi++)
#pragma unroll
        for (int ni = 0; ni < 8; ni++)
#pragma unroll
            for (int c = 0; c < 4; c++) acc[mi][ni][c] = 0.f;

    const __nv_bfloat16* Ah = smb + AH + (mw * 32) * 72;
    const __nv_bfloat16* Al = smb + AL + (mw * 32) * 72;
    const __nv_bfloat16* Bh = smb + BH + (nw * 64) * 72;
    const __nv_bfloat16* Bl = smb + BL + (nw * 64) * 72;
#pragma unroll
    for (int ks = 0; ks < 4; ks++) {
        const int ar = lane >> 2;
        const int ak = ks * 16 + (lane & 3) * 2;
        uint32_t ah[2][4], al[2][4];
#pragma unroll
        for (int mi = 0; mi < 2; mi++) {
            int r = mi * 16 + ar;
            ah[mi][0] = *reinterpret_cast<const uint32_t*>(Ah + r * 72 + ak);
            ah[mi][1] = *reinterpret_cast<const uint32_t*>(Ah + (r + 8) * 72 + ak);
            ah[mi][2] = *reinterpret_cast<const uint32_t*>(Ah + r * 72 + ak + 8);
            ah[mi][3] = *reinterpret_cast<const uint32_t*>(Ah + (r + 8) * 72 + ak + 8);
            al[mi][0] = *reinterpret_cast<const uint32_t*>(Al + r * 72 + ak);
            al[mi][1] = *reinterpret_cast<const uint32_t*>(Al + (r + 8) * 72 + ak);
            al[mi][2] = *reinterpret_cast<const uint32_t*>(Al + r * 72 + ak + 8);
            al[mi][3] = *reinterpret_cast<const uint32_t*>(Al + (r + 8) * 72 + ak + 8);
        }
#pragma unroll
        for (int ni = 0; ni < 8; ni++) {
            int n = ni * 8 + (lane >> 2);
            uint32_t bh0 = *reinterpret_cast<const uint32_t*>(Bh + n * 72 + ak);
            uint32_t bh1 = *reinterpret_cast<const uint32_t*>(Bh + n * 72 + ak + 8);
            uint32_t bl0 = *reinterpret_cast<const uint32_t*>(Bl + n * 72 + ak);
            uint32_t bl1 = *reinterpret_cast<const uint32_t*>(Bl + n * 72 + ak + 8);
#pragma unroll
            for (int mi = 0; mi < 2; mi++) {
                MMA_BF16(acc[mi][ni], al[mi][0], al[mi][1], al[mi][2], al[mi][3], bh0, bh1);
                MMA_BF16(acc[mi][ni], ah[mi][0], ah[mi][1], ah[mi][2], ah[mi][3], bl0, bl1);
                MMA_BF16(acc[mi][ni], ah[mi][0], ah[mi][1], ah[mi][2], ah[mi][3], bh0, bh1);
            }
        }
    }

    const int ar = lane >> 2;
    const int qq = lane & 3;
#pragma unroll
    for (int ni = 0; ni < 8; ni++) {
        int o = nw * 64 + ni * 8 + 2 * qq;
        float2 bb = *reinterpret_cast<const float2*>(b4 + o);
        int f0 = which * 256 + o;
#pragma unroll
        for (int mi = 0; mi < 2; mi++)
#pragma unroll
            for (int rh = 0; rh < 2; rh++) {
                int px = p0 + mw * 32 + mi * 16 + ar + rh * 8;
                float v0 = fmaxf(acc[mi][ni][rh * 2 + 0] + bb.x, 0.f);
                float v1 = fmaxf(acc[mi][ni][rh * 2 + 1] + bb.y, 0.f);
                __nv_bfloat16 h0, l0, h1, l1;
                bf16_split(v0, h0, l0);
                bf16_split(v1, h1, l1);
                size_t base = (size_t)(b * NHW + px) * KP + f0;
                *reinterpret_cast<uint32_t*>(&g_yh[base]) = pk2(h0, h1);
                *reinterpret_cast<uint32_t*>(&g_yl[base]) = pk2(l0, l1);
            }
    }
}

// ---------------- K4: quarter-tile split-bf16 GEMM + partial-logit epilogue ---
// grid (16 pt of 64px, 2 mt of 128ch, 32 b), 128 thr = 4 warps (2M x 2N, m64n32)
// smem bf16: Ah[2][5120] Al Bh[2][2560] Bl = 30720 el = 61440 B (row stride 40)
__global__ void __launch_bounds__(128, 3) k4_mma(const float* __restrict__ w6)
{
    extern __shared__ __nv_bfloat16 smb[];
    const int AH = 0, AL = 10240, BH = 20480, BL = 25600;
    const uint32_t smb_u = smem_u32(smb);
    const int tid = threadIdx.x;
    const int lane = tid & 31;
    const int wid = tid >> 5;
    const int mw = wid & 1;             // M: mw*64 within the 128-ch half
    const int nw = wid >> 1;            // N: nw*32 px
    const int p0 = blockIdx.x * 64;
    const int mt = blockIdx.y;          // which 128-channel half
    const int b = blockIdx.z;
    const size_t pixbase = (size_t)(b * NHW + p0);
    const size_t arowbase = (size_t)(mt * 128) * KP;

    float acc[4][4][4];
#pragma unroll
    for (int mi = 0; mi < 4; mi++)
#pragma unroll
        for (int ni = 0; ni < 4; ni++)
#pragma unroll
            for (int c = 0; c < 4; c++) acc[mi][ni][c] = 0.f;

#define COPY_CHUNK(ch, buf) do {                                                     \
    for (int i = tid; i < 512; i += 128) {                                           \
        int row = i >> 2, q = i & 3;                                                 \
        uint32_t dh = smb_u + (uint32_t)(AH + (buf) * 5120 + row * 40 + q * 8) * 2u; \
        uint32_t dl = smb_u + (uint32_t)(AL + (buf) * 5120 + row * 40 + q * 8) * 2u; \
        size_t so = arowbase + (size_t)row * KP + (ch) * 32 + q * 8;                 \
        asm volatile("cp.async.ca.shared.global [%0], [%1], 16;" :: "r"(dh), "l"(g_w5h + so)); \
        asm volatile("cp.async.ca.shared.global [%0], [%1], 16;" :: "r"(dl), "l"(g_w5l + so)); \
    }                                                                                \
    for (int i = tid; i < 256; i += 128) {                                           \
        int row = i >> 2, q = i & 3;                                                 \
        uint32_t dh = smb_u + (uint32_t)(BH + (buf) * 2560 + row * 40 + q * 8) * 2u; \
        uint32_t dl = smb_u + (uint32_t)(BL + (buf) * 2560 + row * 40 + q * 8) * 2u; \
        size_t so = (pixbase + row) * KP + (ch) * 32 + q * 8;                        \
        asm volatile("cp.async.ca.shared.global [%0], [%1], 16;" :: "r"(dh), "l"(g_yh + so)); \
        asm volatile("cp.async.ca.shared.global [%0], [%1], 16;" :: "r"(dl), "l"(g_yl + so)); \
    }                                                                                \
    asm volatile("cp.async.commit_group;");                                          \
} while (0)

    COPY_CHUNK(0, 0);
    for (int ch = 0; ch < NCHUNK; ch++) {
        if (ch < NCHUNK - 1) {
            COPY_CHUNK(ch + 1, (ch + 1) & 1);
            asm volatile("cp.async.wait_group 1;");
        } else {
            asm volatile("cp.async.wait_group 0;");
        }
        __syncthreads();
        const int buf = ch & 1;
        const __nv_bfloat16* Ah = smb + AH + buf * 5120 + (mw * 64) * 40;
        const __nv_bfloat16* Al = smb + AL + buf * 5120 + (mw * 64) * 40;
        const __nv_bfloat16* Bh = smb + BH + buf * 2560 + (nw * 32) * 40;
        const __nv_bfloat16* Bl = smb + BL + buf * 2560 + (nw * 32) * 40;
#pragma unroll
        for (int ks = 0; ks < 2; ks++) {
            const int ar = lane >> 2;
            const int ak = ks * 16 + (lane & 3) * 2;
            uint32_t ah[4][4], al[4][4], bh[4][2], bl[4][2];
#pragma unroll
            for (int mi = 0; mi < 4; mi++) {
                int r = mi * 16 + ar;
                ah[mi][0] = *reinterpret_cast<const uint32_t*>(Ah + r * 40 + ak);
                ah[mi][1] = *reinterpret_cast<const uint32_t*>(Ah + (r + 8) * 40 + ak);
                ah[mi][2] = *reinterpret_cast<const uint32_t*>(Ah + r * 40 + ak + 8);
                ah[mi][3] = *reinterpret_cast<const uint32_t*>(Ah + (r + 8) * 40 + ak + 8);
                al[mi][0] = *reinterpret_cast<const uint32_t*>(Al + r * 40 + ak);
                al[mi][1] = *reinterpret_cast<const uint32_t*>(Al + (r + 8) * 40 + ak);
                al[mi][2] = *reinterpret_cast<const uint32_t*>(Al + r * 40 + ak + 8);
                al[mi][3] = *reinterpret_cast<const uint32_t*>(Al + (r + 8) * 40 + ak + 8);
            }
#pragma unroll
            for (int ni = 0; ni < 4; ni++) {
                int n = ni * 8 + (lane >> 2);
                bh[ni][0] = *reinterpret_cast<const uint32_t*>(Bh + n * 40 + ak);
                bh[ni][1] = *reinterpret_cast<const uint32_t*>(Bh + n * 40 + ak + 8);
                bl[ni][0] = *reinterpret_cast<const uint32_t*>(Bl + n * 40 + ak);
                bl[ni][1] = *reinterpret_cast<const uint32_t*>(Bl + n * 40 + ak + 8);
            }
#pragma unroll
            for (int mi = 0; mi < 4; mi++)
#pragma unroll
                for (int ni = 0; ni < 4; ni++) {
                    MMA_BF16(acc[mi][ni], al[mi][0], al[mi][1], al[mi][2], al[mi][3],
                             bh[ni][0], bh[ni][1]);
                    MMA_BF16(acc[mi][ni], ah[mi][0], ah[mi][1], ah[mi][2], ah[mi][3],
                             bl[ni][0], bl[ni][1]);
                    MMA_BF16(acc[mi][ni], ah[mi][0], ah[mi][1], ah[mi][2], ah[mi][3],
                             bh[ni][0], bh[ni][1]);
                }
        }
        __syncthreads();
    }
#undef COPY_CHUNK

    // partial logit over this CTA's 128 channels
    float shv[8], wkv[8];
#pragma unroll
    for (int mi = 0; mi < 4; mi++)
#pragma unroll
        for (int rh = 0; rh < 2; rh++) {
            int m = mt * 128 + mw * 64 + mi * 16 + (lane >> 2) + rh * 8;
            shv[mi * 2 + rh] = g_sh5[m];
            wkv[mi * 2 + rh] = w6[m];
        }

    float* red = reinterpret_cast<float*>(smb);     // [64][17]
    const int slice = mw * 8 + (lane >> 2);
#pragma unroll
    for (int ni = 0; ni < 4; ni++)
#pragma unroll
        for (int j = 0; j < 2; j++) {
            float s = 0.f;
#pragma unroll
            for (int mi = 0; mi < 4; mi++)
#pragma unroll
                for (int rh = 0; rh < 2; rh++) {
                    float z = fmaxf(acc[mi][ni][rh * 2 + j] + shv[mi * 2 + rh], 0.f);
                    s = fmaf(z, wkv[mi * 2 + rh], s);
                }
            int col = nw * 32 + ni * 8 + 2 * (lane & 3) + j;
            red[col * 17 + slice] = s;
        }
    __syncthreads();
    if (tid < 64) {
        float t = 0.f;
#pragma unroll
        for (int r = 0; r < 16; r++) t += red[tid * 17 + r];
        g_part[mt][b * NHW + p0 + tid] = t;
    }
}

// ---------------- K5: a = sigmoid(part0+part1+b6); out = x * a ----------------
__global__ void __launch_bounds__(256) k5_scale(const float* __restrict__ x,
                                                const float* __restrict__ b6,
                                                float* __restrict__ out)
{
    int idx = blockIdx.x * 256 + threadIdx.x;
    float4 xv = reinterpret_cast<const float4*>(x)[idx];
    int pix4 = idx & 255;
    int b = idx >> 16;
    float4 t0 = reinterpret_cast<const float4*>(g_part[0])[b * 256 + pix4];
    float4 t1 = reinterpret_cast<const float4*>(g_part[1])[b * 256 + pix4];
    float bb = b6[0];
    float4 av;
    av.x = 1.f / (1.f + expf(-(t0.x + t1.x + bb)));
    av.y = 1.f / (1.f + expf(-(t0.y + t1.y + bb)));
    av.z = 1.f / (1.f + expf(-(t0.z + t1.z + bb)));
    av.w = 1.f / (1.f + expf(-(t0.w + t1.w + bb)));
    float4 o;
    o.x = xv.x * av.x; o.y = xv.y * av.y; o.z = xv.z * av.z; o.w = xv.w * av.w;
    reinterpret_cast<float4*>(out)[idx] = o;
}

// ---------------- launch ------------------------------------------------------
extern "C" void kernel_launch(void* const* d_in, const int* in_sizes, int n_in,
                              void* d_out, int out_size)
{
    const float* x   = (const float*)d_in[0];
    const float* w1  = (const float*)d_in[1];
    const float* b1  = (const float*)d_in[2];
    const float* g1  = (const float*)d_in[3];
    const float* bt1 = (const float*)d_in[4];
    const float* m1  = (const float*)d_in[5];
    const float* v1  = (const float*)d_in[6];
    const float* w2  = (const float*)d_in[7];
    const float* b2  = (const float*)d_in[8];
    const float* g2  = (const float*)d_in[9];
    const float* bt2 = (const float*)d_in[10];
    const float* m2  = (const float*)d_in[11];
    const float* v2  = (const float*)d_in[12];
    const float* w3  = (const float*)d_in[13];
    const float* b3  = (const float*)d_in[14];
    const float* g3  = (const float*)d_in[15];
    const float* bt3 = (const float*)d_in[16];
    const float* m3  = (const float*)d_in[17];
    const float* v3  = (const float*)d_in[18];
    const float* w4  = (const float*)d_in[19];
    const float* b4  = (const float*)d_in[20];
    const float* w5  = (const float*)d_in[21];
    const float* b5  = (const float*)d_in[22];
    const float* g5  = (const float*)d_in[23];
    const float* bt5 = (const float*)d_in[24];
    const float* m5  = (const float*)d_in[25];
    const float* v5  = (const float*)d_in[26];
    const float* w6  = (const float*)d_in[27];
    const float* b6  = (const float*)d_in[28];

    cudaFuncSetAttribute(k1_mma, cudaFuncAttributeMaxDynamicSharedMemorySize, 102400);
    cudaFuncSetAttribute(k2_mma, cudaFuncAttributeMaxDynamicSharedMemorySize, 73728);
    cudaFuncSetAttribute(k3_mma, cudaFuncAttributeMaxDynamicSharedMemorySize, 110592);
    cudaFuncSetAttribute(k4_mma, cudaFuncAttributeMaxDynamicSharedMemorySize, 61440);

    k0_prep<<<NC5 + 1 + NB + 192 + 256, 256>>>(w5, g5, v5, b5, bt5, m5, w4,
                                               w1, b1, g1, bt1, m1, v1,
                                               w2, b2, g2, bt2, m2, v2,
                                               w3, b3, g3, bt3, m3, v3);
    k_x<<<dim3(16, 4, NB), 256>>>(x);
    k1_mma<<<dim3(8, NB), 384, 102400>>>(nullptr);
    k2t<<<dim3(16, 2, NB), 256>>>();
    k2_mma<<<dim3(4, 2, NB), 128, 73728>>>();
    k3_mma<<<dim3(8, 2, NB), 512, 110592>>>(b4);
    k4_mma<<<dim3(16, 2, NB), 128, 61440>>>(w6);
    k5_scale<<<(NB * NINP * NHW / 4) / 256, 256>>>(x, b6, (float*)d_out);
}

// round 10
// speedup vs baseline: 2.0555x; 1.0160x over previous
#include <cuda_runtime.h>
#include <cuda_bf16.h>
#include <math.h>
#include <stdint.h>

#define NB 32
#define NINP 256
#define NHW 1024
#define NCS 64
#define NAOUT 256
#define NCF 513
#define NC5 256
#define EPSV 1e-5f
#define KP 544
#define NCHUNK 17

// ---------------- scratch ------------------------------------------------------
__device__ float g_theta[NB * NCS * NHW];   // [b][c][p] fp32
__device__ float g_phi[NB * NCS * NHW];     // [b][c][p] fp32
__device__ __align__(16) __nv_bfloat16 g_xth[NB * NHW * NINP];  // x^T split hi [b][p][c]
__device__ __align__(16) __nv_bfloat16 g_xtl[NB * NHW * NINP];
__device__ __align__(16) __nv_bfloat16 g_wch[192 * NINP];       // stacked folded conv w
__device__ __align__(16) __nv_bfloat16 g_wcl[192 * NINP];
__device__ __align__(16) __nv_bfloat16 g_w4h[NAOUT * NHW];      // w4 split [o][j]
__device__ __align__(16) __nv_bfloat16 g_w4l[NAOUT * NHW];
__device__ __align__(16) __nv_bfloat16 g_pTh[NB * NCS * NHW];   // P^T split [b][c][j]
__device__ __align__(16) __nv_bfloat16 g_pTl[NB * NCS * NHW];
__device__ __align__(16) __nv_bfloat16 g_thh[NB * NCS * NHW];   // theta split [b][c][p]
__device__ __align__(16) __nv_bfloat16 g_thl[NB * NCS * NHW];
__device__ __align__(16) __nv_bfloat16 g_WPh[NB * 512 * NCS];   // [b][row][c]; 0..255 WP, 256..511 TW^T
__device__ __align__(16) __nv_bfloat16 g_WPl[NB * 512 * NCS];
__device__ __align__(16) __nv_bfloat16 g_yh[NB * NHW * KP];     // [b][p][f'] hi
__device__ __align__(16) __nv_bfloat16 g_yl[NB * NHW * KP];
__device__ float g_part[2][NB * NHW];       // partial logits per M-half
__device__ __align__(16) __nv_bfloat16 g_w5h[NC5 * KP];
__device__ __align__(16) __nv_bfloat16 g_w5l[NC5 * KP];
__device__ float g_sc[3 * NCS];
__device__ float g_sh[3 * NCS];
__device__ float g_sh5[NC5];

__device__ __forceinline__ float f4get(const float4& v, int i) {
    return i == 0 ? v.x : (i == 1 ? v.y : (i == 2 ? v.z : v.w));
}

__device__ __forceinline__ uint32_t smem_u32(const void* p) {
    uint32_t a;
    asm("{ .reg .u64 t; cvta.to.shared.u64 t, %1; cvt.u32.u64 %0, t; }" : "=r"(a) : "l"(p));
    return a;
}

__device__ __forceinline__ void bf16_split(float v, __nv_bfloat16& h, __nv_bfloat16& l) {
    h = __float2bfloat16_rn(v);
    l = __float2bfloat16_rn(v - __bfloat162float(h));
}

__device__ __forceinline__ uint32_t pk2(__nv_bfloat16 a, __nv_bfloat16 b) {
    __nv_bfloat162 t; t.x = a; t.y = b;
    return *reinterpret_cast<uint32_t*>(&t);
}

__device__ __forceinline__ void ldsm4(uint32_t& r0, uint32_t& r1, uint32_t& r2, uint32_t& r3,
                                      uint32_t addr) {
    asm volatile("ldmatrix.sync.aligned.m8n8.x4.shared.b16 {%0,%1,%2,%3}, [%4];"
                 : "=r"(r0), "=r"(r1), "=r"(r2), "=r"(r3) : "r"(addr));
}

#define MMA_BF16(ACC, A0, A1, A2, A3, B0, B1)                                        \
    asm volatile(                                                                    \
        "mma.sync.aligned.m16n8k16.row.col.f32.bf16.bf16.f32 "                       \
        "{%0,%1,%2,%3}, {%4,%5,%6,%7}, {%8,%9}, {%0,%1,%2,%3};"                      \
        : "+f"((ACC)[0]), "+f"((ACC)[1]), "+f"((ACC)[2]), "+f"((ACC)[3])             \
        : "r"(A0), "r"(A1), "r"(A2), "r"(A3), "r"(B0), "r"(B1))

// ---------------- K0: params, w5/convw/w4 split, y pad zero -------------------
__global__ void k0_prep(const float* __restrict__ w5,
                        const float* __restrict__ g5, const float* __restrict__ v5,
                        const float* __restrict__ b5, const float* __restrict__ bt5,
                        const float* __restrict__ m5, const float* __restrict__ w4,
                        const float* __restrict__ w1, const float* __restrict__ b1,
                        const float* __restrict__ g1, const float* __restrict__ bt1,
                        const float* __restrict__ m1, const float* __restrict__ v1,
                        const float* __restrict__ w2, const float* __restrict__ b2,
                        const float* __restrict__ g2, const float* __restrict__ bt2,
                        const float* __restrict__ m2, const float* __restrict__ v2,
                        const float* __restrict__ w3, const float* __restrict__ b3,
                        const float* __restrict__ g3, const float* __restrict__ bt3,
                        const float* __restrict__ m3, const float* __restrict__ v3)
{
    const int blk = blockIdx.x;
    const int tid = threadIdx.x;
    if (blk < NC5) {
        const int k = blk;
        float s5 = g5[k] * rsqrtf(v5[k] + EPSV);
        for (int f = tid; f < KP; f += 256) {
            float val;
            if (f < 512) val = w5[k * NCF + 1 + f] * s5;
            else if (f == 512) val = w5[k * NCF] * s5;
            else val = 0.f;
            __nv_bfloat16 h, l;
            bf16_split(val, h, l);
            g_w5h[k * KP + f] = h;
            g_w5l[k * KP + f] = l;
        }
    } else if (blk == NC5) {
        const int k = tid;
        float s5 = g5[k] * rsqrtf(v5[k] + EPSV);
        g_sh5[k] = (b5[k] - m5[k]) * s5 + bt5[k];
        if (k < 3 * NCS) {
            int cv = k / NCS, c = k % NCS;
            const float* bb = cv == 0 ? b1 : (cv == 1 ? b2 : b3);
            const float* gg = cv == 0 ? g1 : (cv == 1 ? g2 : g3);
            const float* bt = cv == 0 ? bt1 : (cv == 1 ? bt2 : bt3);
            const float* mm = cv == 0 ? m1 : (cv == 1 ? m2 : m3);
            const float* vv = cv == 0 ? v1 : (cv == 1 ? v2 : v3);
            float s = gg[c] * rsqrtf(vv[c] + EPSV);
            g_sc[k] = s;
            g_sh[k] = (bb[c] - mm[c]) * s + bt[c];
        }
    } else if (blk < NC5 + 1 + NB) {
        const int b = blk - NC5 - 1;
        char* baseh = (char*)(g_yh + (size_t)b * NHW * KP + 512);
        char* basel = (char*)(g_yl + (size_t)b * NHW * KP + 512);
        uint4 z = make_uint4(0u, 0u, 0u, 0u);
        for (int i = tid; i < NHW * 4; i += 256) {
            int p = i >> 2, q = i & 3;
            *reinterpret_cast<uint4*>(baseh + (size_t)p * (KP * 2) + q * 16) = z;
            *reinterpret_cast<uint4*>(basel + (size_t)p * (KP * 2) + q * 16) = z;
        }
    } else if (blk < NC5 + 1 + NB + 192) {
        const int row = blk - (NC5 + 1 + NB);
        const int cv = row >> 6, c = row & 63;
        const float* W  = cv == 0 ? w1 : (cv == 1 ? w2 : w3);
        const float* gg = cv == 0 ? g1 : (cv == 1 ? g2 : g3);
        const float* vv = cv == 0 ? v1 : (cv == 1 ? v2 : v3);
        float s = gg[c] * rsqrtf(vv[c] + EPSV);
        float val = W[c * NINP + tid] * s;
        __nv_bfloat16 h, l;
        bf16_split(val, h, l);
        g_wch[row * NINP + tid] = h;
        g_wcl[row * NINP + tid] = l;
    } else {
        const int row = blk - (NC5 + 1 + NB + 192);
        float4 v = *reinterpret_cast<const float4*>(w4 + (size_t)row * NHW + tid * 4);
        __nv_bfloat16 h0, l0, h1, l1, h2, l2, h3, l3;
        bf16_split(v.x, h0, l0); bf16_split(v.y, h1, l1);
        bf16_split(v.z, h2, l2); bf16_split(v.w, h3, l3);
        size_t base = (size_t)row * NHW + tid * 4;
        *reinterpret_cast<uint2*>(&g_w4h[base]) = make_uint2(pk2(h0, h1), pk2(h2, h3));
        *reinterpret_cast<uint2*>(&g_w4l[base]) = make_uint2(pk2(l0, l1), pk2(l2, l3));
    }
}

// ---------------- Kx: x [b][c][p] fp32 -> x^T [b][p][c] split bf16 ------------
__global__ void __launch_bounds__(256) k_x(const float* __restrict__ x)
{
    __shared__ float sm[64 * 68];
    const int p0 = blockIdx.x * 64;
    const int c0 = blockIdx.y * 64;
    const int b  = blockIdx.z;
    const int tid = threadIdx.x;

    const float* src = x + (size_t)b * NINP * NHW;
    for (int i = tid; i < 1024; i += 256) {
        int c = i >> 4, pq = i & 15;
        float4 v = *reinterpret_cast<const float4*>(src + (size_t)(c0 + c) * NHW + p0 + pq * 4);
        *reinterpret_cast<float4*>(sm + c * 68 + pq * 4) = v;
    }
    __syncthreads();

    const int p = tid >> 2;
    const int cs = (tid & 3) * 16;
    uint32_t hb[8], lb[8];
#pragma unroll
    for (int j2 = 0; j2 < 8; j2++) {
        __nv_bfloat16 h0, l0, h1, l1;
        bf16_split(sm[(cs + j2 * 2) * 68 + p], h0, l0);
        bf16_split(sm[(cs + j2 * 2 + 1) * 68 + p], h1, l1);
        hb[j2] = pk2(h0, h1);
        lb[j2] = pk2(l0, l1);
    }
    size_t base = ((size_t)(b * NHW + p0 + p)) * NINP + c0 + cs;
    *reinterpret_cast<uint4*>(&g_xth[base])     = make_uint4(hb[0], hb[1], hb[2], hb[3]);
    *reinterpret_cast<uint4*>(&g_xth[base + 8]) = make_uint4(hb[4], hb[5], hb[6], hb[7]);
    *reinterpret_cast<uint4*>(&g_xtl[base])     = make_uint4(lb[0], lb[1], lb[2], lb[3]);
    *reinterpret_cast<uint4*>(&g_xtl[base + 8]) = make_uint4(lb[4], lb[5], lb[6], lb[7]);
}

// ---------------- K1: conv GEMM C[192,128px] = Wc[192,256] @ xt^T -------------
// 12 warps (3M x 4N), stride 40, ldmatrix fragment loads
__global__ void __launch_bounds__(384) k1_mma(const float* __restrict__ dummy)
{
    extern __shared__ __nv_bfloat16 smb[];
    const int AH = 0, AL = 15360, BH = 30720, BL = 40960;
    const uint32_t smb_u = smem_u32(smb);
    const int tid = threadIdx.x;
    const int lane = tid & 31;
    const int wid = tid >> 5;
    const int mw3 = wid % 3;
    const int nw4 = wid / 3;
    const int b = blockIdx.y;
    const int p0 = blockIdx.x * 128;

    // ldmatrix lane address components
    const int lrA = lane & 15;               // A row within m16
    const int lkA = (lane >> 4) << 3;        // A k-half
    const int lnB = (lane & 7) + ((lane >> 4) << 3);   // B n within 16
    const int lkB = ((lane >> 3) & 1) << 3;  // B k-half

    float acc[4][4][4];
#pragma unroll
    for (int mi = 0; mi < 4; mi++)
#pragma unroll
        for (int ni = 0; ni < 4; ni++)
#pragma unroll
            for (int c = 0; c < 4; c++) acc[mi][ni][c] = 0.f;

#define K1_COPY(ch, buf) do {                                                         \
    for (int i = tid; i < 768; i += 384) {                                            \
        int row = i >> 2, q = i & 3;                                                  \
        uint32_t dh = smb_u + (uint32_t)(AH + (buf) * 7680 + row * 40 + q * 8) * 2u;  \
        uint32_t dl = smb_u + (uint32_t)(AL + (buf) * 7680 + row * 40 + q * 8) * 2u;  \
        size_t so = (size_t)row * NINP + (ch) * 32 + q * 8;                           \
        asm volatile("cp.async.ca.shared.global [%0], [%1], 16;" :: "r"(dh), "l"(g_wch + so)); \
        asm volatile("cp.async.ca.shared.global [%0], [%1], 16;" :: "r"(dl), "l"(g_wcl + so)); \
    }                                                                                 \
    for (int i = tid; i < 512; i += 384) {                                            \
        int row = i >> 2, q = i & 3;                                                  \
        uint32_t dh = smb_u + (uint32_t)(BH + (buf) * 5120 + row * 40 + q * 8) * 2u;  \
        uint32_t dl = smb_u + (uint32_t)(BL + (buf) * 5120 + row * 40 + q * 8) * 2u;  \
        size_t so = ((size_t)(b * NHW + p0 + row)) * NINP + (ch) * 32 + q * 8;        \
        asm volatile("cp.async.ca.shared.global [%0], [%1], 16;" :: "r"(dh), "l"(g_xth + so)); \
        asm volatile("cp.async.ca.shared.global [%0], [%1], 16;" :: "r"(dl), "l"(g_xtl + so)); \
    }                                                                                 \
    asm volatile("cp.async.commit_group;");                                           \
} while (0)

    K1_COPY(0, 0);
    for (int ch = 0; ch < 8; ch++) {
        if (ch < 7) {
            K1_COPY(ch + 1, (ch + 1) & 1);
            asm volatile("cp.async.wait_group 1;");
        } else {
            asm volatile("cp.async.wait_group 0;");
        }
        __syncthreads();
        const int buf = ch & 1;
        const uint32_t AHu = smb_u + (uint32_t)(AH + buf * 7680) * 2u;
        const uint32_t ALu = smb_u + (uint32_t)(AL + buf * 7680) * 2u;
        const uint32_t BHu = smb_u + (uint32_t)(BH + buf * 5120) * 2u;
        const uint32_t BLu = smb_u + (uint32_t)(BL + buf * 5120) * 2u;
#pragma unroll
        for (int ks = 0; ks < 2; ks++) {
            uint32_t ah[4][4], al[4][4], bh[4][2], bl[4][2];
            const uint32_t aoff = (uint32_t)(lrA * 40 + ks * 16 + lkA) * 2u;
            const uint32_t boff = (uint32_t)(lnB * 40 + ks * 16 + lkB) * 2u;
#pragma unroll
            for (int mi = 0; mi < 4; mi++) {
                uint32_t rbase = (uint32_t)((mw3 * 64 + mi * 16) * 40) * 2u;
                ldsm4(ah[mi][0], ah[mi][1], ah[mi][2], ah[mi][3], AHu + rbase + aoff);
                ldsm4(al[mi][0], al[mi][1], al[mi][2], al[mi][3], ALu + rbase + aoff);
            }
#pragma unroll
            for (int no = 0; no < 2; no++) {
                uint32_t nbase = (uint32_t)((nw4 * 32 + no * 16) * 40) * 2u;
                ldsm4(bh[2 * no][0], bh[2 * no][1], bh[2 * no + 1][0], bh[2 * no + 1][1],
                      BHu + nbase + boff);
                ldsm4(bl[2 * no][0], bl[2 * no][1], bl[2 * no + 1][0], bl[2 * no + 1][1],
                      BLu + nbase + boff);
            }
#pragma unroll
            for (int mi = 0; mi < 4; mi++)
#pragma unroll
                for (int ni = 0; ni < 4; ni++) {
                    MMA_BF16(acc[mi][ni], al[mi][0], al[mi][1], al[mi][2], al[mi][3],
                             bh[ni][0], bh[ni][1]);
                    MMA_BF16(acc[mi][ni], ah[mi][0], ah[mi][1], ah[mi][2], ah[mi][3],
                             bl[ni][0], bl[ni][1]);
                    MMA_BF16(acc[mi][ni], ah[mi][0], ah[mi][1], ah[mi][2], ah[mi][3],
                             bh[ni][0], bh[ni][1]);
                }
        }
        __syncthreads();
    }
#undef K1_COPY

    const int ar = lane >> 2;
    const int qq = lane & 3;
    if (mw3 < 2) {
        float* dst = (mw3 == 0 ? g_theta : g_phi) + (size_t)b * NCS * NHW;
#pragma unroll
        for (int mi = 0; mi < 4; mi++)
#pragma unroll
            for (int rh = 0; rh < 2; rh++) {
                int c = mi * 16 + ar + rh * 8;
                float sh = g_sh[mw3 * 64 + c];
#pragma unroll
                for (int ni = 0; ni < 4; ni++) {
                    int px = p0 + nw4 * 32 + ni * 8 + 2 * qq;
                    float2 o;
                    o.x = fmaxf(acc[mi][ni][rh * 2 + 0] + sh, 0.f);
                    o.y = fmaxf(acc[mi][ni][rh * 2 + 1] + sh, 0.f);
                    *reinterpret_cast<float2*>(dst + (size_t)c * NHW + px) = o;
                }
            }
    } else {
        float s_px[8];
#pragma unroll
        for (int ni = 0; ni < 4; ni++)
#pragma unroll
            for (int j = 0; j < 2; j++) {
                float s = 0.f;
#pragma unroll
                for (int mi = 0; mi < 4; mi++)
#pragma unroll
                    for (int rh = 0; rh < 2; rh++) {
                        int c = mi * 16 + ar + rh * 8;
                        s += fmaxf(acc[mi][ni][rh * 2 + j] + g_sh[128 + c], 0.f);
                    }
                s_px[ni * 2 + j] = s;
            }
#pragma unroll
        for (int v = 0; v < 8; v++) {
            s_px[v] += __shfl_xor_sync(0xffffffffu, s_px[v], 4);
            s_px[v] += __shfl_xor_sync(0xffffffffu, s_px[v], 8);
            s_px[v] += __shfl_xor_sync(0xffffffffu, s_px[v], 16);
        }
        if (lane < 4) {
#pragma unroll
            for (int ni = 0; ni < 4; ni++)
#pragma unroll
                for (int j = 0; j < 2; j++) {
                    int px = p0 + nw4 * 32 + ni * 8 + 2 * lane + j;
                    float val = s_px[ni * 2 + j] * (1.f / NCS);
                    __nv_bfloat16 h, l;
                    bf16_split(val, h, l);
                    size_t base = (size_t)(b * NHW + px) * KP + 512;
                    g_yh[base] = h;
                    g_yl[base] = l;
                }
        }
    }
}

// ---------------- K2t: transpose+split phi -> P^T ; split theta ---------------
__global__ void __launch_bounds__(256) k2t()
{
    __shared__ float sm[64 * 68];
    const int jt = blockIdx.x;
    const int task = blockIdx.y;
    const int b = blockIdx.z;
    const int tid = threadIdx.x;

    if (task == 0) {
        const float* src = g_phi + (size_t)b * NCS * NHW + jt * 4096;
        for (int i = tid; i < 1024; i += 256) {
            int r = i >> 4, cq = i & 15;
            float4 v = *reinterpret_cast<const float4*>(src + r * 64 + cq * 4);
            *reinterpret_cast<float4*>(sm + r * 68 + cq * 4) = v;
        }
        __syncthreads();
        const int jg = tid >> 6;
        const int c = tid & 63;
        uint32_t hb[8], lb[8];
#pragma unroll
        for (int k2i = 0; k2i < 8; k2i++) {
            __nv_bfloat16 h0, l0, h1, l1;
            bf16_split(sm[(jg * 16 + k2i * 2) * 68 + c], h0, l0);
            bf16_split(sm[(jg * 16 + k2i * 2 + 1) * 68 + c], h1, l1);
            hb[k2i] = pk2(h0, h1);
            lb[k2i] = pk2(l0, l1);
        }
        size_t base = (size_t)b * NCS * NHW + (size_t)c * NHW + jt * 64 + jg * 16;
        *reinterpret_cast<uint4*>(&g_pTh[base])     = make_uint4(hb[0], hb[1], hb[2], hb[3]);
        *reinterpret_cast<uint4*>(&g_pTh[base + 8]) = make_uint4(hb[4], hb[5], hb[6], hb[7]);
        *reinterpret_cast<uint4*>(&g_pTl[base])     = make_uint4(lb[0], lb[1], lb[2], lb[3]);
        *reinterpret_cast<uint4*>(&g_pTl[base + 8]) = make_uint4(lb[4], lb[5], lb[6], lb[7]);
    } else {
        const float* src = g_theta + (size_t)b * NCS * NHW + jt * 4096;
        size_t dbase = (size_t)b * NCS * NHW + jt * 4096;
        for (int i = tid; i < 1024; i += 256) {
            float4 v = *reinterpret_cast<const float4*>(src + i * 4);
            __nv_bfloat16 h0, l0, h1, l1, h2, l2, h3, l3;
            bf16_split(v.x, h0, l0); bf16_split(v.y, h1, l1);
            bf16_split(v.z, h2, l2); bf16_split(v.w, h3, l3);
            *reinterpret_cast<uint2*>(&g_thh[dbase + i * 4]) = make_uint2(pk2(h0, h1), pk2(h2, h3));
            *reinterpret_cast<uint2*>(&g_thl[dbase + i * 4]) = make_uint2(pk2(l0, l1), pk2(l2, l3));
        }
    }
}

// ---------------- K2: mma GEMM -> WP / TW^T (stride 72, ldmatrix) -------------
__global__ void __launch_bounds__(128) k2_mma()
{
    extern __shared__ __nv_bfloat16 smb[];
    const int AH = 0, AL = 9216, BH = 18432, BL = 27648;
    const uint32_t smb_u = smem_u32(smb);
    const int tid = threadIdx.x;
    const int lane = tid & 31;
    const int wid = tid >> 5;
    const int mw = wid & 1;
    const int nw = wid >> 1;
    const int o0 = blockIdx.x * 64;
    const int which = blockIdx.y;
    const int b = blockIdx.z;

    const int lrA = lane & 15;
    const int lkA = (lane >> 4) << 3;
    const int lnB = (lane & 7) + ((lane >> 4) << 3);
    const int lkB = ((lane >> 3) & 1) << 3;

    const __nv_bfloat16* Asrch = g_w4h + (size_t)o0 * NHW;
    const __nv_bfloat16* Asrcl = g_w4l + (size_t)o0 * NHW;
    const __nv_bfloat16* Bsrch = (which ? g_thh : g_pTh) + (size_t)b * NCS * NHW;
    const __nv_bfloat16* Bsrcl = (which ? g_thl : g_pTl) + (size_t)b * NCS * NHW;

    float acc[2][4][4];
#pragma unroll
    for (int mi = 0; mi < 2; mi++)
#pragma unroll
        for (int ni = 0; ni < 4; ni++)
#pragma unroll
            for (int c = 0; c < 4; c++) acc[mi][ni][c] = 0.f;

#define K2_COPY(ch, buf) do {                                                         \
    for (int i = tid; i < 512; i += 128) {                                            \
        int row = i >> 3, q = i & 7;                                                  \
        uint32_t dh = smb_u + (uint32_t)(AH + (buf) * 4608 + row * 72 + q * 8) * 2u;  \
        uint32_t dl = smb_u + (uint32_t)(AL + (buf) * 4608 + row * 72 + q * 8) * 2u;  \
        size_t so = (size_t)row * NHW + (ch) * 64 + q * 8;                            \
        asm volatile("cp.async.ca.shared.global [%0], [%1], 16;" :: "r"(dh), "l"(Asrch + so)); \
        asm volatile("cp.async.ca.shared.global [%0], [%1], 16;" :: "r"(dl), "l"(Asrcl + so)); \
    }                                                                                 \
    for (int i = tid; i < 512; i += 128) {                                            \
        int row = i >> 3, q = i & 7;                                                  \
        uint32_t dh = smb_u + (uint32_t)(BH + (buf) * 4608 + row * 72 + q * 8) * 2u;  \
        uint32_t dl = smb_u + (uint32_t)(BL + (buf) * 4608 + row * 72 + q * 8) * 2u;  \
        size_t so = (size_t)row * NHW + (ch) * 64 + q * 8;                            \
        asm volatile("cp.async.ca.shared.global [%0], [%1], 16;" :: "r"(dh), "l"(Bsrch + so)); \
        asm volatile("cp.async.ca.shared.global [%0], [%1], 16;" :: "r"(dl), "l"(Bsrcl + so)); \
    }                                                                                 \
    asm volatile("cp.async.commit_group;");                                           \
} while (0)

    K2_COPY(0, 0);
    for (int ch = 0; ch < 16; ch++) {
        if (ch < 15) {
            K2_COPY(ch + 1, (ch + 1) & 1);
            asm volatile("cp.async.wait_group 1;");
        } else {
            asm volatile("cp.async.wait_group 0;");
        }
        __syncthreads();
        const int buf = ch & 1;
        const uint32_t AHu = smb_u + (uint32_t)(AH + buf * 4608) * 2u;
        const uint32_t ALu = smb_u + (uint32_t)(AL + buf * 4608) * 2u;
        const uint32_t BHu = smb_u + (uint32_t)(BH + buf * 4608) * 2u;
        const uint32_t BLu = smb_u + (uint32_t)(BL + buf * 4608) * 2u;
#pragma unroll
        for (int ks = 0; ks < 4; ks++) {
            uint32_t ah[2][4], al[2][4], bh[4][2], bl[4][2];
            const uint32_t aoff = (uint32_t)(lrA * 72 + ks * 16 + lkA) * 2u;
            const uint32_t boff = (uint32_t)(lnB * 72 + ks * 16 + lkB) * 2u;
#pragma unroll
            for (int mi = 0; mi < 2; mi++) {
                uint32_t rbase = (uint32_t)((mw * 32 + mi * 16) * 72) * 2u;
                ldsm4(ah[mi][0], ah[mi][1], ah[mi][2], ah[mi][3], AHu + rbase + aoff);
                ldsm4(al[mi][0], al[mi][1], al[mi][2], al[mi][3], ALu + rbase + aoff);
            }
#pragma unroll
            for (int no = 0; no < 2; no++) {
                uint32_t nbase = (uint32_t)((nw * 32 + no * 16) * 72) * 2u;
                ldsm4(bh[2 * no][0], bh[2 * no][1], bh[2 * no + 1][0], bh[2 * no + 1][1],
                      BHu + nbase + boff);
                ldsm4(bl[2 * no][0], bl[2 * no][1], bl[2 * no + 1][0], bl[2 * no + 1][1],
                      BLu + nbase + boff);
            }
#pragma unroll
            for (int mi = 0; mi < 2; mi++)
#pragma unroll
                for (int ni = 0; ni < 4; ni++) {
                    MMA_BF16(acc[mi][ni], al[mi][0], al[mi][1], al[mi][2], al[mi][3],
                             bh[ni][0], bh[ni][1]);
                    MMA_BF16(acc[mi][ni], ah[mi][0], ah[mi][1], ah[mi][2], ah[mi][3],
                             bl[ni][0], bl[ni][1]);
                    MMA_BF16(acc[mi][ni], ah[mi][0], ah[mi][1], ah[mi][2], ah[mi][3],
                             bh[ni][0], bh[ni][1]);
                }
        }
        __syncthreads();
    }
#undef K2_COPY

    const int ar = lane >> 2;
    const int qq = lane & 3;
    __nv_bfloat16* WH = g_WPh + (size_t)b * 512 * NCS;
    __nv_bfloat16* WL = g_WPl + (size_t)b * 512 * NCS;
#pragma unroll
    for (int mi = 0; mi < 2; mi++)
#pragma unroll
        for (int rh = 0; rh < 2; rh++) {
            int row = which * 256 + o0 + mw * 32 + mi * 16 + ar + rh * 8;
#pragma unroll
            for (int ni = 0; ni < 4; ni++) {
                int col = nw * 32 + ni * 8 + 2 * qq;
                __nv_bfloat16 h0, l0, h1, l1;
                bf16_split(acc[mi][ni][rh * 2 + 0], h0, l0);
                bf16_split(acc[mi][ni][rh * 2 + 1], h1, l1);
                *reinterpret_cast<uint32_t*>(WH + (size_t)row * NCS + col) = pk2(h0, h1);
                *reinterpret_cast<uint32_t*>(WL + (size_t)row * NCS + col) = pk2(l0, l1);
            }
        }
}

// ---------------- K3: C[128px, 256f] = A[px, 64c] @ B[f, 64c]^T ---------------
__global__ void __launch_bounds__(512) k3_mma(const float* __restrict__ b4)
{
    extern __shared__ __nv_bfloat16 smb[];
    const int AH = 0, AL = 9216, BH = 18432, BL = 36864;
    const uint32_t smb_u = smem_u32(smb);
    const int tid = threadIdx.x;
    const int lane = tid & 31;
    const int wid = tid >> 5;
    const int mw = wid & 3;
    const int nw = wid >> 2;
    const int p0 = blockIdx.x * 128;
    const int which = blockIdx.y;
    const int b = blockIdx.z;

    const int lrA = lane & 15;
    const int lkA = (lane >> 4) << 3;
    const int lnB = (lane & 7) + ((lane >> 4) << 3);
    const int lkB = ((lane >> 3) & 1) << 3;

    {
        const __nv_bfloat16* srch = g_WPh + ((size_t)b * 512 + which * 256) * NCS;
        const __nv_bfloat16* srcl = g_WPl + ((size_t)b * 512 + which * 256) * NCS;
        for (int i = tid; i < 2048; i += 512) {
            int row = i >> 3, q = i & 7;
            uint32_t dh = smb_u + (uint32_t)(BH + row * 72 + q * 8) * 2u;
            uint32_t dl = smb_u + (uint32_t)(BL + row * 72 + q * 8) * 2u;
            size_t so = (size_t)row * NCS + q * 8;
            asm volatile("cp.async.ca.shared.global [%0], [%1], 16;" :: "r"(dh), "l"(srch + so));
            asm volatile("cp.async.ca.shared.global [%0], [%1], 16;" :: "r"(dl), "l"(srcl + so));
        }
        asm volatile("cp.async.commit_group;");
    }
    if (which == 0) {
        const float* th = g_theta + (size_t)b * NCS * NHW;
        for (int i = tid; i < 2048; i += 512) {
            int c = i >> 5, pq = i & 31;
            float4 v = *reinterpret_cast<const float4*>(th + (size_t)c * NHW + p0 + pq * 4);
#pragma unroll
            for (int j = 0; j < 4; j++) {
                __nv_bfloat16 h, l;
                bf16_split(f4get(v, j), h, l);
                smb[AH + (pq * 4 + j) * 72 + c] = h;
                smb[AL + (pq * 4 + j) * 72 + c] = l;
            }
        }
    } else {
        const float* ph = g_phi + (size_t)b * NCS * NHW;
        for (int i = tid; i < 2048; i += 512) {
            int p = i >> 4, cq = i & 15;
            float4 v = *reinterpret_cast<const float4*>(ph + (size_t)(p0 + p) * NCS + cq * 4);
            __nv_bfloat16 h0, l0, h1, l1, h2, l2, h3, l3;
            bf16_split(v.x, h0, l0); bf16_split(v.y, h1, l1);
            bf16_split(v.z, h2, l2); bf16_split(v.w, h3, l3);
            *reinterpret_cast<uint2*>(&smb[AH + p * 72 + cq * 4]) =
                make_uint2(pk2(h0, h1), pk2(h2, h3));
            *reinterpret_cast<uint2*>(&smb[AL + p * 72 + cq * 4]) =
                make_uint2(pk2(l0, l1), pk2(l2, l3));
        }
    }
    asm volatile("cp.async.wait_group 0;");
    __syncthreads();

    float acc[2][8][4];
#pragma unroll
    for (int mi = 0; mi < 2; mi++)
#pragma unroll
        for (int ni = 0; ni < 8; ni++)
#pragma unroll
            for (int c = 0; c < 4; c++) acc[mi][ni][c] = 0.f;

#pragma unroll
    for (int ks = 0; ks < 4; ks++) {
        uint32_t ah[2][4], al[2][4], bh[8][2], bl[8][2];
        const uint32_t aoff = (uint32_t)(lrA * 72 + ks * 16 + lkA) * 2u;
        const uint32_t boff = (uint32_t)(lnB * 72 + ks * 16 + lkB) * 2u;
#pragma unroll
        for (int mi = 0; mi < 2; mi++) {
            uint32_t rbase = (uint32_t)(AH * 2) + (uint32_t)((mw * 32 + mi * 16) * 72) * 2u;
            ldsm4(ah[mi][0], ah[mi][1], ah[mi][2], ah[mi][3], smb_u + rbase + aoff);
            uint32_t rbl = (uint32_t)(AL * 2) + (uint32_t)((mw * 32 + mi * 16) * 72) * 2u;
            ldsm4(al[mi][0], al[mi][1], al[mi][2], al[mi][3], smb_u + rbl + aoff);
        }
#pragma unroll
        for (int no = 0; no < 4; no++) {
            uint32_t nb = (uint32_t)((nw * 64 + no * 16) * 72) * 2u;
            ldsm4(bh[2 * no][0], bh[2 * no][1], bh[2 * no + 1][0], bh[2 * no + 1][1],
                  smb_u + (uint32_t)(BH * 2) + nb + boff);
            ldsm4(bl[2 * no][0], bl[2 * no][1], bl[2 * no + 1][0], bl[2 * no + 1][1],
                  smb_u + (uint32_t)(BL * 2) + nb + boff);
        }
#pragma unroll
        for (int ni = 0; ni < 8; ni++)
#pragma unroll
            for (int mi = 0; mi < 2; mi++) {
                MMA_BF16(acc[mi][ni], al[mi][0], al[mi][1], al[mi][2], al[mi][3],
                         bh[ni][0], bh[ni][1]);
                MMA_BF16(acc[mi][ni], ah[mi][0], ah[mi][1], ah[mi][2], ah[mi][3],
                         bl[ni][0], bl[ni][1]);
                MMA_BF16(acc[mi][ni], ah[mi][0], ah[mi][1], ah[mi][2], ah[mi][3],
                         bh[ni][0], bh[ni][1]);
            }
    }

    const int ar = lane >> 2;
    const int qq = lane & 3;
#pragma unroll
    for (int ni = 0; ni < 8; ni++) {
        int o = nw * 64 + ni * 8 + 2 * qq;
        float2 bb = *reinterpret_cast<const float2*>(b4 + o);
        int f0 = which * 256 + o;
#pragma unroll
        for (int mi = 0; mi < 2; mi++)
#pragma unroll
            for (int rh = 0; rh < 2; rh++) {
                int px = p0 + mw * 32 + mi * 16 + ar + rh * 8;
                float v0 = fmaxf(acc[mi][ni][rh * 2 + 0] + bb.x, 0.f);
                float v1 = fmaxf(acc[mi][ni][rh * 2 + 1] + bb.y, 0.f);
                __nv_bfloat16 h0, l0, h1, l1;
                bf16_split(v0, h0, l0);
                bf16_split(v1, h1, l1);
                size_t base = (size_t)(b * NHW + px) * KP + f0;
                *reinterpret_cast<uint32_t*>(&g_yh[base]) = pk2(h0, h1);
                *reinterpret_cast<uint32_t*>(&g_yl[base]) = pk2(l0, l1);
            }
    }
}

// ---------------- K4: quarter-tile split-bf16 GEMM + partial-logit epilogue ---
__global__ void __launch_bounds__(128, 3) k4_mma(const float* __restrict__ w6)
{
    extern __shared__ __nv_bfloat16 smb[];
    const int AH = 0, AL = 10240, BH = 20480, BL = 25600;
    const uint32_t smb_u = smem_u32(smb);
    const int tid = threadIdx.x;
    const int lane = tid & 31;
    const int wid = tid >> 5;
    const int mw = wid & 1;
    const int nw = wid >> 1;
    const int p0 = blockIdx.x * 64;
    const int mt = blockIdx.y;
    const int b = blockIdx.z;
    const size_t pixbase = (size_t)(b * NHW + p0);
    const size_t arowbase = (size_t)(mt * 128) * KP;

    const int lrA = lane & 15;
    const int lkA = (lane >> 4) << 3;
    const int lnB = (lane & 7) + ((lane >> 4) << 3);
    const int lkB = ((lane >> 3) & 1) << 3;

    float acc[4][4][4];
#pragma unroll
    for (int mi = 0; mi < 4; mi++)
#pragma unroll
        for (int ni = 0; ni < 4; ni++)
#pragma unroll
            for (int c = 0; c < 4; c++) acc[mi][ni][c] = 0.f;

#define COPY_CHUNK(ch, buf) do {                                                     \
    for (int i = tid; i < 512; i += 128) {                                           \
        int row = i >> 2, q = i & 3;                                                 \
        uint32_t dh = smb_u + (uint32_t)(AH + (buf) * 5120 + row * 40 + q * 8) * 2u; \
        uint32_t dl = smb_u + (uint32_t)(AL + (buf) * 5120 + row * 40 + q * 8) * 2u; \
        size_t so = arowbase + (size_t)row * KP + (ch) * 32 + q * 8;                 \
        asm volatile("cp.async.ca.shared.global [%0], [%1], 16;" :: "r"(dh), "l"(g_w5h + so)); \
        asm volatile("cp.async.ca.shared.global [%0], [%1], 16;" :: "r"(dl), "l"(g_w5l + so)); \
    }                                                                                \
    for (int i = tid; i < 256; i += 128) {                                           \
        int row = i >> 2, q = i & 3;                                                 \
        uint32_t dh = smb_u + (uint32_t)(BH + (buf) * 2560 + row * 40 + q * 8) * 2u; \
        uint32_t dl = smb_u + (uint32_t)(BL + (buf) * 2560 + row * 40 + q * 8) * 2u; \
        size_t so = (pixbase + row) * KP + (ch) * 32 + q * 8;                        \
        asm volatile("cp.async.ca.shared.global [%0], [%1], 16;" :: "r"(dh), "l"(g_yh + so)); \
        asm volatile("cp.async.ca.shared.global [%0], [%1], 16;" :: "r"(dl), "l"(g_yl + so)); \
    }                                                                                \
    asm volatile("cp.async.commit_group;");                                          \
} while (0)

    COPY_CHUNK(0, 0);
    for (int ch = 0; ch < NCHUNK; ch++) {
        if (ch < NCHUNK - 1) {
            COPY_CHUNK(ch + 1, (ch + 1) & 1);
            asm volatile("cp.async.wait_group 1;");
        } else {
            asm volatile("cp.async.wait_group 0;");
        }
        __syncthreads();
        const int buf = ch & 1;
        const uint32_t AHu = smb_u + (uint32_t)(AH + buf * 5120) * 2u;
        const uint32_t ALu = smb_u + (uint32_t)(AL + buf * 5120) * 2u;
        const uint32_t BHu = smb_u + (uint32_t)(BH + buf * 2560) * 2u;
        const uint32_t BLu = smb_u + (uint32_t)(BL + buf * 2560) * 2u;
#pragma unroll
        for (int ks = 0; ks < 2; ks++) {
            uint32_t ah[4][4], al[4][4], bh[4][2], bl[4][2];
            const uint32_t aoff = (uint32_t)(lrA * 40 + ks * 16 + lkA) * 2u;
            const uint32_t boff = (uint32_t)(lnB * 40 + ks * 16 + lkB) * 2u;
#pragma unroll
            for (int mi = 0; mi < 4; mi++) {
                uint32_t rbase = (uint32_t)((mw * 64 + mi * 16) * 40) * 2u;
                ldsm4(ah[mi][0], ah[mi][1], ah[mi][2], ah[mi][3], AHu + rbase + aoff);
                ldsm4(al[mi][0], al[mi][1], al[mi][2], al[mi][3], ALu + rbase + aoff);
            }
#pragma unroll
            for (int no = 0; no < 2; no++) {
                uint32_t nbase = (uint32_t)((nw * 32 + no * 16) * 40) * 2u;
                ldsm4(bh[2 * no][0], bh[2 * no][1], bh[2 * no + 1][0], bh[2 * no + 1][1],
                      BHu + nbase + boff);
                ldsm4(bl[2 * no][0], bl[2 * no][1], bl[2 * no + 1][0], bl[2 * no + 1][1],
                      BLu + nbase + boff);
            }
#pragma unroll
            for (int mi = 0; mi < 4; mi++)
#pragma unroll
                for (int ni = 0; ni < 4; ni++) {
                    MMA_BF16(acc[mi][ni], al[mi][0], al[mi][1], al[mi][2], al[mi][3],
                             bh[ni][0], bh[ni][1]);
                    MMA_BF16(acc[mi][ni], ah[mi][0], ah[mi][1], ah[mi][2], ah[mi][3],
                             bl[ni][0], bl[ni][1]);
                    MMA_BF16(acc[mi][ni], ah[mi][0], ah[mi][1], ah[mi][2], ah[mi][3],
                             bh[ni][0], bh[ni][1]);
                }
        }
        __syncthreads();
    }
#undef COPY_CHUNK

    float shv[8], wkv[8];
#pragma unroll
    for (int mi = 0; mi < 4; mi++)
#pragma unroll
        for (int rh = 0; rh < 2; rh++) {
            int m = mt * 128 + mw * 64 + mi * 16 + (lane >> 2) + rh * 8;
            shv[mi * 2 + rh] = g_sh5[m];
            wkv[mi * 2 + rh] = w6[m];
        }

    float* red = reinterpret_cast<float*>(smb);     // [64][17]
    const int slice = mw * 8 + (lane >> 2);
#pragma unroll
    for (int ni = 0; ni < 4; ni++)
#pragma unroll
        for (int j = 0; j < 2; j++) {
            float s = 0.f;
#pragma unroll
            for (int mi = 0; mi < 4; mi++)
#pragma unroll
                for (int rh = 0; rh < 2; rh++) {
                    float z = fmaxf(acc[mi][ni][rh * 2 + j] + shv[mi * 2 + rh], 0.f);
                    s = fmaf(z, wkv[mi * 2 + rh], s);
                }
            int col = nw * 32 + ni * 8 + 2 * (lane & 3) + j;
            red[col * 17 + slice] = s;
        }
    __syncthreads();
    if (tid < 64) {
        float t = 0.f;
#pragma unroll
        for (int r = 0; r < 16; r++) t += red[tid * 17 + r];
        g_part[mt][b * NHW + p0 + tid] = t;
    }
}

// ---------------- K5: a = sigmoid(part0+part1+b6); out = x * a ----------------
__global__ void __launch_bounds__(256) k5_scale(const float* __restrict__ x,
                                                const float* __restrict__ b6,
                                                float* __restrict__ out)
{
    int idx = blockIdx.x * 256 + threadIdx.x;
    float4 xv = reinterpret_cast<const float4*>(x)[idx];
    int pix4 = idx & 255;
    int b = idx >> 16;
    float4 t0 = reinterpret_cast<const float4*>(g_part[0])[b * 256 + pix4];
    float4 t1 = reinterpret_cast<const float4*>(g_part[1])[b * 256 + pix4];
    float bb = b6[0];
    float4 av;
    av.x = 1.f / (1.f + expf(-(t0.x + t1.x + bb)));
    av.y = 1.f / (1.f + expf(-(t0.y + t1.y + bb)));
    av.z = 1.f / (1.f + expf(-(t0.z + t1.z + bb)));
    av.w = 1.f / (1.f + expf(-(t0.w + t1.w + bb)));
    float4 o;
    o.x = xv.x * av.x; o.y = xv.y * av.y; o.z = xv.z * av.z; o.w = xv.w * av.w;
    reinterpret_cast<float4*>(out)[idx] = o;
}

// ---------------- launch ------------------------------------------------------
extern "C" void kernel_launch(void* const* d_in, const int* in_sizes, int n_in,
                              void* d_out, int out_size)
{
    const float* x   = (const float*)d_in[0];
    const float* w1  = (const float*)d_in[1];
    const float* b1  = (const float*)d_in[2];
    const float* g1  = (const float*)d_in[3];
    const float* bt1 = (const float*)d_in[4];
    const float* m1  = (const float*)d_in[5];
    const float* v1  = (const float*)d_in[6];
    const float* w2  = (const float*)d_in[7];
    const float* b2  = (const float*)d_in[8];
    const float* g2  = (const float*)d_in[9];
    const float* bt2 = (const float*)d_in[10];
    const float* m2  = (const float*)d_in[11];
    const float* v2  = (const float*)d_in[12];
    const float* w3  = (const float*)d_in[13];
    const float* b3  = (const float*)d_in[14];
    const float* g3  = (const float*)d_in[15];
    const float* bt3 = (const float*)d_in[16];
    const float* m3  = (const float*)d_in[17];
    const float* v3  = (const float*)d_in[18];
    const float* w4  = (const float*)d_in[19];
    const float* b4  = (const float*)d_in[20];
    const float* w5  = (const float*)d_in[21];
    const float* b5  = (const float*)d_in[22];
    const float* g5  = (const float*)d_in[23];
    const float* bt5 = (const float*)d_in[24];
    const float* m5  = (const float*)d_in[25];
    const float* v5  = (const float*)d_in[26];
    const float* w6  = (const float*)d_in[27];
    const float* b6  = (const float*)d_in[28];

    cudaFuncSetAttribute(k1_mma, cudaFuncAttributeMaxDynamicSharedMemorySize, 102400);
    cudaFuncSetAttribute(k2_mma, cudaFuncAttributeMaxDynamicSharedMemorySize, 73728);
    cudaFuncSetAttribute(k3_mma, cudaFuncAttributeMaxDynamicSharedMemorySize, 110592);
    cudaFuncSetAttribute(k4_mma, cudaFuncAttributeMaxDynamicSharedMemorySize, 61440);

    k0_prep<<<NC5 + 1 + NB + 192 + 256, 256>>>(w5, g5, v5, b5, bt5, m5, w4,
                                               w1, b1, g1, bt1, m1, v1,
                                               w2, b2, g2, bt2, m2, v2,
                                               w3, b3, g3, bt3, m3, v3);
    k_x<<<dim3(16, 4, NB), 256>>>(x);
    k1_mma<<<dim3(8, NB), 384, 102400>>>(nullptr);
    k2t<<<dim3(16, 2, NB), 256>>>();
    k2_mma<<<dim3(4, 2, NB), 128, 73728>>>();
    k3_mma<<<dim3(8, 2, NB), 512, 110592>>>(b4);
    k4_mma<<<dim3(16, 2, NB), 128, 61440>>>(w6);
    k5_scale<<<(NB * NINP * NHW / 4) / 256, 256>>>(x, b6, (float*)d_out);
}

// round 11
// speedup vs baseline: 2.1392x; 1.0407x over previous
#include <cuda_runtime.h>
#include <cuda_bf16.h>
#include <math.h>
#include <stdint.h>

#define NB 32
#define NINP 256
#define NHW 1024
#define NCS 64
#define NAOUT 256
#define NCF 513
#define NC5 256
#define EPSV 1e-5f
#define KP 544
#define NCHUNK 17

// ---------------- scratch ------------------------------------------------------
__device__ float g_theta[NB * NCS * NHW];   // [b][c][p] fp32
__device__ float g_phi[NB * NCS * NHW];     // [b][c][p] fp32
__device__ __align__(16) __nv_bfloat16 g_wch[192 * NINP];       // stacked folded conv w
__device__ __align__(16) __nv_bfloat16 g_wcl[192 * NINP];
__device__ __align__(16) __nv_bfloat16 g_w4h[NAOUT * NHW];      // w4 split [o][j]
__device__ __align__(16) __nv_bfloat16 g_w4l[NAOUT * NHW];
__device__ __align__(16) __nv_bfloat16 g_pTh[NB * NCS * NHW];   // P^T split [b][c][j]
__device__ __align__(16) __nv_bfloat16 g_pTl[NB * NCS * NHW];
__device__ __align__(16) __nv_bfloat16 g_thh[NB * NCS * NHW];   // theta split [b][c][p]
__device__ __align__(16) __nv_bfloat16 g_thl[NB * NCS * NHW];
__device__ __align__(16) __nv_bfloat16 g_WPh[NB * 512 * NCS];   // [b][row][c]; 0..255 WP, 256..511 TW^T
__device__ __align__(16) __nv_bfloat16 g_WPl[NB * 512 * NCS];
__device__ __align__(16) __nv_bfloat16 g_yh[NB * NHW * KP];     // [b][p][f'] hi
__device__ __align__(16) __nv_bfloat16 g_yl[NB * NHW * KP];
__device__ float g_part[2][NB * NHW];       // partial logits per M-half
__device__ __align__(16) __nv_bfloat16 g_w5h[NC5 * KP];
__device__ __align__(16) __nv_bfloat16 g_w5l[NC5 * KP];
__device__ float g_sc[3 * NCS];
__device__ float g_sh[3 * NCS];
__device__ float g_sh5[NC5];

__device__ __forceinline__ float f4get(const float4& v, int i) {
    return i == 0 ? v.x : (i == 1 ? v.y : (i == 2 ? v.z : v.w));
}

__device__ __forceinline__ uint32_t smem_u32(const void* p) {
    uint32_t a;
    asm("{ .reg .u64 t; cvta.to.shared.u64 t, %1; cvt.u32.u64 %0, t; }" : "=r"(a) : "l"(p));
    return a;
}

__device__ __forceinline__ void bf16_split(float v, __nv_bfloat16& h, __nv_bfloat16& l) {
    h = __float2bfloat16_rn(v);
    l = __float2bfloat16_rn(v - __bfloat162float(h));
}

__device__ __forceinline__ uint32_t pk2(__nv_bfloat16 a, __nv_bfloat16 b) {
    __nv_bfloat162 t; t.x = a; t.y = b;
    return *reinterpret_cast<uint32_t*>(&t);
}

__device__ __forceinline__ void ldsm4(uint32_t& r0, uint32_t& r1, uint32_t& r2, uint32_t& r3,
                                      uint32_t addr) {
    asm volatile("ldmatrix.sync.aligned.m8n8.x4.shared.b16 {%0,%1,%2,%3}, [%4];"
                 : "=r"(r0), "=r"(r1), "=r"(r2), "=r"(r3) : "r"(addr));
}

#define MMA_BF16(ACC, A0, A1, A2, A3, B0, B1)                                        \
    asm volatile(                                                                    \
        "mma.sync.aligned.m16n8k16.row.col.f32.bf16.bf16.f32 "                       \
        "{%0,%1,%2,%3}, {%4,%5,%6,%7}, {%8,%9}, {%0,%1,%2,%3};"                      \
        : "+f"((ACC)[0]), "+f"((ACC)[1]), "+f"((ACC)[2]), "+f"((ACC)[3])             \
        : "r"(A0), "r"(A1), "r"(A2), "r"(A3), "r"(B0), "r"(B1))

// ---------------- K0: params, w5/convw/w4 split, y pad zero -------------------
__global__ void k0_prep(const float* __restrict__ w5,
                        const float* __restrict__ g5, const float* __restrict__ v5,
                        const float* __restrict__ b5, const float* __restrict__ bt5,
                        const float* __restrict__ m5, const float* __restrict__ w4,
                        const float* __restrict__ w1, const float* __restrict__ b1,
                        const float* __restrict__ g1, const float* __restrict__ bt1,
                        const float* __restrict__ m1, const float* __restrict__ v1,
                        const float* __restrict__ w2, const float* __restrict__ b2,
                        const float* __restrict__ g2, const float* __restrict__ bt2,
                        const float* __restrict__ m2, const float* __restrict__ v2,
                        const float* __restrict__ w3, const float* __restrict__ b3,
                        const float* __restrict__ g3, const float* __restrict__ bt3,
                        const float* __restrict__ m3, const float* __restrict__ v3)
{
    const int blk = blockIdx.x;
    const int tid = threadIdx.x;
    if (blk < NC5) {
        const int k = blk;
        float s5 = g5[k] * rsqrtf(v5[k] + EPSV);
        for (int f = tid; f < KP; f += 256) {
            float val;
            if (f < 512) val = w5[k * NCF + 1 + f] * s5;
            else if (f == 512) val = w5[k * NCF] * s5;
            else val = 0.f;
            __nv_bfloat16 h, l;
            bf16_split(val, h, l);
            g_w5h[k * KP + f] = h;
            g_w5l[k * KP + f] = l;
        }
    } else if (blk == NC5) {
        const int k = tid;
        float s5 = g5[k] * rsqrtf(v5[k] + EPSV);
        g_sh5[k] = (b5[k] - m5[k]) * s5 + bt5[k];
        if (k < 3 * NCS) {
            int cv = k / NCS, c = k % NCS;
            const float* bb = cv == 0 ? b1 : (cv == 1 ? b2 : b3);
            const float* gg = cv == 0 ? g1 : (cv == 1 ? g2 : g3);
            const float* bt = cv == 0 ? bt1 : (cv == 1 ? bt2 : bt3);
            const float* mm = cv == 0 ? m1 : (cv == 1 ? m2 : m3);
            const float* vv = cv == 0 ? v1 : (cv == 1 ? v2 : v3);
            float s = gg[c] * rsqrtf(vv[c] + EPSV);
            g_sc[k] = s;
            g_sh[k] = (bb[c] - mm[c]) * s + bt[c];
        }
    } else if (blk < NC5 + 1 + NB) {
        const int b = blk - NC5 - 1;
        char* baseh = (char*)(g_yh + (size_t)b * NHW * KP + 512);
        char* basel = (char*)(g_yl + (size_t)b * NHW * KP + 512);
        uint4 z = make_uint4(0u, 0u, 0u, 0u);
        for (int i = tid; i < NHW * 4; i += 256) {
            int p = i >> 2, q = i & 3;
            *reinterpret_cast<uint4*>(baseh + (size_t)p * (KP * 2) + q * 16) = z;
            *reinterpret_cast<uint4*>(basel + (size_t)p * (KP * 2) + q * 16) = z;
        }
    } else if (blk < NC5 + 1 + NB + 192) {
        const int row = blk - (NC5 + 1 + NB);
        const int cv = row >> 6, c = row & 63;
        const float* W  = cv == 0 ? w1 : (cv == 1 ? w2 : w3);
        const float* gg = cv == 0 ? g1 : (cv == 1 ? g2 : g3);
        const float* vv = cv == 0 ? v1 : (cv == 1 ? v2 : v3);
        float s = gg[c] * rsqrtf(vv[c] + EPSV);
        float val = W[c * NINP + tid] * s;
        __nv_bfloat16 h, l;
        bf16_split(val, h, l);
        g_wch[row * NINP + tid] = h;
        g_wcl[row * NINP + tid] = l;
    } else {
        const int row = blk - (NC5 + 1 + NB + 192);
        float4 v = *reinterpret_cast<const float4*>(w4 + (size_t)row * NHW + tid * 4);
        __nv_bfloat16 h0, l0, h1, l1, h2, l2, h3, l3;
        bf16_split(v.x, h0, l0); bf16_split(v.y, h1, l1);
        bf16_split(v.z, h2, l2); bf16_split(v.w, h3, l3);
        size_t base = (size_t)row * NHW + tid * 4;
        *reinterpret_cast<uint2*>(&g_w4h[base]) = make_uint2(pk2(h0, h1), pk2(h2, h3));
        *reinterpret_cast<uint2*>(&g_w4l[base]) = make_uint2(pk2(l0, l1), pk2(l2, l3));
    }
}

// ---------------- K1: conv GEMM C[192,128px] = Wc[192,256] @ x^T --------------
// 12 warps (3M x 4N), stride 40, ldmatrix fragment loads.
// B tile built in-kernel from fp32 x (split + transpose at copy time).
__global__ void __launch_bounds__(384) k1_mma(const float* __restrict__ x)
{
    extern __shared__ __nv_bfloat16 smb[];
    const int AH = 0, AL = 15360, BH = 30720, BL = 40960;
    const uint32_t smb_u = smem_u32(smb);
    const int tid = threadIdx.x;
    const int lane = tid & 31;
    const int wid = tid >> 5;
    const int mw3 = wid % 3;
    const int nw4 = wid / 3;
    const int b = blockIdx.y;
    const int p0 = blockIdx.x * 128;
    const float* xb = x + (size_t)b * NINP * NHW;

    const int lrA = lane & 15;
    const int lkA = (lane >> 4) << 3;
    const int lnB = (lane & 7) + ((lane >> 4) << 3);
    const int lkB = ((lane >> 3) & 1) << 3;

    float acc[4][4][4];
#pragma unroll
    for (int mi = 0; mi < 4; mi++)
#pragma unroll
        for (int ni = 0; ni < 4; ni++)
#pragma unroll
            for (int c = 0; c < 4; c++) acc[mi][ni][c] = 0.f;

#define K1_COPYA(ch, buf) do {                                                        \
    for (int i = tid; i < 768; i += 384) {                                            \
        int row = i >> 2, q = i & 3;                                                  \
        uint32_t dh = smb_u + (uint32_t)(AH + (buf) * 7680 + row * 40 + q * 8) * 2u;  \
        uint32_t dl = smb_u + (uint32_t)(AL + (buf) * 7680 + row * 40 + q * 8) * 2u;  \
        size_t so = (size_t)row * NINP + (ch) * 32 + q * 8;                           \
        asm volatile("cp.async.ca.shared.global [%0], [%1], 16;" :: "r"(dh), "l"(g_wch + so)); \
        asm volatile("cp.async.ca.shared.global [%0], [%1], 16;" :: "r"(dl), "l"(g_wcl + so)); \
    }                                                                                 \
    asm volatile("cp.async.commit_group;");                                           \
} while (0)

// B build: x chunk [32c x 128px] fp32 -> split bf16 transposed [128px][40]
#define K1_BUILDB(ch, buf) do {                                                       \
    for (int i = tid; i < 512; i += 384) {                                            \
        int cpair = i & 15, pq = i >> 4;                                              \
        const float* src = xb + (size_t)((ch) * 32 + cpair * 2) * NHW + p0 + pq * 4;  \
        float4 v0 = *reinterpret_cast<const float4*>(src);                            \
        float4 v1 = *reinterpret_cast<const float4*>(src + NHW);                      \
        _Pragma("unroll")                                                             \
        for (int j = 0; j < 4; j++) {                                                 \
            __nv_bfloat16 h0, l0, h1, l1;                                             \
            bf16_split(f4get(v0, j), h0, l0);                                         \
            bf16_split(f4get(v1, j), h1, l1);                                         \
            int eo = (pq * 4 + j) * 40 + cpair * 2;                                   \
            *reinterpret_cast<uint32_t*>(smb + BH + (buf) * 5120 + eo) = pk2(h0, h1); \
            *reinterpret_cast<uint32_t*>(smb + BL + (buf) * 5120 + eo) = pk2(l0, l1); \
        }                                                                             \
    }                                                                                 \
} while (0)

    K1_COPYA(0, 0);
    K1_BUILDB(0, 0);
    for (int ch = 0; ch < 8; ch++) {
        if (ch < 7) {
            K1_COPYA(ch + 1, (ch + 1) & 1);
            K1_BUILDB(ch + 1, (ch + 1) & 1);
            asm volatile("cp.async.wait_group 1;");
        } else {
            asm volatile("cp.async.wait_group 0;");
        }
        __syncthreads();
        const int buf = ch & 1;
        const uint32_t AHu = smb_u + (uint32_t)(AH + buf * 7680) * 2u;
        const uint32_t ALu = smb_u + (uint32_t)(AL + buf * 7680) * 2u;
        const uint32_t BHu = smb_u + (uint32_t)(BH + buf * 5120) * 2u;
        const uint32_t BLu = smb_u + (uint32_t)(BL + buf * 5120) * 2u;
#pragma unroll
        for (int ks = 0; ks < 2; ks++) {
            uint32_t ah[4][4], al[4][4], bh[4][2], bl[4][2];
            const uint32_t aoff = (uint32_t)(lrA * 40 + ks * 16 + lkA) * 2u;
            const uint32_t boff = (uint32_t)(lnB * 40 + ks * 16 + lkB) * 2u;
#pragma unroll
            for (int mi = 0; mi < 4; mi++) {
                uint32_t rbase = (uint32_t)((mw3 * 64 + mi * 16) * 40) * 2u;
                ldsm4(ah[mi][0], ah[mi][1], ah[mi][2], ah[mi][3], AHu + rbase + aoff);
                ldsm4(al[mi][0], al[mi][1], al[mi][2], al[mi][3], ALu + rbase + aoff);
            }
#pragma unroll
            for (int no = 0; no < 2; no++) {
                uint32_t nbase = (uint32_t)((nw4 * 32 + no * 16) * 40) * 2u;
                ldsm4(bh[2 * no][0], bh[2 * no][1], bh[2 * no + 1][0], bh[2 * no + 1][1],
                      BHu + nbase + boff);
                ldsm4(bl[2 * no][0], bl[2 * no][1], bl[2 * no + 1][0], bl[2 * no + 1][1],
                      BLu + nbase + boff);
            }
#pragma unroll
            for (int mi = 0; mi < 4; mi++)
#pragma unroll
                for (int ni = 0; ni < 4; ni++) {
                    MMA_BF16(acc[mi][ni], al[mi][0], al[mi][1], al[mi][2], al[mi][3],
                             bh[ni][0], bh[ni][1]);
                    MMA_BF16(acc[mi][ni], ah[mi][0], ah[mi][1], ah[mi][2], ah[mi][3],
                             bl[ni][0], bl[ni][1]);
                    MMA_BF16(acc[mi][ni], ah[mi][0], ah[mi][1], ah[mi][2], ah[mi][3],
                             bh[ni][0], bh[ni][1]);
                }
        }
        __syncthreads();
    }
#undef K1_COPYA
#undef K1_BUILDB

    const int ar = lane >> 2;
    const int qq = lane & 3;
    if (mw3 < 2) {
        float* dst = (mw3 == 0 ? g_theta : g_phi) + (size_t)b * NCS * NHW;
#pragma unroll
        for (int mi = 0; mi < 4; mi++)
#pragma unroll
            for (int rh = 0; rh < 2; rh++) {
                int c = mi * 16 + ar + rh * 8;
                float sh = g_sh[mw3 * 64 + c];
#pragma unroll
                for (int ni = 0; ni < 4; ni++) {
                    int px = p0 + nw4 * 32 + ni * 8 + 2 * qq;
                    float2 o;
                    o.x = fmaxf(acc[mi][ni][rh * 2 + 0] + sh, 0.f);
                    o.y = fmaxf(acc[mi][ni][rh * 2 + 1] + sh, 0.f);
                    *reinterpret_cast<float2*>(dst + (size_t)c * NHW + px) = o;
                    if (mw3 == 0) {
                        // theta split for k2 (layout [c][p], p-contig)
                        __nv_bfloat16 h0, l0, h1, l1;
                        bf16_split(o.x, h0, l0);
                        bf16_split(o.y, h1, l1);
                        size_t tb = (size_t)b * NCS * NHW + (size_t)c * NHW + px;
                        *reinterpret_cast<uint32_t*>(&g_thh[tb]) = pk2(h0, h1);
                        *reinterpret_cast<uint32_t*>(&g_thl[tb]) = pk2(l0, l1);
                    }
                }
            }
    } else {
        float s_px[8];
#pragma unroll
        for (int ni = 0; ni < 4; ni++)
#pragma unroll
            for (int j = 0; j < 2; j++) {
                float s = 0.f;
#pragma unroll
                for (int mi = 0; mi < 4; mi++)
#pragma unroll
                    for (int rh = 0; rh < 2; rh++) {
                        int c = mi * 16 + ar + rh * 8;
                        s += fmaxf(acc[mi][ni][rh * 2 + j] + g_sh[128 + c], 0.f);
                    }
                s_px[ni * 2 + j] = s;
            }
#pragma unroll
        for (int v = 0; v < 8; v++) {
            s_px[v] += __shfl_xor_sync(0xffffffffu, s_px[v], 4);
            s_px[v] += __shfl_xor_sync(0xffffffffu, s_px[v], 8);
            s_px[v] += __shfl_xor_sync(0xffffffffu, s_px[v], 16);
        }
        if (lane < 4) {
#pragma unroll
            for (int ni = 0; ni < 4; ni++)
#pragma unroll
                for (int j = 0; j < 2; j++) {
                    int px = p0 + nw4 * 32 + ni * 8 + 2 * lane + j;
                    float val = s_px[ni * 2 + j] * (1.f / NCS);
                    __nv_bfloat16 h, l;
                    bf16_split(val, h, l);
                    size_t base = (size_t)(b * NHW + px) * KP + 512;
                    g_yh[base] = h;
                    g_yl[base] = l;
                }
        }
    }
}

// ---------------- K2t: transpose+split phi -> P^T (theta split now in K1) -----
__global__ void __launch_bounds__(256) k2t()
{
    __shared__ float sm[64 * 68];
    const int jt = blockIdx.x;
    const int b = blockIdx.y;
    const int tid = threadIdx.x;

    const float* src = g_phi + (size_t)b * NCS * NHW + jt * 4096;
    for (int i = tid; i < 1024; i += 256) {
        int r = i >> 4, cq = i & 15;
        float4 v = *reinterpret_cast<const float4*>(src + r * 64 + cq * 4);
        *reinterpret_cast<float4*>(sm + r * 68 + cq * 4) = v;
    }
    __syncthreads();
    const int jg = tid >> 6;
    const int c = tid & 63;
    uint32_t hb[8], lb[8];
#pragma unroll
    for (int k2i = 0; k2i < 8; k2i++) {
        __nv_bfloat16 h0, l0, h1, l1;
        bf16_split(sm[(jg * 16 + k2i * 2) * 68 + c], h0, l0);
        bf16_split(sm[(jg * 16 + k2i * 2 + 1) * 68 + c], h1, l1);
        hb[k2i] = pk2(h0, h1);
        lb[k2i] = pk2(l0, l1);
    }
    size_t base = (size_t)b * NCS * NHW + (size_t)c * NHW + jt * 64 + jg * 16;
    *reinterpret_cast<uint4*>(&g_pTh[base])     = make_uint4(hb[0], hb[1], hb[2], hb[3]);
    *reinterpret_cast<uint4*>(&g_pTh[base + 8]) = make_uint4(hb[4], hb[5], hb[6], hb[7]);
    *reinterpret_cast<uint4*>(&g_pTl[base])     = make_uint4(lb[0], lb[1], lb[2], lb[3]);
    *reinterpret_cast<uint4*>(&g_pTl[base + 8]) = make_uint4(lb[4], lb[5], lb[6], lb[7]);
}

// ---------------- K2: mma GEMM -> WP / TW^T (stride 72, ldmatrix) -------------
__global__ void __launch_bounds__(128) k2_mma()
{
    extern __shared__ __nv_bfloat16 smb[];
    const int AH = 0, AL = 9216, BH = 18432, BL = 27648;
    const uint32_t smb_u = smem_u32(smb);
    const int tid = threadIdx.x;
    const int lane = tid & 31;
    const int wid = tid >> 5;
    const int mw = wid & 1;
    const int nw = wid >> 1;
    const int o0 = blockIdx.x * 64;
    const int which = blockIdx.y;
    const int b = blockIdx.z;

    const int lrA = lane & 15;
    const int lkA = (lane >> 4) << 3;
    const int lnB = (lane & 7) + ((lane >> 4) << 3);
    const int lkB = ((lane >> 3) & 1) << 3;

    const __nv_bfloat16* Asrch = g_w4h + (size_t)o0 * NHW;
    const __nv_bfloat16* Asrcl = g_w4l + (size_t)o0 * NHW;
    const __nv_bfloat16* Bsrch = (which ? g_thh : g_pTh) + (size_t)b * NCS * NHW;
    const __nv_bfloat16* Bsrcl = (which ? g_thl : g_pTl) + (size_t)b * NCS * NHW;

    float acc[2][4][4];
#pragma unroll
    for (int mi = 0; mi < 2; mi++)
#pragma unroll
        for (int ni = 0; ni < 4; ni++)
#pragma unroll
            for (int c = 0; c < 4; c++) acc[mi][ni][c] = 0.f;

#define K2_COPY(ch, buf) do {                                                         \
    for (int i = tid; i < 512; i += 128) {                                            \
        int row = i >> 3, q = i & 7;                                                  \
        uint32_t dh = smb_u + (uint32_t)(AH + (buf) * 4608 + row * 72 + q * 8) * 2u;  \
        uint32_t dl = smb_u + (uint32_t)(AL + (buf) * 4608 + row * 72 + q * 8) * 2u;  \
        size_t so = (size_t)row * NHW + (ch) * 64 + q * 8;                            \
        asm volatile("cp.async.ca.shared.global [%0], [%1], 16;" :: "r"(dh), "l"(Asrch + so)); \
        asm volatile("cp.async.ca.shared.global [%0], [%1], 16;" :: "r"(dl), "l"(Asrcl + so)); \
    }                                                                                 \
    for (int i = tid; i < 512; i += 128) {                                            \
        int row = i >> 3, q = i & 7;                                                  \
        uint32_t dh = smb_u + (uint32_t)(BH + (buf) * 4608 + row * 72 + q * 8) * 2u;  \
        uint32_t dl = smb_u + (uint32_t)(BL + (buf) * 4608 + row * 72 + q * 8) * 2u;  \
        size_t so = (size_t)row * NHW + (ch) * 64 + q * 8;                            \
        asm volatile("cp.async.ca.shared.global [%0], [%1], 16;" :: "r"(dh), "l"(Bsrch + so)); \
        asm volatile("cp.async.ca.shared.global [%0], [%1], 16;" :: "r"(dl), "l"(Bsrcl + so)); \
    }                                                                                 \
    asm volatile("cp.async.commit_group;");                                           \
} while (0)

    K2_COPY(0, 0);
    for (int ch = 0; ch < 16; ch++) {
        if (ch < 15) {
            K2_COPY(ch + 1, (ch + 1) & 1);
            asm volatile("cp.async.wait_group 1;");
        } else {
            asm volatile("cp.async.wait_group 0;");
        }
        __syncthreads();
        const int buf = ch & 1;
        const uint32_t AHu = smb_u + (uint32_t)(AH + buf * 4608) * 2u;
        const uint32_t ALu = smb_u + (uint32_t)(AL + buf * 4608) * 2u;
        const uint32_t BHu = smb_u + (uint32_t)(BH + buf * 4608) * 2u;
        const uint32_t BLu = smb_u + (uint32_t)(BL + buf * 4608) * 2u;
#pragma unroll
        for (int ks = 0; ks < 4; ks++) {
            uint32_t ah[2][4], al[2][4], bh[4][2], bl[4][2];
            const uint32_t aoff = (uint32_t)(lrA * 72 + ks * 16 + lkA) * 2u;
            const uint32_t boff = (uint32_t)(lnB * 72 + ks * 16 + lkB) * 2u;
#pragma unroll
            for (int mi = 0; mi < 2; mi++) {
                uint32_t rbase = (uint32_t)((mw * 32 + mi * 16) * 72) * 2u;
                ldsm4(ah[mi][0], ah[mi][1], ah[mi][2], ah[mi][3], AHu + rbase + aoff);
                ldsm4(al[mi][0], al[mi][1], al[mi][2], al[mi][3], ALu + rbase + aoff);
            }
#pragma unroll
            for (int no = 0; no < 2; no++) {
                uint32_t nbase = (uint32_t)((nw * 32 + no * 16) * 72) * 2u;
                ldsm4(bh[2 * no][0], bh[2 * no][1], bh[2 * no + 1][0], bh[2 * no + 1][1],
                      BHu + nbase + boff);
                ldsm4(bl[2 * no][0], bl[2 * no][1], bl[2 * no + 1][0], bl[2 * no + 1][1],
                      BLu + nbase + boff);
            }
#pragma unroll
            for (int mi = 0; mi < 2; mi++)
#pragma unroll
                for (int ni = 0; ni < 4; ni++) {
                    MMA_BF16(acc[mi][ni], al[mi][0], al[mi][1], al[mi][2], al[mi][3],
                             bh[ni][0], bh[ni][1]);
                    MMA_BF16(acc[mi][ni], ah[mi][0], ah[mi][1], ah[mi][2], ah[mi][3],
                             bl[ni][0], bl[ni][1]);
                    MMA_BF16(acc[mi][ni], ah[mi][0], ah[mi][1], ah[mi][2], ah[mi][3],
                             bh[ni][0], bh[ni][1]);
                }
        }
        __syncthreads();
    }
#undef K2_COPY

    const int ar = lane >> 2;
    const int qq = lane & 3;
    __nv_bfloat16* WH = g_WPh + (size_t)b * 512 * NCS;
    __nv_bfloat16* WL = g_WPl + (size_t)b * 512 * NCS;
#pragma unroll
    for (int mi = 0; mi < 2; mi++)
#pragma unroll
        for (int rh = 0; rh < 2; rh++) {
            int row = which * 256 + o0 + mw * 32 + mi * 16 + ar + rh * 8;
#pragma unroll
            for (int ni = 0; ni < 4; ni++) {
                int col = nw * 32 + ni * 8 + 2 * qq;
                __nv_bfloat16 h0, l0, h1, l1;
                bf16_split(acc[mi][ni][rh * 2 + 0], h0, l0);
                bf16_split(acc[mi][ni][rh * 2 + 1], h1, l1);
                *reinterpret_cast<uint32_t*>(WH + (size_t)row * NCS + col) = pk2(h0, h1);
                *reinterpret_cast<uint32_t*>(WL + (size_t)row * NCS + col) = pk2(l0, l1);
            }
        }
}

// ---------------- K3: quarter tile C[64px, 128f] = A[px,64c] @ B[f,64c]^T -----
// grid (16 pt of 64px, 4 = 2 nt x 2 which, 32 b), 128 thr = 4 warps (2M x 2N)
// smem bf16: Ah[4608] Al[4608] Bh[9216] Bl[9216] = 27648 el = 55296 B (stride 72)
__global__ void __launch_bounds__(128) k3_mma(const float* __restrict__ b4)
{
    extern __shared__ __nv_bfloat16 smb[];
    const int AH = 0, AL = 4608, BH = 9216, BL = 18432;
    const uint32_t smb_u = smem_u32(smb);
    const int tid = threadIdx.x;
    const int lane = tid & 31;
    const int wid = tid >> 5;
    const int mw = wid & 1;             // px: mw*32
    const int nwf = wid >> 1;           // f: nwf*64
    const int p0 = blockIdx.x * 64;
    const int by = blockIdx.y;
    const int which = by >> 1;
    const int nt = by & 1;
    const int b = blockIdx.z;

    const int lrA = lane & 15;
    const int lkA = (lane >> 4) << 3;
    const int lnB = (lane & 7) + ((lane >> 4) << 3);
    const int lkB = ((lane >> 3) & 1) << 3;

    {
        const __nv_bfloat16* srch = g_WPh + ((size_t)b * 512 + which * 256 + nt * 128) * NCS;
        const __nv_bfloat16* srcl = g_WPl + ((size_t)b * 512 + which * 256 + nt * 128) * NCS;
        for (int i = tid; i < 1024; i += 128) {
            int row = i >> 3, q = i & 7;
            uint32_t dh = smb_u + (uint32_t)(BH + row * 72 + q * 8) * 2u;
            uint32_t dl = smb_u + (uint32_t)(BL + row * 72 + q * 8) * 2u;
            size_t so = (size_t)row * NCS + q * 8;
            asm volatile("cp.async.ca.shared.global [%0], [%1], 16;" :: "r"(dh), "l"(srch + so));
            asm volatile("cp.async.ca.shared.global [%0], [%1], 16;" :: "r"(dl), "l"(srcl + so));
        }
        asm volatile("cp.async.commit_group;");
    }
    if (which == 0) {
        // theta [c][p] fp32, transpose into A[px][c]; sector-friendly mapping
        const float* th = g_theta + (size_t)b * NCS * NHW;
        for (int i = tid; i < 1024; i += 128) {
            int c = (i & 15) + ((i >> 8) << 4);     // 0..63
            int pq = (i >> 4) & 15;                 // 0..15 (float4 over 64 px)
            float4 v = *reinterpret_cast<const float4*>(th + (size_t)c * NHW + p0 + pq * 4);
#pragma unroll
            for (int j = 0; j < 4; j++) {
                __nv_bfloat16 h, l;
                bf16_split(f4get(v, j), h, l);
                smb[AH + (pq * 4 + j) * 72 + c] = h;
                smb[AL + (pq * 4 + j) * 72 + c] = l;
            }
        }
    } else {
        const float* ph = g_phi + (size_t)b * NCS * NHW;
        for (int i = tid; i < 1024; i += 128) {
            int p = i >> 4, cq = i & 15;
            float4 v = *reinterpret_cast<const float4*>(ph + (size_t)(p0 + p) * NCS + cq * 4);
            __nv_bfloat16 h0, l0, h1, l1, h2, l2, h3, l3;
            bf16_split(v.x, h0, l0); bf16_split(v.y, h1, l1);
            bf16_split(v.z, h2, l2); bf16_split(v.w, h3, l3);
            *reinterpret_cast<uint2*>(&smb[AH + p * 72 + cq * 4]) =
                make_uint2(pk2(h0, h1), pk2(h2, h3));
            *reinterpret_cast<uint2*>(&smb[AL + p * 72 + cq * 4]) =
                make_uint2(pk2(l0, l1), pk2(l2, l3));
        }
    }
    asm volatile("cp.async.wait_group 0;");
    __syncthreads();

    float acc[2][8][4];
#pragma unroll
    for (int mi = 0; mi < 2; mi++)
#pragma unroll
        for (int ni = 0; ni < 8; ni++)
#pragma unroll
            for (int c = 0; c < 4; c++) acc[mi][ni][c] = 0.f;

#pragma unroll
    for (int ks = 0; ks < 4; ks++) {
        uint32_t ah[2][4], al[2][4], bh[8][2], bl[8][2];
        const uint32_t aoff = (uint32_t)(lrA * 72 + ks * 16 + lkA) * 2u;
        const uint32_t boff = (uint32_t)(lnB * 72 + ks * 16 + lkB) * 2u;
#pragma unroll
        for (int mi = 0; mi < 2; mi++) {
            uint32_t rb = (uint32_t)((mw * 32 + mi * 16) * 72) * 2u;
            ldsm4(ah[mi][0], ah[mi][1], ah[mi][2], ah[mi][3],
                  smb_u + (uint32_t)(AH * 2) + rb + aoff);
            ldsm4(al[mi][0], al[mi][1], al[mi][2], al[mi][3],
                  smb_u + (uint32_t)(AL * 2) + rb + aoff);
        }
#pragma unroll
        for (int no = 0; no < 4; no++) {
            uint32_t nb = (uint32_t)((nwf * 64 + no * 16) * 72) * 2u;
            ldsm4(bh[2 * no][0], bh[2 * no][1], bh[2 * no + 1][0], bh[2 * no + 1][1],
                  smb_u + (uint32_t)(BH * 2) + nb + boff);
            ldsm4(bl[2 * no][0], bl[2 * no][1], bl[2 * no + 1][0], bl[2 * no + 1][1],
                  smb_u + (uint32_t)(BL * 2) + nb + boff);
        }
#pragma unroll
        for (int ni = 0; ni < 8; ni++)
#pragma unroll
            for (int mi = 0; mi < 2; mi++) {
                MMA_BF16(acc[mi][ni], al[mi][0], al[mi][1], al[mi][2], al[mi][3],
                         bh[ni][0], bh[ni][1]);
                MMA_BF16(acc[mi][ni], ah[mi][0], ah[mi][1], ah[mi][2], ah[mi][3],
                         bl[ni][0], bl[ni][1]);
                MMA_BF16(acc[mi][ni], ah[mi][0], ah[mi][1], ah[mi][2], ah[mi][3],
                         bh[ni][0], bh[ni][1]);
            }
    }

    const int ar = lane >> 2;
    const int qq = lane & 3;
#pragma unroll
    for (int ni = 0; ni < 8; ni++) {
        int o = nt * 128 + nwf * 64 + ni * 8 + 2 * qq;
        float2 bb = *reinterpret_cast<const float2*>(b4 + o);
        int f0 = which * 256 + o;
#pragma unroll
        for (int mi = 0; mi < 2; mi++)
#pragma unroll
            for (int rh = 0; rh < 2; rh++) {
                int px = p0 + mw * 32 + mi * 16 + ar + rh * 8;
                float v0 = fmaxf(acc[mi][ni][rh * 2 + 0] + bb.x, 0.f);
                float v1 = fmaxf(acc[mi][ni][rh * 2 + 1] + bb.y, 0.f);
                __nv_bfloat16 h0, l0, h1, l1;
                bf16_split(v0, h0, l0);
                bf16_split(v1, h1, l1);
                size_t base = (size_t)(b * NHW + px) * KP + f0;
                *reinterpret_cast<uint32_t*>(&g_yh[base]) = pk2(h0, h1);
                *reinterpret_cast<uint32_t*>(&g_yl[base]) = pk2(l0, l1);
            }
    }
}

// ---------------- K4: quarter-tile split-bf16 GEMM + partial-logit epilogue ---
__global__ void __launch_bounds__(128, 3) k4_mma(const float* __restrict__ w6)
{
    extern __shared__ __nv_bfloat16 smb[];
    const int AH = 0, AL = 10240, BH = 20480, BL = 25600;
    const uint32_t smb_u = smem_u32(smb);
    const int tid = threadIdx.x;
    const int lane = tid & 31;
    const int wid = tid >> 5;
    const int mw = wid & 1;
    const int nw = wid >> 1;
    const int p0 = blockIdx.x * 64;
    const int mt = blockIdx.y;
    const int b = blockIdx.z;
    const size_t pixbase = (size_t)(b * NHW + p0);
    const size_t arowbase = (size_t)(mt * 128) * KP;

    const int lrA = lane & 15;
    const int lkA = (lane >> 4) << 3;
    const int lnB = (lane & 7) + ((lane >> 4) << 3);
    const int lkB = ((lane >> 3) & 1) << 3;

    float acc[4][4][4];
#pragma unroll
    for (int mi = 0; mi < 4; mi++)
#pragma unroll
        for (int ni = 0; ni < 4; ni++)
#pragma unroll
            for (int c = 0; c < 4; c++) acc[mi][ni][c] = 0.f;

#define COPY_CHUNK(ch, buf) do {                                                     \
    for (int i = tid; i < 512; i += 128) {                                           \
        int row = i >> 2, q = i & 3;                                                 \
        uint32_t dh = smb_u + (uint32_t)(AH + (buf) * 5120 + row * 40 + q * 8) * 2u; \
        uint32_t dl = smb_u + (uint32_t)(AL + (buf) * 5120 + row * 40 + q * 8) * 2u; \
        size_t so = arowbase + (size_t)row * KP + (ch) * 32 + q * 8;                 \
        asm volatile("cp.async.ca.shared.global [%0], [%1], 16;" :: "r"(dh), "l"(g_w5h + so)); \
        asm volatile("cp.async.ca.shared.global [%0], [%1], 16;" :: "r"(dl), "l"(g_w5l + so)); \
    }                                                                                \
    for (int i = tid; i < 256; i += 128) {                                           \
        int row = i >> 2, q = i & 3;                                                 \
        uint32_t dh = smb_u + (uint32_t)(BH + (buf) * 2560 + row * 40 + q * 8) * 2u; \
        uint32_t dl = smb_u + (uint32_t)(BL + (buf) * 2560 + row * 40 + q * 8) * 2u; \
        size_t so = (pixbase + row) * KP + (ch) * 32 + q * 8;                        \
        asm volatile("cp.async.ca.shared.global [%0], [%1], 16;" :: "r"(dh), "l"(g_yh + so)); \
        asm volatile("cp.async.ca.shared.global [%0], [%1], 16;" :: "r"(dl), "l"(g_yl + so)); \
    }                                                                                \
    asm volatile("cp.async.commit_group;");                                          \
} while (0)

    COPY_CHUNK(0, 0);
    for (int ch = 0; ch < NCHUNK; ch++) {
        if (ch < NCHUNK - 1) {
            COPY_CHUNK(ch + 1, (ch + 1) & 1);
            asm volatile("cp.async.wait_group 1;");
        } else {
            asm volatile("cp.async.wait_group 0;");
        }
        __syncthreads();
        const int buf = ch & 1;
        const uint32_t AHu = smb_u + (uint32_t)(AH + buf * 5120) * 2u;
        const uint32_t ALu = smb_u + (uint32_t)(AL + buf * 5120) * 2u;
        const uint32_t BHu = smb_u + (uint32_t)(BH + buf * 2560) * 2u;
        const uint32_t BLu = smb_u + (uint32_t)(BL + buf * 2560) * 2u;
#pragma unroll
        for (int ks = 0; ks < 2; ks++) {
            uint32_t ah[4][4], al[4][4], bh[4][2], bl[4][2];
            const uint32_t aoff = (uint32_t)(lrA * 40 + ks * 16 + lkA) * 2u;
            const uint32_t boff = (uint32_t)(lnB * 40 + ks * 16 + lkB) * 2u;
#pragma unroll
            for (int mi = 0; mi < 4; mi++) {
                uint32_t rbase = (uint32_t)((mw * 64 + mi * 16) * 40) * 2u;
                ldsm4(ah[mi][0], ah[mi][1], ah[mi][2], ah[mi][3], AHu + rbase + aoff);
                ldsm4(al[mi][0], al[mi][1], al[mi][2], al[mi][3], ALu + rbase + aoff);
            }
#pragma unroll
            for (int no = 0; no < 2; no++) {
                uint32_t nbase = (uint32_t)((nw * 32 + no * 16) * 40) * 2u;
                ldsm4(bh[2 * no][0], bh[2 * no][1], bh[2 * no + 1][0], bh[2 * no + 1][1],
                      BHu + nbase + boff);
                ldsm4(bl[2 * no][0], bl[2 * no][1], bl[2 * no + 1][0], bl[2 * no + 1][1],
                      BLu + nbase + boff);
            }
#pragma unroll
            for (int mi = 0; mi < 4; mi++)
#pragma unroll
                for (int ni = 0; ni < 4; ni++) {
                    MMA_BF16(acc[mi][ni], al[mi][0], al[mi][1], al[mi][2], al[mi][3],
                             bh[ni][0], bh[ni][1]);
                    MMA_BF16(acc[mi][ni], ah[mi][0], ah[mi][1], ah[mi][2], ah[mi][3],
                             bl[ni][0], bl[ni][1]);
                    MMA_BF16(acc[mi][ni], ah[mi][0], ah[mi][1], ah[mi][2], ah[mi][3],
                             bh[ni][0], bh[ni][1]);
                }
        }
        __syncthreads();
    }
#undef COPY_CHUNK

    float shv[8], wkv[8];
#pragma unroll
    for (int mi = 0; mi < 4; mi++)
#pragma unroll
        for (int rh = 0; rh < 2; rh++) {
            int m = mt * 128 + mw * 64 + mi * 16 + (lane >> 2) + rh * 8;
            shv[mi * 2 + rh] = g_sh5[m];
            wkv[mi * 2 + rh] = w6[m];
        }

    float* red = reinterpret_cast<float*>(smb);     // [64][17]
    const int slice = mw * 8 + (lane >> 2);
#pragma unroll
    for (int ni = 0; ni < 4; ni++)
#pragma unroll
        for (int j = 0; j < 2; j++) {
            float s = 0.f;
#pragma unroll
            for (int mi = 0; mi < 4; mi++)
#pragma unroll
                for (int rh = 0; rh < 2; rh++) {
                    float z = fmaxf(acc[mi][ni][rh * 2 + j] + shv[mi * 2 + rh], 0.f);
                    s = fmaf(z, wkv[mi * 2 + rh], s);
                }
            int col = nw * 32 + ni * 8 + 2 * (lane & 3) + j;
            red[col * 17 + slice] = s;
        }
    __syncthreads();
    if (tid < 64) {
        float t = 0.f;
#pragma unroll
        for (int r = 0; r < 16; r++) t += red[tid * 17 + r];
        g_part[mt][b * NHW + p0 + tid] = t;
    }
}

// ---------------- K5: a = sigmoid(part0+part1+b6); out = x * a ----------------
__global__ void __launch_bounds__(256) k5_scale(const float* __restrict__ x,
                                                const float* __restrict__ b6,
                                                float* __restrict__ out)
{
    int idx = blockIdx.x * 256 + threadIdx.x;
    float4 xv = reinterpret_cast<const float4*>(x)[idx];
    int pix4 = idx & 255;
    int b = idx >> 16;
    float4 t0 = reinterpret_cast<const float4*>(g_part[0])[b * 256 + pix4];
    float4 t1 = reinterpret_cast<const float4*>(g_part[1])[b * 256 + pix4];
    float bb = b6[0];
    float4 av;
    av.x = 1.f / (1.f + expf(-(t0.x + t1.x + bb)));
    av.y = 1.f / (1.f + expf(-(t0.y + t1.y + bb)));
    av.z = 1.f / (1.f + expf(-(t0.z + t1.z + bb)));
    av.w = 1.f / (1.f + expf(-(t0.w + t1.w + bb)));
    float4 o;
    o.x = xv.x * av.x; o.y = xv.y * av.y; o.z = xv.z * av.z; o.w = xv.w * av.w;
    reinterpret_cast<float4*>(out)[idx] = o;
}

// ---------------- launch ------------------------------------------------------
extern "C" void kernel_launch(void* const* d_in, const int* in_sizes, int n_in,
                              void* d_out, int out_size)
{
    const float* x   = (const float*)d_in[0];
    const float* w1  = (const float*)d_in[1];
    const float* b1  = (const float*)d_in[2];
    const float* g1  = (const float*)d_in[3];
    const float* bt1 = (const float*)d_in[4];
    const float* m1  = (const float*)d_in[5];
    const float* v1  = (const float*)d_in[6];
    const float* w2  = (const float*)d_in[7];
    const float* b2  = (const float*)d_in[8];
    const float* g2  = (const float*)d_in[9];
    const float* bt2 = (const float*)d_in[10];
    const float* m2  = (const float*)d_in[11];
    const float* v2  = (const float*)d_in[12];
    const float* w3  = (const float*)d_in[13];
    const float* b3  = (const float*)d_in[14];
    const float* g3  = (const float*)d_in[15];
    const float* bt3 = (const float*)d_in[16];
    const float* m3  = (const float*)d_in[17];
    const float* v3  = (const float*)d_in[18];
    const float* w4  = (const float*)d_in[19];
    const float* b4  = (const float*)d_in[20];
    const float* w5  = (const float*)d_in[21];
    const float* b5  = (const float*)d_in[22];
    const float* g5  = (const float*)d_in[23];
    const float* bt5 = (const float*)d_in[24];
    const float* m5  = (const float*)d_in[25];
    const float* v5  = (const float*)d_in[26];
    const float* w6  = (const float*)d_in[27];
    const float* b6  = (const float*)d_in[28];

    cudaFuncSetAttribute(k1_mma, cudaFuncAttributeMaxDynamicSharedMemorySize, 102400);
    cudaFuncSetAttribute(k2_mma, cudaFuncAttributeMaxDynamicSharedMemorySize, 73728);
    cudaFuncSetAttribute(k3_mma, cudaFuncAttributeMaxDynamicSharedMemorySize, 55296);
    cudaFuncSetAttribute(k4_mma, cudaFuncAttributeMaxDynamicSharedMemorySize, 61440);

    k0_prep<<<NC5 + 1 + NB + 192 + 256, 256>>>(w5, g5, v5, b5, bt5, m5, w4,
                                               w1, b1, g1, bt1, m1, v1,
                                               w2, b2, g2, bt2, m2, v2,
                                               w3, b3, g3, bt3, m3, v3);
    k1_mma<<<dim3(8, NB), 384, 102400>>>(x);
    k2t<<<dim3(16, NB), 256>>>();
    k2_mma<<<dim3(4, 2, NB), 128, 73728>>>();
    k3_mma<<<dim3(16, 4, NB), 128, 55296>>>(b4);
    k4_mma<<<dim3(16, 2, NB), 128, 61440>>>(w6);
    k5_scale<<<(NB * NINP * NHW / 4) / 256, 256>>>(x, b6, (float*)d_out);
}

// round 12
// speedup vs baseline: 2.1444x; 1.0024x over previous
#include <cuda_runtime.h>
#include <cuda_bf16.h>
#include <math.h>
#include <stdint.h>

#define NB 32
#define NINP 256
#define NHW 1024
#define NCS 64
#define NAOUT 256
#define NCF 513
#define NC5 256
#define EPSV 1e-5f
#define KP 544
#define NCHUNK 17

// ---------------- scratch ------------------------------------------------------
__device__ float g_theta[NB * NCS * NHW];   // [b][c][p] fp32
__device__ float g_phi[NB * NCS * NHW];     // [b][c][p] fp32
__device__ __align__(16) __nv_bfloat16 g_wch[192 * NINP];       // stacked folded conv w
__device__ __align__(16) __nv_bfloat16 g_wcl[192 * NINP];
__device__ __align__(16) __nv_bfloat16 g_w4h[NAOUT * NHW];      // w4 split [o][j]
__device__ __align__(16) __nv_bfloat16 g_w4l[NAOUT * NHW];
__device__ __align__(16) __nv_bfloat16 g_pTh[NB * NCS * NHW];   // P^T split [b][c][j]
__device__ __align__(16) __nv_bfloat16 g_pTl[NB * NCS * NHW];
__device__ __align__(16) __nv_bfloat16 g_thh[NB * NCS * NHW];   // theta split [b][c][p]
__device__ __align__(16) __nv_bfloat16 g_thl[NB * NCS * NHW];
__device__ float g_WPp[4][NB * 512 * NCS];  // fp32 K-split partials
__device__ __align__(16) __nv_bfloat16 g_WPh[NB * 512 * NCS];   // [b][row][c]
__device__ __align__(16) __nv_bfloat16 g_WPl[NB * 512 * NCS];
__device__ __align__(16) __nv_bfloat16 g_yh[NB * NHW * KP];     // [b][p][f'] hi
__device__ __align__(16) __nv_bfloat16 g_yl[NB * NHW * KP];
__device__ float g_part[2][NB * NHW];       // partial logits per M-half
__device__ __align__(16) __nv_bfloat16 g_w5h[NC5 * KP];
__device__ __align__(16) __nv_bfloat16 g_w5l[NC5 * KP];
__device__ float g_sc[3 * NCS];
__device__ float g_sh[3 * NCS];
__device__ float g_sh5[NC5];

__device__ __forceinline__ float f4get(const float4& v, int i) {
    return i == 0 ? v.x : (i == 1 ? v.y : (i == 2 ? v.z : v.w));
}

__device__ __forceinline__ uint32_t smem_u32(const void* p) {
    uint32_t a;
    asm("{ .reg .u64 t; cvta.to.shared.u64 t, %1; cvt.u32.u64 %0, t; }" : "=r"(a) : "l"(p));
    return a;
}

__device__ __forceinline__ void bf16_split(float v, __nv_bfloat16& h, __nv_bfloat16& l) {
    h = __float2bfloat16_rn(v);
    l = __float2bfloat16_rn(v - __bfloat162float(h));
}

__device__ __forceinline__ uint32_t pk2(__nv_bfloat16 a, __nv_bfloat16 b) {
    __nv_bfloat162 t; t.x = a; t.y = b;
    return *reinterpret_cast<uint32_t*>(&t);
}

__device__ __forceinline__ void ldsm4(uint32_t& r0, uint32_t& r1, uint32_t& r2, uint32_t& r3,
                                      uint32_t addr) {
    asm volatile("ldmatrix.sync.aligned.m8n8.x4.shared.b16 {%0,%1,%2,%3}, [%4];"
                 : "=r"(r0), "=r"(r1), "=r"(r2), "=r"(r3) : "r"(addr));
}

#define MMA_BF16(ACC, A0, A1, A2, A3, B0, B1)                                        \
    asm volatile(                                                                    \
        "mma.sync.aligned.m16n8k16.row.col.f32.bf16.bf16.f32 "                       \
        "{%0,%1,%2,%3}, {%4,%5,%6,%7}, {%8,%9}, {%0,%1,%2,%3};"                      \
        : "+f"((ACC)[0]), "+f"((ACC)[1]), "+f"((ACC)[2]), "+f"((ACC)[3])             \
        : "r"(A0), "r"(A1), "r"(A2), "r"(A3), "r"(B0), "r"(B1))

// ---------------- K0: params, w5/convw/w4 split, y pad zero -------------------
__global__ void k0_prep(const float* __restrict__ w5,
                        const float* __restrict__ g5, const float* __restrict__ v5,
                        const float* __restrict__ b5, const float* __restrict__ bt5,
                        const float* __restrict__ m5, const float* __restrict__ w4,
                        const float* __restrict__ w1, const float* __restrict__ b1,
                        const float* __restrict__ g1, const float* __restrict__ bt1,
                        const float* __restrict__ m1, const float* __restrict__ v1,
                        const float* __restrict__ w2, const float* __restrict__ b2,
                        const float* __restrict__ g2, const float* __restrict__ bt2,
                        const float* __restrict__ m2, const float* __restrict__ v2,
                        const float* __restrict__ w3, const float* __restrict__ b3,
                        const float* __restrict__ g3, const float* __restrict__ bt3,
                        const float* __restrict__ m3, const float* __restrict__ v3)
{
    const int blk = blockIdx.x;
    const int tid = threadIdx.x;
    if (blk < NC5) {
        const int k = blk;
        float s5 = g5[k] * rsqrtf(v5[k] + EPSV);
        for (int f = tid; f < KP; f += 256) {
            float val;
            if (f < 512) val = w5[k * NCF + 1 + f] * s5;
            else if (f == 512) val = w5[k * NCF] * s5;
            else val = 0.f;
            __nv_bfloat16 h, l;
            bf16_split(val, h, l);
            g_w5h[k * KP + f] = h;
            g_w5l[k * KP + f] = l;
        }
    } else if (blk == NC5) {
        const int k = tid;
        float s5 = g5[k] * rsqrtf(v5[k] + EPSV);
        g_sh5[k] = (b5[k] - m5[k]) * s5 + bt5[k];
        if (k < 3 * NCS) {
            int cv = k / NCS, c = k % NCS;
            const float* bb = cv == 0 ? b1 : (cv == 1 ? b2 : b3);
            const float* gg = cv == 0 ? g1 : (cv == 1 ? g2 : g3);
            const float* bt = cv == 0 ? bt1 : (cv == 1 ? bt2 : bt3);
            const float* mm = cv == 0 ? m1 : (cv == 1 ? m2 : m3);
            const float* vv = cv == 0 ? v1 : (cv == 1 ? v2 : v3);
            float s = gg[c] * rsqrtf(vv[c] + EPSV);
            g_sc[k] = s;
            g_sh[k] = (bb[c] - mm[c]) * s + bt[c];
        }
    } else if (blk < NC5 + 1 + NB) {
        const int b = blk - NC5 - 1;
        char* baseh = (char*)(g_yh + (size_t)b * NHW * KP + 512);
        char* basel = (char*)(g_yl + (size_t)b * NHW * KP + 512);
        uint4 z = make_uint4(0u, 0u, 0u, 0u);
        for (int i = tid; i < NHW * 4; i += 256) {
            int p = i >> 2, q = i & 3;
            *reinterpret_cast<uint4*>(baseh + (size_t)p * (KP * 2) + q * 16) = z;
            *reinterpret_cast<uint4*>(basel + (size_t)p * (KP * 2) + q * 16) = z;
        }
    } else if (blk < NC5 + 1 + NB + 192) {
        const int row = blk - (NC5 + 1 + NB);
        const int cv = row >> 6, c = row & 63;
        const float* W  = cv == 0 ? w1 : (cv == 1 ? w2 : w3);
        const float* gg = cv == 0 ? g1 : (cv == 1 ? g2 : g3);
        const float* vv = cv == 0 ? v1 : (cv == 1 ? v2 : v3);
        float s = gg[c] * rsqrtf(vv[c] + EPSV);
        float val = W[c * NINP + tid] * s;
        __nv_bfloat16 h, l;
        bf16_split(val, h, l);
        g_wch[row * NINP + tid] = h;
        g_wcl[row * NINP + tid] = l;
    } else {
        const int row = blk - (NC5 + 1 + NB + 192);
        float4 v = *reinterpret_cast<const float4*>(w4 + (size_t)row * NHW + tid * 4);
        __nv_bfloat16 h0, l0, h1, l1, h2, l2, h3, l3;
        bf16_split(v.x, h0, l0); bf16_split(v.y, h1, l1);
        bf16_split(v.z, h2, l2); bf16_split(v.w, h3, l3);
        size_t base = (size_t)row * NHW + tid * 4;
        *reinterpret_cast<uint2*>(&g_w4h[base]) = make_uint2(pk2(h0, h1), pk2(h2, h3));
        *reinterpret_cast<uint2*>(&g_w4l[base]) = make_uint2(pk2(l0, l1), pk2(l2, l3));
    }
}

// ---------------- K1: conv GEMM C[192,128px] = Wc[192,256] @ x^T --------------
__global__ void __launch_bounds__(384) k1_mma(const float* __restrict__ x)
{
    extern __shared__ __nv_bfloat16 smb[];
    const int AH = 0, AL = 15360, BH = 30720, BL = 40960;
    const uint32_t smb_u = smem_u32(smb);
    const int tid = threadIdx.x;
    const int lane = tid & 31;
    const int wid = tid >> 5;
    const int mw3 = wid % 3;
    const int nw4 = wid / 3;
    const int b = blockIdx.y;
    const int p0 = blockIdx.x * 128;
    const float* xb = x + (size_t)b * NINP * NHW;

    const int lrA = lane & 15;
    const int lkA = (lane >> 4) << 3;
    const int lnB = (lane & 7) + ((lane >> 4) << 3);
    const int lkB = ((lane >> 3) & 1) << 3;

    float acc[4][4][4];
#pragma unroll
    for (int mi = 0; mi < 4; mi++)
#pragma unroll
        for (int ni = 0; ni < 4; ni++)
#pragma unroll
            for (int c = 0; c < 4; c++) acc[mi][ni][c] = 0.f;

#define K1_COPYA(ch, buf) do {                                                        \
    for (int i = tid; i < 768; i += 384) {                                            \
        int row = i >> 2, q = i & 3;                                                  \
        uint32_t dh = smb_u + (uint32_t)(AH + (buf) * 7680 + row * 40 + q * 8) * 2u;  \
        uint32_t dl = smb_u + (uint32_t)(AL + (buf) * 7680 + row * 40 + q * 8) * 2u;  \
        size_t so = (size_t)row * NINP + (ch) * 32 + q * 8;                           \
        asm volatile("cp.async.ca.shared.global [%0], [%1], 16;" :: "r"(dh), "l"(g_wch + so)); \
        asm volatile("cp.async.ca.shared.global [%0], [%1], 16;" :: "r"(dl), "l"(g_wcl + so)); \
    }                                                                                 \
    asm volatile("cp.async.commit_group;");                                           \
} while (0)

#define K1_BUILDB(ch, buf) do {                                                       \
    for (int i = tid; i < 512; i += 384) {                                            \
        int cpair = i & 15, pq = i >> 4;                                              \
        const float* src = xb + (size_t)((ch) * 32 + cpair * 2) * NHW + p0 + pq * 4;  \
        float4 v0 = *reinterpret_cast<const float4*>(src);                            \
        float4 v1 = *reinterpret_cast<const float4*>(src + NHW);                      \
        _Pragma("unroll")                                                             \
        for (int j = 0; j < 4; j++) {                                                 \
            __nv_bfloat16 h0, l0, h1, l1;                                             \
            bf16_split(f4get(v0, j), h0, l0);                                         \
            bf16_split(f4get(v1, j), h1, l1);                                         \
            int eo = (pq * 4 + j) * 40 + cpair * 2;                                   \
            *reinterpret_cast<uint32_t*>(smb + BH + (buf) * 5120 + eo) = pk2(h0, h1); \
            *reinterpret_cast<uint32_t*>(smb + BL + (buf) * 5120 + eo) = pk2(l0, l1); \
        }                                                                             \
    }                                                                                 \
} while (0)

    K1_COPYA(0, 0);
    K1_BUILDB(0, 0);
    for (int ch = 0; ch < 8; ch++) {
        if (ch < 7) {
            K1_COPYA(ch + 1, (ch + 1) & 1);
            K1_BUILDB(ch + 1, (ch + 1) & 1);
            asm volatile("cp.async.wait_group 1;");
        } else {
            asm volatile("cp.async.wait_group 0;");
        }
        __syncthreads();
        const int buf = ch & 1;
        const uint32_t AHu = smb_u + (uint32_t)(AH + buf * 7680) * 2u;
        const uint32_t ALu = smb_u + (uint32_t)(AL + buf * 7680) * 2u;
        const uint32_t BHu = smb_u + (uint32_t)(BH + buf * 5120) * 2u;
        const uint32_t BLu = smb_u + (uint32_t)(BL + buf * 5120) * 2u;
#pragma unroll
        for (int ks = 0; ks < 2; ks++) {
            uint32_t ah[4][4], al[4][4], bh[4][2], bl[4][2];
            const uint32_t aoff = (uint32_t)(lrA * 40 + ks * 16 + lkA) * 2u;
            const uint32_t boff = (uint32_t)(lnB * 40 + ks * 16 + lkB) * 2u;
#pragma unroll
            for (int mi = 0; mi < 4; mi++) {
                uint32_t rbase = (uint32_t)((mw3 * 64 + mi * 16) * 40) * 2u;
                ldsm4(ah[mi][0], ah[mi][1], ah[mi][2], ah[mi][3], AHu + rbase + aoff);
                ldsm4(al[mi][0], al[mi][1], al[mi][2], al[mi][3], ALu + rbase + aoff);
            }
#pragma unroll
            for (int no = 0; no < 2; no++) {
                uint32_t nbase = (uint32_t)((nw4 * 32 + no * 16) * 40) * 2u;
                ldsm4(bh[2 * no][0], bh[2 * no][1], bh[2 * no + 1][0], bh[2 * no + 1][1],
                      BHu + nbase + boff);
                ldsm4(bl[2 * no][0], bl[2 * no][1], bl[2 * no + 1][0], bl[2 * no + 1][1],
                      BLu + nbase + boff);
            }
#pragma unroll
            for (int mi = 0; mi < 4; mi++)
#pragma unroll
                for (int ni = 0; ni < 4; ni++) {
                    MMA_BF16(acc[mi][ni], al[mi][0], al[mi][1], al[mi][2], al[mi][3],
                             bh[ni][0], bh[ni][1]);
                    MMA_BF16(acc[mi][ni], ah[mi][0], ah[mi][1], ah[mi][2], ah[mi][3],
                             bl[ni][0], bl[ni][1]);
                    MMA_BF16(acc[mi][ni], ah[mi][0], ah[mi][1], ah[mi][2], ah[mi][3],
                             bh[ni][0], bh[ni][1]);
                }
        }
        __syncthreads();
    }
#undef K1_COPYA
#undef K1_BUILDB

    const int ar = lane >> 2;
    const int qq = lane & 3;
    if (mw3 < 2) {
        float* dst = (mw3 == 0 ? g_theta : g_phi) + (size_t)b * NCS * NHW;
#pragma unroll
        for (int mi = 0; mi < 4; mi++)
#pragma unroll
            for (int rh = 0; rh < 2; rh++) {
                int c = mi * 16 + ar + rh * 8;
                float sh = g_sh[mw3 * 64 + c];
#pragma unroll
                for (int ni = 0; ni < 4; ni++) {
                    int px = p0 + nw4 * 32 + ni * 8 + 2 * qq;
                    float2 o;
                    o.x = fmaxf(acc[mi][ni][rh * 2 + 0] + sh, 0.f);
                    o.y = fmaxf(acc[mi][ni][rh * 2 + 1] + sh, 0.f);
                    *reinterpret_cast<float2*>(dst + (size_t)c * NHW + px) = o;
                    if (mw3 == 0) {
                        __nv_bfloat16 h0, l0, h1, l1;
                        bf16_split(o.x, h0, l0);
                        bf16_split(o.y, h1, l1);
                        size_t tb = (size_t)b * NCS * NHW + (size_t)c * NHW + px;
                        *reinterpret_cast<uint32_t*>(&g_thh[tb]) = pk2(h0, h1);
                        *reinterpret_cast<uint32_t*>(&g_thl[tb]) = pk2(l0, l1);
                    }
                }
            }
    } else {
        float s_px[8];
#pragma unroll
        for (int ni = 0; ni < 4; ni++)
#pragma unroll
            for (int j = 0; j < 2; j++) {
                float s = 0.f;
#pragma unroll
                for (int mi = 0; mi < 4; mi++)
#pragma unroll
                    for (int rh = 0; rh < 2; rh++) {
                        int c = mi * 16 + ar + rh * 8;
                        s += fmaxf(acc[mi][ni][rh * 2 + j] + g_sh[128 + c], 0.f);
                    }
                s_px[ni * 2 + j] = s;
            }
#pragma unroll
        for (int v = 0; v < 8; v++) {
            s_px[v] += __shfl_xor_sync(0xffffffffu, s_px[v], 4);
            s_px[v] += __shfl_xor_sync(0xffffffffu, s_px[v], 8);
            s_px[v] += __shfl_xor_sync(0xffffffffu, s_px[v], 16);
        }
        if (lane < 4) {
#pragma unroll
            for (int ni = 0; ni < 4; ni++)
#pragma unroll
                for (int j = 0; j < 2; j++) {
                    int px = p0 + nw4 * 32 + ni * 8 + 2 * lane + j;
                    float val = s_px[ni * 2 + j] * (1.f / NCS);
                    __nv_bfloat16 h, l;
                    bf16_split(val, h, l);
                    size_t base = (size_t)(b * NHW + px) * KP + 512;
                    g_yh[base] = h;
                    g_yl[base] = l;
                }
        }
    }
}

// ---------------- K2t: transpose+split phi -> P^T -----------------------------
__global__ void __launch_bounds__(256) k2t()
{
    __shared__ float sm[64 * 68];
    const int jt = blockIdx.x;
    const int b = blockIdx.y;
    const int tid = threadIdx.x;

    const float* src = g_phi + (size_t)b * NCS * NHW + jt * 4096;
    for (int i = tid; i < 1024; i += 256) {
        int r = i >> 4, cq = i & 15;
        float4 v = *reinterpret_cast<const float4*>(src + r * 64 + cq * 4);
        *reinterpret_cast<float4*>(sm + r * 68 + cq * 4) = v;
    }
    __syncthreads();
    const int jg = tid >> 6;
    const int c = tid & 63;
    uint32_t hb[8], lb[8];
#pragma unroll
    for (int k2i = 0; k2i < 8; k2i++) {
        __nv_bfloat16 h0, l0, h1, l1;
        bf16_split(sm[(jg * 16 + k2i * 2) * 68 + c], h0, l0);
        bf16_split(sm[(jg * 16 + k2i * 2 + 1) * 68 + c], h1, l1);
        hb[k2i] = pk2(h0, h1);
        lb[k2i] = pk2(l0, l1);
    }
    size_t base = (size_t)b * NCS * NHW + (size_t)c * NHW + jt * 64 + jg * 16;
    *reinterpret_cast<uint4*>(&g_pTh[base])     = make_uint4(hb[0], hb[1], hb[2], hb[3]);
    *reinterpret_cast<uint4*>(&g_pTh[base + 8]) = make_uint4(hb[4], hb[5], hb[6], hb[7]);
    *reinterpret_cast<uint4*>(&g_pTl[base])     = make_uint4(lb[0], lb[1], lb[2], lb[3]);
    *reinterpret_cast<uint4*>(&g_pTl[base + 8]) = make_uint4(lb[4], lb[5], lb[6], lb[7]);
}

// ---------------- K2: K-split mma GEMM -> fp32 partials -----------------------
// grid (4 otiles, 2 which, NB*4 ksplit), 128 thr; each CTA: K chunk of 256
__global__ void __launch_bounds__(128) k2_mma()
{
    extern __shared__ __nv_bfloat16 smb[];
    const int AH = 0, AL = 9216, BH = 18432, BL = 27648;
    const uint32_t smb_u = smem_u32(smb);
    const int tid = threadIdx.x;
    const int lane = tid & 31;
    const int wid = tid >> 5;
    const int mw = wid & 1;
    const int nw = wid >> 1;
    const int o0 = blockIdx.x * 64;
    const int which = blockIdx.y;
    const int ksp = blockIdx.z & 3;
    const int b = blockIdx.z >> 2;

    const int lrA = lane & 15;
    const int lkA = (lane >> 4) << 3;
    const int lnB = (lane & 7) + ((lane >> 4) << 3);
    const int lkB = ((lane >> 3) & 1) << 3;

    const __nv_bfloat16* Asrch = g_w4h + (size_t)o0 * NHW;
    const __nv_bfloat16* Asrcl = g_w4l + (size_t)o0 * NHW;
    const __nv_bfloat16* Bsrch = (which ? g_thh : g_pTh) + (size_t)b * NCS * NHW;
    const __nv_bfloat16* Bsrcl = (which ? g_thl : g_pTl) + (size_t)b * NCS * NHW;

    float acc[2][4][4];
#pragma unroll
    for (int mi = 0; mi < 2; mi++)
#pragma unroll
        for (int ni = 0; ni < 4; ni++)
#pragma unroll
            for (int c = 0; c < 4; c++) acc[mi][ni][c] = 0.f;

#define K2_COPY(ch, buf) do {                                                         \
    for (int i = tid; i < 512; i += 128) {                                            \
        int row = i >> 3, q = i & 7;                                                  \
        uint32_t dh = smb_u + (uint32_t)(AH + (buf) * 4608 + row * 72 + q * 8) * 2u;  \
        uint32_t dl = smb_u + (uint32_t)(AL + (buf) * 4608 + row * 72 + q * 8) * 2u;  \
        size_t so = (size_t)row * NHW + (ch) * 64 + q * 8;                            \
        asm volatile("cp.async.ca.shared.global [%0], [%1], 16;" :: "r"(dh), "l"(Asrch + so)); \
        asm volatile("cp.async.ca.shared.global [%0], [%1], 16;" :: "r"(dl), "l"(Asrcl + so)); \
    }                                                                                 \
    for (int i = tid; i < 512; i += 128) {                                            \
        int row = i >> 3, q = i & 7;                                                  \
        uint32_t dh = smb_u + (uint32_t)(BH + (buf) * 4608 + row * 72 + q * 8) * 2u;  \
        uint32_t dl = smb_u + (uint32_t)(BL + (buf) * 4608 + row * 72 + q * 8) * 2u;  \
        size_t so = (size_t)row * NHW + (ch) * 64 + q * 8;                            \
        asm volatile("cp.async.ca.shared.global [%0], [%1], 16;" :: "r"(dh), "l"(Bsrch + so)); \
        asm volatile("cp.async.ca.shared.global [%0], [%1], 16;" :: "r"(dl), "l"(Bsrcl + so)); \
    }                                                                                 \
    asm volatile("cp.async.commit_group;");                                           \
} while (0)

    const int ch0 = ksp * 4;
    K2_COPY(ch0, 0);
    for (int ci = 0; ci < 4; ci++) {
        if (ci < 3) {
            K2_COPY(ch0 + ci + 1, (ci + 1) & 1);
            asm volatile("cp.async.wait_group 1;");
        } else {
            asm volatile("cp.async.wait_group 0;");
        }
        __syncthreads();
        const int buf = ci & 1;
        const uint32_t AHu = smb_u + (uint32_t)(AH + buf * 4608) * 2u;
        const uint32_t ALu = smb_u + (uint32_t)(AL + buf * 4608) * 2u;
        const uint32_t BHu = smb_u + (uint32_t)(BH + buf * 4608) * 2u;
        const uint32_t BLu = smb_u + (uint32_t)(BL + buf * 4608) * 2u;
#pragma unroll
        for (int ks = 0; ks < 4; ks++) {
            uint32_t ah[2][4], al[2][4], bh[4][2], bl[4][2];
            const uint32_t aoff = (uint32_t)(lrA * 72 + ks * 16 + lkA) * 2u;
            const uint32_t boff = (uint32_t)(lnB * 72 + ks * 16 + lkB) * 2u;
#pragma unroll
            for (int mi = 0; mi < 2; mi++) {
                uint32_t rbase = (uint32_t)((mw * 32 + mi * 16) * 72) * 2u;
                ldsm4(ah[mi][0], ah[mi][1], ah[mi][2], ah[mi][3], AHu + rbase + aoff);
                ldsm4(al[mi][0], al[mi][1], al[mi][2], al[mi][3], ALu + rbase + aoff);
            }
#pragma unroll
            for (int no = 0; no < 2; no++) {
                uint32_t nbase = (uint32_t)((nw * 32 + no * 16) * 72) * 2u;
                ldsm4(bh[2 * no][0], bh[2 * no][1], bh[2 * no + 1][0], bh[2 * no + 1][1],
                      BHu + nbase + boff);
                ldsm4(bl[2 * no][0], bl[2 * no][1], bl[2 * no + 1][0], bl[2 * no + 1][1],
                      BLu + nbase + boff);
            }
#pragma unroll
            for (int mi = 0; mi < 2; mi++)
#pragma unroll
                for (int ni = 0; ni < 4; ni++) {
                    MMA_BF16(acc[mi][ni], al[mi][0], al[mi][1], al[mi][2], al[mi][3],
                             bh[ni][0], bh[ni][1]);
                    MMA_BF16(acc[mi][ni], ah[mi][0], ah[mi][1], ah[mi][2], ah[mi][3],
                             bl[ni][0], bl[ni][1]);
                    MMA_BF16(acc[mi][ni], ah[mi][0], ah[mi][1], ah[mi][2], ah[mi][3],
                             bh[ni][0], bh[ni][1]);
                }
        }
        __syncthreads();
    }
#undef K2_COPY

    // fp32 partial store
    const int ar = lane >> 2;
    const int qq = lane & 3;
    float* WP = g_WPp[ksp] + (size_t)b * 512 * NCS;
#pragma unroll
    for (int mi = 0; mi < 2; mi++)
#pragma unroll
        for (int rh = 0; rh < 2; rh++) {
            int row = which * 256 + o0 + mw * 32 + mi * 16 + ar + rh * 8;
#pragma unroll
            for (int ni = 0; ni < 4; ni++) {
                int col = nw * 32 + ni * 8 + 2 * qq;
                float2 o;
                o.x = acc[mi][ni][rh * 2 + 0];
                o.y = acc[mi][ni][rh * 2 + 1];
                *reinterpret_cast<float2*>(WP + (size_t)row * NCS + col) = o;
            }
        }
}

// ---------------- K2r: reduce 4 partials -> split bf16 ------------------------
__global__ void __launch_bounds__(256) k2r()
{
    const size_t idx = ((size_t)blockIdx.x * 256 + threadIdx.x) * 4;   // over NB*512*64
    const size_t STRIDE = (size_t)NB * 512 * NCS;
    float4 s = *reinterpret_cast<const float4*>(&g_WPp[0][0] + idx);
    float4 t1 = *reinterpret_cast<const float4*>(&g_WPp[0][0] + STRIDE + idx);
    float4 t2 = *reinterpret_cast<const float4*>(&g_WPp[0][0] + 2 * STRIDE + idx);
    float4 t3 = *reinterpret_cast<const float4*>(&g_WPp[0][0] + 3 * STRIDE + idx);
    s.x += t1.x + (t2.x + t3.x);
    s.y += t1.y + (t2.y + t3.y);
    s.z += t1.z + (t2.z + t3.z);
    s.w += t1.w + (t2.w + t3.w);
    __nv_bfloat16 h0, l0, h1, l1, h2, l2, h3, l3;
    bf16_split(s.x, h0, l0); bf16_split(s.y, h1, l1);
    bf16_split(s.z, h2, l2); bf16_split(s.w, h3, l3);
    *reinterpret_cast<uint2*>(&g_WPh[idx]) = make_uint2(pk2(h0, h1), pk2(h2, h3));
    *reinterpret_cast<uint2*>(&g_WPl[idx]) = make_uint2(pk2(l0, l1), pk2(l2, l3));
}

// ---------------- K3: quarter tile C[64px, 128f] = A[px,64c] @ B[f,64c]^T -----
__global__ void __launch_bounds__(128) k3_mma(const float* __restrict__ b4)
{
    extern __shared__ __nv_bfloat16 smb[];
    const int AH = 0, AL = 4608, BH = 9216, BL = 18432;
    const uint32_t smb_u = smem_u32(smb);
    const int tid = threadIdx.x;
    const int lane = tid & 31;
    const int wid = tid >> 5;
    const int mw = wid & 1;
    const int nwf = wid >> 1;
    const int p0 = blockIdx.x * 64;
    const int by = blockIdx.y;
    const int which = by >> 1;
    const int nt = by & 1;
    const int b = blockIdx.z;

    const int lrA = lane & 15;
    const int lkA = (lane >> 4) << 3;
    const int lnB = (lane & 7) + ((lane >> 4) << 3);
    const int lkB = ((lane >> 3) & 1) << 3;

    {
        const __nv_bfloat16* srch = g_WPh + ((size_t)b * 512 + which * 256 + nt * 128) * NCS;
        const __nv_bfloat16* srcl = g_WPl + ((size_t)b * 512 + which * 256 + nt * 128) * NCS;
        for (int i = tid; i < 1024; i += 128) {
            int row = i >> 3, q = i & 7;
            uint32_t dh = smb_u + (uint32_t)(BH + row * 72 + q * 8) * 2u;
            uint32_t dl = smb_u + (uint32_t)(BL + row * 72 + q * 8) * 2u;
            size_t so = (size_t)row * NCS + q * 8;
            asm volatile("cp.async.ca.shared.global [%0], [%1], 16;" :: "r"(dh), "l"(srch + so));
            asm volatile("cp.async.ca.shared.global [%0], [%1], 16;" :: "r"(dl), "l"(srcl + so));
        }
        asm volatile("cp.async.commit_group;");
    }
    if (which == 0) {
        const float* th = g_theta + (size_t)b * NCS * NHW;
        for (int i = tid; i < 1024; i += 128) {
            int c = (i & 15) + ((i >> 8) << 4);
            int pq = (i >> 4) & 15;
            float4 v = *reinterpret_cast<const float4*>(th + (size_t)c * NHW + p0 + pq * 4);
#pragma unroll
            for (int j = 0; j < 4; j++) {
                __nv_bfloat16 h, l;
                bf16_split(f4get(v, j), h, l);
                smb[AH + (pq * 4 + j) * 72 + c] = h;
                smb[AL + (pq * 4 + j) * 72 + c] = l;
            }
        }
    } else {
        const float* ph = g_phi + (size_t)b * NCS * NHW;
        for (int i = tid; i < 1024; i += 128) {
            int p = i >> 4, cq = i & 15;
            float4 v = *reinterpret_cast<const float4*>(ph + (size_t)(p0 + p) * NCS + cq * 4);
            __nv_bfloat16 h0, l0, h1, l1, h2, l2, h3, l3;
            bf16_split(v.x, h0, l0); bf16_split(v.y, h1, l1);
            bf16_split(v.z, h2, l2); bf16_split(v.w, h3, l3);
            *reinterpret_cast<uint2*>(&smb[AH + p * 72 + cq * 4]) =
                make_uint2(pk2(h0, h1), pk2(h2, h3));
            *reinterpret_cast<uint2*>(&smb[AL + p * 72 + cq * 4]) =
                make_uint2(pk2(l0, l1), pk2(l2, l3));
        }
    }
    asm volatile("cp.async.wait_group 0;");
    __syncthreads();

    float acc[2][8][4];
#pragma unroll
    for (int mi = 0; mi < 2; mi++)
#pragma unroll
        for (int ni = 0; ni < 8; ni++)
#pragma unroll
            for (int c = 0; c < 4; c++) acc[mi][ni][c] = 0.f;

#pragma unroll
    for (int ks = 0; ks < 4; ks++) {
        uint32_t ah[2][4], al[2][4], bh[8][2], bl[8][2];
        const uint32_t aoff = (uint32_t)(lrA * 72 + ks * 16 + lkA) * 2u;
        const uint32_t boff = (uint32_t)(lnB * 72 + ks * 16 + lkB) * 2u;
#pragma unroll
        for (int mi = 0; mi < 2; mi++) {
            uint32_t rb = (uint32_t)((mw * 32 + mi * 16) * 72) * 2u;
            ldsm4(ah[mi][0], ah[mi][1], ah[mi][2], ah[mi][3],
                  smb_u + (uint32_t)(AH * 2) + rb + aoff);
            ldsm4(al[mi][0], al[mi][1], al[mi][2], al[mi][3],
                  smb_u + (uint32_t)(AL * 2) + rb + aoff);
        }
#pragma unroll
        for (int no = 0; no < 4; no++) {
            uint32_t nb = (uint32_t)((nwf * 64 + no * 16) * 72) * 2u;
            ldsm4(bh[2 * no][0], bh[2 * no][1], bh[2 * no + 1][0], bh[2 * no + 1][1],
                  smb_u + (uint32_t)(BH * 2) + nb + boff);
            ldsm4(bl[2 * no][0], bl[2 * no][1], bl[2 * no + 1][0], bl[2 * no + 1][1],
                  smb_u + (uint32_t)(BL * 2) + nb + boff);
        }
#pragma unroll
        for (int ni = 0; ni < 8; ni++)
#pragma unroll
            for (int mi = 0; mi < 2; mi++) {
                MMA_BF16(acc[mi][ni], al[mi][0], al[mi][1], al[mi][2], al[mi][3],
                         bh[ni][0], bh[ni][1]);
                MMA_BF16(acc[mi][ni], ah[mi][0], ah[mi][1], ah[mi][2], ah[mi][3],
                         bl[ni][0], bl[ni][1]);
                MMA_BF16(acc[mi][ni], ah[mi][0], ah[mi][1], ah[mi][2], ah[mi][3],
                         bh[ni][0], bh[ni][1]);
            }
    }

    const int ar = lane >> 2;
    const int qq = lane & 3;
#pragma unroll
    for (int ni = 0; ni < 8; ni++) {
        int o = nt * 128 + nwf * 64 + ni * 8 + 2 * qq;
        float2 bb = *reinterpret_cast<const float2*>(b4 + o);
        int f0 = which * 256 + o;
#pragma unroll
        for (int mi = 0; mi < 2; mi++)
#pragma unroll
            for (int rh = 0; rh < 2; rh++) {
                int px = p0 + mw * 32 + mi * 16 + ar + rh * 8;
                float v0 = fmaxf(acc[mi][ni][rh * 2 + 0] + bb.x, 0.f);
                float v1 = fmaxf(acc[mi][ni][rh * 2 + 1] + bb.y, 0.f);
                __nv_bfloat16 h0, l0, h1, l1;
                bf16_split(v0, h0, l0);
                bf16_split(v1, h1, l1);
                size_t base = (size_t)(b * NHW + px) * KP + f0;
                *reinterpret_cast<uint32_t*>(&g_yh[base]) = pk2(h0, h1);
                *reinterpret_cast<uint32_t*>(&g_yl[base]) = pk2(l0, l1);
            }
    }
}

// ---------------- K4: quarter-tile split-bf16 GEMM + partial-logit epilogue ---
__global__ void __launch_bounds__(128, 3) k4_mma(const float* __restrict__ w6)
{
    extern __shared__ __nv_bfloat16 smb[];
    const int AH = 0, AL = 10240, BH = 20480, BL = 25600;
    const uint32_t smb_u = smem_u32(smb);
    const int tid = threadIdx.x;
    const int lane = tid & 31;
    const int wid = tid >> 5;
    const int mw = wid & 1;
    const int nw = wid >> 1;
    const int p0 = blockIdx.x * 64;
    const int mt = blockIdx.y;
    const int b = blockIdx.z;
    const size_t pixbase = (size_t)(b * NHW + p0);
    const size_t arowbase = (size_t)(mt * 128) * KP;

    const int lrA = lane & 15;
    const int lkA = (lane >> 4) << 3;
    const int lnB = (lane & 7) + ((lane >> 4) << 3);
    const int lkB = ((lane >> 3) & 1) << 3;

    float acc[4][4][4];
#pragma unroll
    for (int mi = 0; mi < 4; mi++)
#pragma unroll
        for (int ni = 0; ni < 4; ni++)
#pragma unroll
            for (int c = 0; c < 4; c++) acc[mi][ni][c] = 0.f;

#define COPY_CHUNK(ch, buf) do {                                                     \
    for (int i = tid; i < 512; i += 128) {                                           \
        int row = i >> 2, q = i & 3;                                                 \
        uint32_t dh = smb_u + (uint32_t)(AH + (buf) * 5120 + row * 40 + q * 8) * 2u; \
        uint32_t dl = smb_u + (uint32_t)(AL + (buf) * 5120 + row * 40 + q * 8) * 2u; \
        size_t so = arowbase + (size_t)row * KP + (ch) * 32 + q * 8;                 \
        asm volatile("cp.async.ca.shared.global [%0], [%1], 16;" :: "r"(dh), "l"(g_w5h + so)); \
        asm volatile("cp.async.ca.shared.global [%0], [%1], 16;" :: "r"(dl), "l"(g_w5l + so)); \
    }                                                                                \
    for (int i = tid; i < 256; i += 128) {                                           \
        int row = i >> 2, q = i & 3;                                                 \
        uint32_t dh = smb_u + (uint32_t)(BH + (buf) * 2560 + row * 40 + q * 8) * 2u; \
        uint32_t dl = smb_u + (uint32_t)(BL + (buf) * 2560 + row * 40 + q * 8) * 2u; \
        size_t so = (pixbase + row) * KP + (ch) * 32 + q * 8;                        \
        asm volatile("cp.async.ca.shared.global [%0], [%1], 16;" :: "r"(dh), "l"(g_yh + so)); \
        asm volatile("cp.async.ca.shared.global [%0], [%1], 16;" :: "r"(dl), "l"(g_yl + so)); \
    }                                                                                \
    asm volatile("cp.async.commit_group;");                                          \
} while (0)

    COPY_CHUNK(0, 0);
    for (int ch = 0; ch < NCHUNK; ch++) {
        if (ch < NCHUNK - 1) {
            COPY_CHUNK(ch + 1, (ch + 1) & 1);
            asm volatile("cp.async.wait_group 1;");
        } else {
            asm volatile("cp.async.wait_group 0;");
        }
        __syncthreads();
        const int buf = ch & 1;
        const uint32_t AHu = smb_u + (uint32_t)(AH + buf * 5120) * 2u;
        const uint32_t ALu = smb_u + (uint32_t)(AL + buf * 5120) * 2u;
        const uint32_t BHu = smb_u + (uint32_t)(BH + buf * 2560) * 2u;
        const uint32_t BLu = smb_u + (uint32_t)(BL + buf * 2560) * 2u;
#pragma unroll
        for (int ks = 0; ks < 2; ks++) {
            uint32_t ah[4][4], al[4][4], bh[4][2], bl[4][2];
            const uint32_t aoff = (uint32_t)(lrA * 40 + ks * 16 + lkA) * 2u;
            const uint32_t boff = (uint32_t)(lnB * 40 + ks * 16 + lkB) * 2u;
#pragma unroll
            for (int mi = 0; mi < 4; mi++) {
                uint32_t rbase = (uint32_t)((mw * 64 + mi * 16) * 40) * 2u;
                ldsm4(ah[mi][0], ah[mi][1], ah[mi][2], ah[mi][3], AHu + rbase + aoff);
                ldsm4(al[mi][0], al[mi][1], al[mi][2], al[mi][3], ALu + rbase + aoff);
            }
#pragma unroll
            for (int no = 0; no < 2; no++) {
                uint32_t nbase = (uint32_t)((nw * 32 + no * 16) * 40) * 2u;
                ldsm4(bh[2 * no][0], bh[2 * no][1], bh[2 * no + 1][0], bh[2 * no + 1][1],
                      BHu + nbase + boff);
                ldsm4(bl[2 * no][0], bl[2 * no][1], bl[2 * no + 1][0], bl[2 * no + 1][1],
                      BLu + nbase + boff);
            }
#pragma unroll
            for (int mi = 0; mi < 4; mi++)
#pragma unroll
                for (int ni = 0; ni < 4; ni++) {
                    MMA_BF16(acc[mi][ni], al[mi][0], al[mi][1], al[mi][2], al[mi][3],
                             bh[ni][0], bh[ni][1]);
                    MMA_BF16(acc[mi][ni], ah[mi][0], ah[mi][1], ah[mi][2], ah[mi][3],
                             bl[ni][0], bl[ni][1]);
                    MMA_BF16(acc[mi][ni], ah[mi][0], ah[mi][1], ah[mi][2], ah[mi][3],
                             bh[ni][0], bh[ni][1]);
                }
        }
        __syncthreads();
    }
#undef COPY_CHUNK

    float shv[8], wkv[8];
#pragma unroll
    for (int mi = 0; mi < 4; mi++)
#pragma unroll
        for (int rh = 0; rh < 2; rh++) {
            int m = mt * 128 + mw * 64 + mi * 16 + (lane >> 2) + rh * 8;
            shv[mi * 2 + rh] = g_sh5[m];
            wkv[mi * 2 + rh] = w6[m];
        }

    float* red = reinterpret_cast<float*>(smb);     // [64][17]
    const int slice = mw * 8 + (lane >> 2);
#pragma unroll
    for (int ni = 0; ni < 4; ni++)
#pragma unroll
        for (int j = 0; j < 2; j++) {
            float s = 0.f;
#pragma unroll
            for (int mi = 0; mi < 4; mi++)
#pragma unroll
                for (int rh = 0; rh < 2; rh++) {
                    float z = fmaxf(acc[mi][ni][rh * 2 + j] + shv[mi * 2 + rh], 0.f);
                    s = fmaf(z, wkv[mi * 2 + rh], s);
                }
            int col = nw * 32 + ni * 8 + 2 * (lane & 3) + j;
            red[col * 17 + slice] = s;
        }
    __syncthreads();
    if (tid < 64) {
        float t = 0.f;
#pragma unroll
        for (int r = 0; r < 16; r++) t += red[tid * 17 + r];
        g_part[mt][b * NHW + p0 + tid] = t;
    }
}

// ---------------- K5: a = sigmoid(part0+part1+b6); out = x * a ----------------
__global__ void __launch_bounds__(256) k5_scale(const float* __restrict__ x,
                                                const float* __restrict__ b6,
                                                float* __restrict__ out)
{
    int idx = blockIdx.x * 256 + threadIdx.x;
    float4 xv = reinterpret_cast<const float4*>(x)[idx];
    int pix4 = idx & 255;
    int b = idx >> 16;
    float4 t0 = reinterpret_cast<const float4*>(g_part[0])[b * 256 + pix4];
    float4 t1 = reinterpret_cast<const float4*>(g_part[1])[b * 256 + pix4];
    float bb = b6[0];
    float4 av;
    av.x = 1.f / (1.f + expf(-(t0.x + t1.x + bb)));
    av.y = 1.f / (1.f + expf(-(t0.y + t1.y + bb)));
    av.z = 1.f / (1.f + expf(-(t0.z + t1.z + bb)));
    av.w = 1.f / (1.f + expf(-(t0.w + t1.w + bb)));
    float4 o;
    o.x = xv.x * av.x; o.y = xv.y * av.y; o.z = xv.z * av.z; o.w = xv.w * av.w;
    reinterpret_cast<float4*>(out)[idx] = o;
}

// ---------------- launch ------------------------------------------------------
extern "C" void kernel_launch(void* const* d_in, const int* in_sizes, int n_in,
                              void* d_out, int out_size)
{
    const float* x   = (const float*)d_in[0];
    const float* w1  = (const float*)d_in[1];
    const float* b1  = (const float*)d_in[2];
    const float* g1  = (const float*)d_in[3];
    const float* bt1 = (const float*)d_in[4];
    const float* m1  = (const float*)d_in[5];
    const float* v1  = (const float*)d_in[6];
    const float* w2  = (const float*)d_in[7];
    const float* b2  = (const float*)d_in[8];
    const float* g2  = (const float*)d_in[9];
    const float* bt2 = (const float*)d_in[10];
    const float* m2  = (const float*)d_in[11];
    const float* v2  = (const float*)d_in[12];
    const float* w3  = (const float*)d_in[13];
    const float* b3  = (const float*)d_in[14];
    const float* g3  = (const float*)d_in[15];
    const float* bt3 = (const float*)d_in[16];
    const float* m3  = (const float*)d_in[17];
    const float* v3  = (const float*)d_in[18];
    const float* w4  = (const float*)d_in[19];
    const float* b4  = (const float*)d_in[20];
    const float* w5  = (const float*)d_in[21];
    const float* b5  = (const float*)d_in[22];
    const float* g5  = (const float*)d_in[23];
    const float* bt5 = (const float*)d_in[24];
    const float* m5  = (const float*)d_in[25];
    const float* v5  = (const float*)d_in[26];
    const float* w6  = (const float*)d_in[27];
    const float* b6  = (const float*)d_in[28];

    cudaFuncSetAttribute(k1_mma, cudaFuncAttributeMaxDynamicSharedMemorySize, 102400);
    cudaFuncSetAttribute(k2_mma, cudaFuncAttributeMaxDynamicSharedMemorySize, 73728);
    cudaFuncSetAttribute(k3_mma, cudaFuncAttributeMaxDynamicSharedMemorySize, 55296);
    cudaFuncSetAttribute(k4_mma, cudaFuncAttributeMaxDynamicSharedMemorySize, 61440);

    k0_prep<<<NC5 + 1 + NB + 192 + 256, 256>>>(w5, g5, v5, b5, bt5, m5, w4,
                                               w1, b1, g1, bt1, m1, v1,
                                               w2, b2, g2, bt2, m2, v2,
                                               w3, b3, g3, bt3, m3, v3);
    k1_mma<<<dim3(8, NB), 384, 102400>>>(x);
    k2t<<<dim3(16, NB), 256>>>();
    k2_mma<<<dim3(4, 2, NB * 4), 128, 73728>>>();
    k2r<<<1024, 256>>>();
    k3_mma<<<dim3(16, 4, NB), 128, 55296>>>(b4);
    k4_mma<<<dim3(16, 2, NB), 128, 61440>>>(w6);
    k5_scale<<<(NB * NINP * NHW / 4) / 256, 256>>>(x, b6, (float*)d_out);
}